// round 8
// baseline (speedup 1.0000x reference)
#include <cuda_runtime.h>
#include <math.h>

#define NN 50000
#define NE 500000
#define FN 7
#define FE 8
#define DD 64
#define HH 128
#define PP 256           // Pab width (src-part 128 | dst-part 128)
#define EIN 136
#define UIN 192
#define LL 3
#define EPB 64           // edges per block-iteration (msg/pred)

// padded SMEM strides — multiples of 4 floats (16B alignment for LDS.128),
// chosen so lane-varying rows land on distinct banks
#define W2S 132          // weight rows [ch][k]
#define WUS 196          // upd weight rows
#define NLS 68           // node_lin weight rows
#define SHS 132          // sH edge rows (GEMM2 v loads: bank = e*4 + k, distinct)
#define SMS 132          // sMsg edge rows
#define SH2S 68          // pred sH2 edge rows

typedef unsigned long long u64;

__device__ __forceinline__ void ffma2(u64 &d, u64 a, u64 b) {
    asm("fma.rn.f32x2 %0, %1, %2, %0;" : "+l"(d) : "l"(a), "l"(b));
}
__device__ __forceinline__ float f2sum(u64 a) {
    float lo, hi;
    asm("mov.b64 {%0, %1}, %2;" : "=f"(lo), "=f"(hi) : "l"(a));
    return lo + hi;
}
__device__ __forceinline__ void red_add_v4(float* p, float4 v) {
    u64 gp;
    asm("cvta.to.global.u64 %0, %1;" : "=l"(gp) : "l"(p));
    asm volatile("red.global.add.v4.f32 [%0], {%1, %2, %3, %4};"
                 :: "l"(gp), "f"(v.x), "f"(v.y), "f"(v.z), "f"(v.w) : "memory");
}
__device__ __forceinline__ void cp16(unsigned saddr, const void* g) {
    asm volatile("cp.async.cg.shared.global [%0], [%1], 16;" :: "r"(saddr), "l"(g));
}
#define CP_COMMIT()   asm volatile("cp.async.commit_group;" ::: "memory")
#define CP_WAIT_ALL() asm volatile("cp.async.wait_group 0;" ::: "memory")

// ---------------- scratch ----------------
__device__ float g_x[NN * DD];
__device__ float g_agg[NN * HH];
__device__ float g_cnt[NN];
__device__ float g_pab[NN * PP];

// ---------------- init ----------------
__global__ void init_kernel() {
    int i = blockIdx.x * blockDim.x + threadIdx.x;
    const int A4 = NN * HH / 4;
    if (i < A4) ((float4*)g_agg)[i] = make_float4(0.f, 0.f, 0.f, 0.f);
    else if (i < A4 + NN / 4) ((float4*)g_cnt)[i - A4] = make_float4(0.f, 0.f, 0.f, 0.f);
}

__global__ void count_kernel(const int* __restrict__ dst) {
    int e = blockIdx.x * blockDim.x + threadIdx.x;
    if (e < NE) atomicAdd(&g_cnt[dst[e]], 1.0f);
}

// ---------------- fused embed + node_lin(layer0) ----------------
#define EMB_SMEM ((PP*NLS + FN*DD + DD + 8*FN + 8*DD) * 4)

__global__ void __launch_bounds__(256, 2)
embed_nl_kernel(const float* __restrict__ nf,
                const float* __restrict__ eW, const float* __restrict__ eb,
                const float* __restrict__ W1) {
    extern __shared__ float s[];
    float* sWt = s;                    // [256][68]
    float* sWe = sWt + PP * NLS;
    float* sBe = sWe + FN * DD;
    float* sNf = sBe + DD;
    float* sX  = sNf + 8 * FN;

    const int tid = threadIdx.x;
    for (int i = tid; i < DD * PP; i += 256) {
        int k = i >> 8, j = i & 255;
        sWt[j * NLS + k] = (j < HH) ? W1[k * HH + j] : W1[(DD + k) * HH + (j - HH)];
    }
    for (int i = tid; i < FN * DD; i += 256) sWe[i] = eW[i];
    if (tid < DD) sBe[tid] = eb[tid];
    __syncthreads();

    const int step = gridDim.x * 8;
    for (int n0 = blockIdx.x * 8; n0 < NN; n0 += step) {
        for (int i = tid; i < 8 * FN; i += 256) {
            int c = i / FN, f = i % FN;
            sNf[i] = nf[(n0 + c) * FN + f];
        }
        __syncthreads();
        for (int i = tid; i < 8 * DD; i += 256) {
            int c = i >> 6, d = i & 63;
            float xv = sBe[d];
#pragma unroll
            for (int f = 0; f < FN; f++) xv += sNf[c * FN + f] * sWe[f * DD + d];
            xv = fmaxf(xv, 0.f);
            sX[c * DD + d] = xv;
            g_x[(n0 + c) * DD + d] = xv;
        }
        __syncthreads();
        u64 acc[8];
#pragma unroll
        for (int c = 0; c < 8; c++) acc[c] = 0ull;
        const float* wr = sWt + tid * NLS;
#pragma unroll 4
        for (int k = 0; k < DD; k += 4) {
            ulonglong2 w = *(const ulonglong2*)(wr + k);
#pragma unroll
            for (int c = 0; c < 8; c++) {
                ulonglong2 v = *(const ulonglong2*)(sX + c * DD + k);
                ffma2(acc[c], w.x, v.x);
                ffma2(acc[c], w.y, v.y);
            }
        }
#pragma unroll
        for (int c = 0; c < 8; c++)
            g_pab[(size_t)(n0 + c) * PP + tid] = f2sum(acc[c]);
        __syncthreads();
    }
}

// ---------------- fused edge message (512 thr, edge-spread GEMM2) ----------------
#define MSG_SMEM ((HH*W2S + EPB*SHS + EPB*SMS + EPB*PP + EPB*FE) * 4)

__global__ void __launch_bounds__(512, 1)
msg_kernel(const float* __restrict__ ea,
           const int* __restrict__ src, const int* __restrict__ dst,
           const float* __restrict__ W1, const float* __restrict__ b1,
           const float* __restrict__ W2, const float* __restrict__ b2) {
    extern __shared__ float s[];
    float* sW2t = s;                       // [128][132]
    float* sH   = sW2t + HH * W2S;         // [64][132]
    float* sMsg = sH + EPB * SHS;          // [64][132]
    float* sPab = sMsg + EPB * SMS;        // [64][256]
    float* sEa  = sPab + EPB * PP;         // [64][8]

    const unsigned aPab = (unsigned)__cvta_generic_to_shared(sPab);
    const unsigned aEa  = (unsigned)__cvta_generic_to_shared(sEa);

    const int tid = threadIdx.x;
    for (int i = tid; i < HH * HH; i += 512) { int k = i >> 7, j = i & 127; sW2t[j * W2S + k] = W2[i]; }

    const int j = tid & 127, g = tid >> 7;       // phaseA: 4 groups, 16 edges/thread
    const int eg = tid & 7, j2 = tid >> 3;       // GEMM2: edge-spread map, E8 x C2
    const int wid = tid >> 5, lane = tid & 31;   // staging/scatter: 16 warps x 4 edges
    const float b1v = b1[j];
    const float b2lo = b2[j2], b2hi = b2[j2 + 64];
    float w1c[8];
#pragma unroll
    for (int f = 0; f < 8; f++) w1c[f] = W1[(2 * DD + f) * HH + j];

    int nsrc[4], ndst[4], pd_cur[4];
    const int ea_le = wid * 4 + (lane >> 1), ea_off = (lane & 1) * 4;

#define MSG_LOADIDX(BASE) { \
    _Pragma("unroll") \
    for (int t = 0; t < 4; t++) { \
        int ge = (BASE) + wid * 4 + t; \
        int gc = (ge < NE) ? ge : NE - 1; \
        nsrc[t] = src[gc]; ndst[t] = dst[gc]; } }

#define MSG_STAGE(BASE) { \
    _Pragma("unroll") \
    for (int t = 0; t < 4; t++) { \
        int le = wid * 4 + t; \
        cp16(aPab + (le * PP + lane * 4) * 4, g_pab + (size_t)nsrc[t] * PP + lane * 4); \
        cp16(aPab + (le * PP + HH + lane * 4) * 4, g_pab + (size_t)ndst[t] * PP + HH + lane * 4); } \
    if (lane < 8) { \
        int ge = (BASE) + ea_le; \
        int gc = (ge < NE) ? ge : NE - 1; \
        cp16(aEa + (ea_le * FE + ea_off) * 4, ea + (size_t)gc * FE + ea_off); } }

    int e0 = blockIdx.x * EPB;
    const int step = gridDim.x * EPB;
    MSG_LOADIDX(e0);
    MSG_STAGE(e0);
    CP_COMMIT();

    for (; e0 < NE; e0 += step) {
        int enext = e0 + step;
        CP_WAIT_ALL();
        __syncthreads();                         // staged tile + weights visible

#pragma unroll
        for (int t = 0; t < 4; t++) pd_cur[t] = ndst[t];
        if (enext < NE) MSG_LOADIDX(enext);      // LDG latency hidden by phaseA

        // ---- phase A: h = relu(Pa + Pb + ea@W1c + b1) : 16 edges/thread ----
#pragma unroll
        for (int c = 0; c < 16; c++) {
            int e = g + 4 * c;
            float hv = sPab[e * PP + j] + sPab[e * PP + HH + j] + b1v;
            float4 a0 = ((const float4*)(sEa + e * FE))[0];
            float4 a1 = ((const float4*)(sEa + e * FE))[1];
            hv = fmaf(a0.x, w1c[0], hv); hv = fmaf(a0.y, w1c[1], hv);
            hv = fmaf(a0.z, w1c[2], hv); hv = fmaf(a0.w, w1c[3], hv);
            hv = fmaf(a1.x, w1c[4], hv); hv = fmaf(a1.y, w1c[5], hv);
            hv = fmaf(a1.z, w1c[6], hv); hv = fmaf(a1.w, w1c[7], hv);
            sH[e * SHS + j] = fmaxf(hv, 0.f);
        }
        __syncthreads();                         // sH visible; sPab/sEa free

        if (enext < NE) MSG_STAGE(enext);        // lands under GEMM2 + scatter
        CP_COMMIT();

        // ---- GEMM2: thread (eg, j2) -> edges {eg+8c}, channels {j2, j2+64} ----
        u64 aLo[8], aHi[8];
#pragma unroll
        for (int c = 0; c < 8; c++) { aLo[c] = 0ull; aHi[c] = 0ull; }
        const float* wr0 = sW2t + j2 * W2S;
        const float* wr1 = sW2t + (j2 + 64) * W2S;
#pragma unroll 2
        for (int k = 0; k < HH; k += 4) {
            ulonglong2 w0 = *(const ulonglong2*)(wr0 + k);
            ulonglong2 w1 = *(const ulonglong2*)(wr1 + k);
#pragma unroll
            for (int c = 0; c < 8; c++) {
                ulonglong2 v = *(const ulonglong2*)(sH + (eg + 8 * c) * SHS + k);
                ffma2(aLo[c], w0.x, v.x);
                ffma2(aLo[c], w0.y, v.y);
                ffma2(aHi[c], w1.x, v.x);
                ffma2(aHi[c], w1.y, v.y);
            }
        }
#pragma unroll
        for (int c = 0; c < 8; c++) {
            int e = eg + 8 * c;
            sMsg[e * SMS + j2]      = f2sum(aLo[c]) + b2lo;
            sMsg[e * SMS + 64 + j2] = f2sum(aHi[c]) + b2hi;
        }
        __syncthreads();                         // sMsg visible

        // ---- scatter: warp -> its 4 edges ----
#pragma unroll
        for (int t = 0; t < 4; t++) {
            int le = wid * 4 + t;
            if (e0 + le < NE) {
                float4 m = ((const float4*)(sMsg + le * SMS))[lane];
                red_add_v4(g_agg + (size_t)pd_cur[t] * HH + lane * 4, m);
            }
        }
    }
#undef MSG_LOADIDX
#undef MSG_STAGE
}

// ---------------- fused node update + LayerNorm + agg-zero + node_lin ----------------
#define UPDNL_SMEM ((DD*WUS + 3*DD + PP*NLS + 8*UIN + 8*DD + 32) * 4)

__global__ void __launch_bounds__(512, 1)
updnl_kernel(const float* __restrict__ W, const float* __restrict__ b,
             const float* __restrict__ lg, const float* __restrict__ lb,
             const float* __restrict__ W1next) {
    extern __shared__ float s[];
    float* sWt  = s;                   // [64][196]  upd W^T
    float* sB   = sWt + DD * WUS;
    float* sG   = sB + DD;
    float* sLB  = sG + DD;
    float* sWnl = sLB + DD;            // [256][68]  next-layer W1 (both halves)
    float* sNin = sWnl + PP * NLS;     // [8][192]
    float* sXn  = sNin + 8 * UIN;      // [8][64]
    float* sRed = sXn + 8 * DD;        // 32

    const int tid = threadIdx.x;
    for (int i = tid; i < UIN * DD; i += 512) { int k = i >> 6, d = i & 63; sWt[d * WUS + k] = W[i]; }
    for (int i = tid; i < DD * PP; i += 512) {
        int k = i >> 8, j = i & 255;
        sWnl[j * NLS + k] = (j < HH) ? W1next[k * HH + j] : W1next[(DD + k) * HH + (j - HH)];
    }
    if (tid < DD) { sB[tid] = b[tid]; sG[tid] = lg[tid]; sLB[tid] = lb[tid]; }
    __syncthreads();

    const int d = tid & 63, ln = tid >> 6;       // upd: 1 node-output/thread
    const int wg = (tid >> 5) & 1, lane = tid & 31;
    const int j = tid & 255, grp = tid >> 8;     // NL: 4 nodes/thread
    const float bv = sB[d], gv = sG[d], lbv = sLB[d];

    for (int n0 = blockIdx.x * 8; n0 < NN; n0 += gridDim.x * 8) {
        // stage [x | agg/count]
        for (int i = tid; i < 8 * UIN; i += 512) {
            int c = i / UIN, idx = i - c * UIN;
            int n = n0 + c;
            float v = 0.f;
            if (n < NN) {
                if (idx < DD) v = g_x[n * DD + idx];
                else v = g_agg[(size_t)n * HH + (idx - DD)] * (1.f / (g_cnt[n] + 1e-6f));
            }
            sNin[c * UIN + idx] = v;
        }
        __syncthreads();
        // zero agg rows for next layer (reads complete)
        if (tid < 256) {
            int n = n0 + (tid >> 5);
            if (n < NN) ((float4*)(g_agg + (size_t)n * HH))[tid & 31] = make_float4(0.f, 0.f, 0.f, 0.f);
        }

        // upd MLP + residual
        u64 a0 = 0ull;
        const float* wr = sWt + d * WUS;
        const float* in0 = sNin + ln * UIN;
#pragma unroll 4
        for (int k = 0; k < UIN; k += 4) {
            ulonglong2 w = *(const ulonglong2*)(wr + k);
            ulonglong2 v = *(const ulonglong2*)(in0 + k);
            ffma2(a0, w.x, v.x);
            ffma2(a0, w.y, v.y);
        }
        float outv = in0[d] + fmaxf(f2sum(a0) + bv, 0.f);

        // LayerNorm: shuffle within warp, combine 2 warps per node
        float s1 = outv, s2 = outv * outv;
#pragma unroll
        for (int off = 16; off; off >>= 1) {
            s1 += __shfl_xor_sync(0xFFFFFFFFu, s1, off);
            s2 += __shfl_xor_sync(0xFFFFFFFFu, s2, off);
        }
        if (lane == 0) { sRed[(ln * 2 + wg) * 2] = s1; sRed[(ln * 2 + wg) * 2 + 1] = s2; }
        __syncthreads();
        {
            float t1 = sRed[ln * 4] + sRed[ln * 4 + 2];
            float t2 = sRed[ln * 4 + 1] + sRed[ln * 4 + 3];
            float mu = t1 * (1.f / DD);
            float var = t2 * (1.f / DD) - mu * mu;
            float xn = (outv - mu) * rsqrtf(var + 1e-5f) * gv + lbv;
            int n = n0 + ln;
            if (n < NN) g_x[n * DD + d] = xn;
            sXn[ln * DD + d] = xn;
        }
        __syncthreads();

        // node_lin for next layer: Pab = xnew @ W1next[0:128]
        u64 acc[4];
#pragma unroll
        for (int c = 0; c < 4; c++) acc[c] = 0ull;
        const float* wr2 = sWnl + j * NLS;
#pragma unroll 4
        for (int k = 0; k < DD; k += 4) {
            ulonglong2 w = *(const ulonglong2*)(wr2 + k);
#pragma unroll
            for (int c = 0; c < 4; c++) {
                ulonglong2 v = *(const ulonglong2*)(sXn + (grp + 2 * c) * DD + k);
                ffma2(acc[c], w.x, v.x);
                ffma2(acc[c], w.y, v.y);
            }
        }
#pragma unroll
        for (int c = 0; c < 4; c++) {
            int n = n0 + grp + 2 * c;
            if (n < NN) g_pab[(size_t)n * PP + j] = f2sum(acc[c]);
        }
        __syncthreads();
    }
}

// ---------------- edge predictor (512 thr, edge-spread GEMM2) ----------------
#define PRED_SMEM ((DD*W2S + DD + EPB*SHS + EPB*SH2S + EPB*PP + EPB*FE) * 4)

__global__ void __launch_bounds__(512, 1)
pred_kernel(const float* __restrict__ ea,
            const int* __restrict__ src, const int* __restrict__ dst,
            const float* __restrict__ W1, const float* __restrict__ b1,
            const float* __restrict__ W2, const float* __restrict__ b2,
            const float* __restrict__ W3, const float* __restrict__ b3,
            float* __restrict__ out) {
    extern __shared__ float s[];
    float* sW2t = s;                   // [64][132]
    float* sW3  = sW2t + DD * W2S;     // [64]
    float* sH1  = sW3 + DD;            // [64][132]
    float* sH2  = sH1 + EPB * SHS;     // [64][68]
    float* sPab = sH2 + EPB * SH2S;    // [64][256]
    float* sEa  = sPab + EPB * PP;     // [64][8]

    const unsigned aPab = (unsigned)__cvta_generic_to_shared(sPab);
    const unsigned aEa  = (unsigned)__cvta_generic_to_shared(sEa);

    const int tid = threadIdx.x;
    for (int i = tid; i < HH * DD; i += 512) { int k = i >> 6, jj = i & 63; sW2t[jj * W2S + k] = W2[i]; }
    if (tid < DD) sW3[tid] = W3[tid];

    const int j = tid & 127, g = tid >> 7;
    const int eg = tid & 7, j2 = tid >> 3;       // edge-spread GEMM2 map (E8 x C1)
    const int wid = tid >> 5, lane = tid & 31;
    const float b1v = b1[j], b2v = b2[j2], b3v = b3[0];
    float w1c[8];
#pragma unroll
    for (int f = 0; f < 8; f++) w1c[f] = W1[(2 * DD + f) * HH + j];

    int nsrc[4], ndst[4];
    const int ea_le = wid * 4 + (lane >> 1), ea_off = (lane & 1) * 4;

#define PRD_LOADIDX(BASE) { \
    _Pragma("unroll") \
    for (int t = 0; t < 4; t++) { \
        int ge = (BASE) + wid * 4 + t; \
        int gc = (ge < NE) ? ge : NE - 1; \
        nsrc[t] = src[gc]; ndst[t] = dst[gc]; } }

#define PRD_STAGE(BASE) { \
    _Pragma("unroll") \
    for (int t = 0; t < 4; t++) { \
        int le = wid * 4 + t; \
        cp16(aPab + (le * PP + lane * 4) * 4, g_pab + (size_t)nsrc[t] * PP + lane * 4); \
        cp16(aPab + (le * PP + HH + lane * 4) * 4, g_pab + (size_t)ndst[t] * PP + HH + lane * 4); } \
    if (lane < 8) { \
        int ge = (BASE) + ea_le; \
        int gc = (ge < NE) ? ge : NE - 1; \
        cp16(aEa + (ea_le * FE + ea_off) * 4, ea + (size_t)gc * FE + ea_off); } }

    int e0 = blockIdx.x * EPB;
    const int step = gridDim.x * EPB;
    PRD_LOADIDX(e0);
    PRD_STAGE(e0);
    CP_COMMIT();

    for (; e0 < NE; e0 += step) {
        int enext = e0 + step;
        CP_WAIT_ALL();
        __syncthreads();

        if (enext < NE) PRD_LOADIDX(enext);

        // phase A: h1 = relu(Pa + Pb + ea@W1c + b1) : 16 edges/thread
#pragma unroll
        for (int c = 0; c < 16; c++) {
            int e = g + 4 * c;
            float hv = sPab[e * PP + j] + sPab[e * PP + HH + j] + b1v;
            float4 a0 = ((const float4*)(sEa + e * FE))[0];
            float4 a1 = ((const float4*)(sEa + e * FE))[1];
            hv = fmaf(a0.x, w1c[0], hv); hv = fmaf(a0.y, w1c[1], hv);
            hv = fmaf(a0.z, w1c[2], hv); hv = fmaf(a0.w, w1c[3], hv);
            hv = fmaf(a1.x, w1c[4], hv); hv = fmaf(a1.y, w1c[5], hv);
            hv = fmaf(a1.z, w1c[6], hv); hv = fmaf(a1.w, w1c[7], hv);
            sH1[e * SHS + j] = fmaxf(hv, 0.f);
        }
        __syncthreads();

        if (enext < NE) PRD_STAGE(enext);
        CP_COMMIT();

        // GEMM2: 128 -> 64, thread (eg, j2) -> edges {eg+8c}, channel j2
        u64 acc[8];
#pragma unroll
        for (int c = 0; c < 8; c++) acc[c] = 0ull;
        const float* wr = sW2t + j2 * W2S;
#pragma unroll 2
        for (int k = 0; k < HH; k += 4) {
            ulonglong2 w = *(const ulonglong2*)(wr + k);
#pragma unroll
            for (int c = 0; c < 8; c++) {
                ulonglong2 v = *(const ulonglong2*)(sH1 + (eg + 8 * c) * SHS + k);
                ffma2(acc[c], w.x, v.x);
                ffma2(acc[c], w.y, v.y);
            }
        }
#pragma unroll
        for (int c = 0; c < 8; c++)
            sH2[(eg + 8 * c) * SH2S + j2] = fmaxf(f2sum(acc[c]) + b2v, 0.f);
        __syncthreads();

        // final dot 64 -> 1 + tanh : warp -> its 4 edges
#pragma unroll
        for (int t = 0; t < 4; t++) {
            int le = wid * 4 + t, ge = e0 + le;
            float v = sH2[le * SH2S + lane] * sW3[lane]
                    + sH2[le * SH2S + 32 + lane] * sW3[32 + lane];
#pragma unroll
            for (int off = 16; off; off >>= 1) v += __shfl_xor_sync(0xFFFFFFFFu, v, off);
            if (lane == 0 && ge < NE) out[ge] = tanhf(v + b3v);
        }
    }
#undef PRD_LOADIDX
#undef PRD_STAGE
}

// ---------------- launch ----------------
extern "C" void kernel_launch(void* const* d_in, const int* in_sizes, int n_in,
                              void* d_out, int out_size) {
    const float* node_features = (const float*)d_in[0];
    const float* edge_attr     = (const float*)d_in[1];
    const float* embed_W       = (const float*)d_in[2];
    const float* embed_b       = (const float*)d_in[3];
    const float* msg_W1        = (const float*)d_in[4];
    const float* msg_b1        = (const float*)d_in[5];
    const float* msg_W2        = (const float*)d_in[6];
    const float* msg_b2        = (const float*)d_in[7];
    const float* upd_W         = (const float*)d_in[8];
    const float* upd_b         = (const float*)d_in[9];
    const float* ln_g          = (const float*)d_in[10];
    const float* ln_b          = (const float*)d_in[11];
    const float* pred_W1       = (const float*)d_in[12];
    const float* pred_b1       = (const float*)d_in[13];
    const float* pred_W2       = (const float*)d_in[14];
    const float* pred_b2       = (const float*)d_in[15];
    const float* pred_W3       = (const float*)d_in[16];
    const float* pred_b3       = (const float*)d_in[17];
    const int*   edge_index    = (const int*)d_in[18];
    float* out = (float*)d_out;

    const int* src = edge_index;
    const int* dst = edge_index + NE;

    cudaFuncSetAttribute(msg_kernel,      cudaFuncAttributeMaxDynamicSharedMemorySize, MSG_SMEM);
    cudaFuncSetAttribute(pred_kernel,     cudaFuncAttributeMaxDynamicSharedMemorySize, PRED_SMEM);
    cudaFuncSetAttribute(updnl_kernel,    cudaFuncAttributeMaxDynamicSharedMemorySize, UPDNL_SMEM);
    cudaFuncSetAttribute(embed_nl_kernel, cudaFuncAttributeMaxDynamicSharedMemorySize, EMB_SMEM);

    init_kernel<<<(NN * HH / 4 + NN / 4 + 255) / 256, 256>>>();
    count_kernel<<<(NE + 255) / 256, 256>>>(dst);
    embed_nl_kernel<<<296, 256, EMB_SMEM>>>(node_features, embed_W, embed_b, msg_W1);

    for (int l = 0; l < LL; l++) {
        // launch index 3 on l=0 -> ncu profiles msg_kernel
        msg_kernel<<<148, 512, MSG_SMEM>>>(edge_attr, src, dst,
                                           msg_W1 + l * EIN * HH, msg_b1 + l * HH,
                                           msg_W2 + l * HH * HH, msg_b2 + l * HH);
        const float* nextW1 = (l < LL - 1) ? (msg_W1 + (l + 1) * EIN * HH) : pred_W1;
        updnl_kernel<<<148, 512, UPDNL_SMEM>>>(upd_W + l * UIN * DD, upd_b + l * DD,
                                               ln_g + l * DD, ln_b + l * DD, nextW1);
    }

    pred_kernel<<<148, 512, PRED_SMEM>>>(edge_attr, src, dst,
                                         pred_W1, pred_b1, pred_W2, pred_b2,
                                         pred_W3, pred_b3, out);
}

// round 9
// speedup vs baseline: 1.1874x; 1.1874x over previous
#include <cuda_runtime.h>
#include <math.h>

#define NN 50000
#define NE 500000
#define FN 7
#define FE 8
#define DD 64
#define HH 128
#define PP 256           // Pab width (src-part 128 | dst-part 128)
#define EIN 136
#define UIN 192
#define LL 3
#define EPB 128          // edges per block-iteration (msg/pred)

// padded weight strides (multiple of 4 floats -> 16B aligned; (row*stride) banks distinct)
#define W2S 132
#define WUS 196
#define NLS 68

typedef unsigned long long u64;

__device__ __forceinline__ void ffma2(u64 &d, u64 a, u64 b) {
    asm("fma.rn.f32x2 %0, %1, %2, %0;" : "+l"(d) : "l"(a), "l"(b));
}
__device__ __forceinline__ float f2sum(u64 a) {
    float lo, hi;
    asm("mov.b64 {%0, %1}, %2;" : "=f"(lo), "=f"(hi) : "l"(a));
    return lo + hi;
}
__device__ __forceinline__ void red_add_v4(float* p, float4 v) {
    u64 gp;
    asm("cvta.to.global.u64 %0, %1;" : "=l"(gp) : "l"(p));
    asm volatile("red.global.add.v4.f32 [%0], {%1, %2, %3, %4};"
                 :: "l"(gp), "f"(v.x), "f"(v.y), "f"(v.z), "f"(v.w) : "memory");
}

// ---------------- scratch ----------------
__device__ float g_x[NN * DD];
__device__ float g_agg[NN * HH];
__device__ float g_cnt[NN];
__device__ float g_pab[NN * PP];

// ---------------- init ----------------
__global__ void init_kernel() {
    int i = blockIdx.x * blockDim.x + threadIdx.x;
    const int A4 = NN * HH / 4;
    if (i < A4) ((float4*)g_agg)[i] = make_float4(0.f, 0.f, 0.f, 0.f);
    else if (i < A4 + NN / 4) ((float4*)g_cnt)[i - A4] = make_float4(0.f, 0.f, 0.f, 0.f);
}

__global__ void count_kernel(const int* __restrict__ dst) {
    int e = blockIdx.x * blockDim.x + threadIdx.x;
    if (e < NE) atomicAdd(&g_cnt[dst[e]], 1.0f);
}

// ---------------- fused embed + node_lin(layer0) ----------------
#define EMB_SMEM ((PP*NLS + FN*DD + DD + 8*FN + 8*DD) * 4)

__global__ void __launch_bounds__(256, 2)
embed_nl_kernel(const float* __restrict__ nf,
                const float* __restrict__ eW, const float* __restrict__ eb,
                const float* __restrict__ W1) {
    extern __shared__ float s[];
    float* sWt = s;                    // [256][68]
    float* sWe = sWt + PP * NLS;
    float* sBe = sWe + FN * DD;
    float* sNf = sBe + DD;
    float* sX  = sNf + 8 * FN;

    const int tid = threadIdx.x;
    for (int i = tid; i < DD * PP; i += 256) {
        int k = i >> 8, j = i & 255;
        sWt[j * NLS + k] = (j < HH) ? W1[k * HH + j] : W1[(DD + k) * HH + (j - HH)];
    }
    for (int i = tid; i < FN * DD; i += 256) sWe[i] = eW[i];
    if (tid < DD) sBe[tid] = eb[tid];
    __syncthreads();

    const int step = gridDim.x * 8;
    for (int n0 = blockIdx.x * 8; n0 < NN; n0 += step) {
        for (int i = tid; i < 8 * FN; i += 256) {
            int c = i / FN, f = i % FN;
            sNf[i] = nf[(n0 + c) * FN + f];
        }
        __syncthreads();
        for (int i = tid; i < 8 * DD; i += 256) {
            int c = i >> 6, d = i & 63;
            float xv = sBe[d];
#pragma unroll
            for (int f = 0; f < FN; f++) xv += sNf[c * FN + f] * sWe[f * DD + d];
            xv = fmaxf(xv, 0.f);
            sX[c * DD + d] = xv;
            g_x[(n0 + c) * DD + d] = xv;
        }
        __syncthreads();
        u64 acc[8];
#pragma unroll
        for (int c = 0; c < 8; c++) acc[c] = 0ull;
        const float* wr = sWt + tid * NLS;
#pragma unroll 4
        for (int k = 0; k < DD; k += 4) {
            ulonglong2 w = *(const ulonglong2*)(wr + k);
#pragma unroll
            for (int c = 0; c < 8; c++) {
                ulonglong2 v = *(const ulonglong2*)(sX + c * DD + k);
                ffma2(acc[c], w.x, v.x);
                ffma2(acc[c], w.y, v.y);
            }
        }
#pragma unroll
        for (int c = 0; c < 8; c++)
            g_pab[(size_t)(n0 + c) * PP + tid] = f2sum(acc[c]);
        __syncthreads();
    }
}

// ---------------- fused edge message (EPB=128, direct-LDG phaseA, E16C2 GEMM2) ----------------
#define MSG_SMEM ((HH*W2S + EPB*HH + EPB*HH + EPB*FE + 2*EPB) * 4)

__global__ void __launch_bounds__(512, 1)
msg_kernel(const float* __restrict__ ea,
           const int* __restrict__ src, const int* __restrict__ dst,
           const float* __restrict__ W1, const float* __restrict__ b1,
           const float* __restrict__ W2, const float* __restrict__ b2) {
    extern __shared__ float s[];
    float* sW2t = s;                       // [128][132]
    float* sH   = sW2t + HH * W2S;         // [128][128]
    float* sMsg = sH + EPB * HH;           // [128][128]
    float* sEa  = sMsg + EPB * HH;         // [128][8]
    int*   sSrc = (int*)(sEa + EPB * FE);  // [128]
    int*   sDst = sSrc + EPB;              // [128]

    const int tid = threadIdx.x;
    for (int i = tid; i < HH * HH; i += 512) { int k = i >> 7, j = i & 127; sW2t[j * W2S + k] = W2[i]; }

    const int j = tid & 127, g = tid >> 7;       // phaseA: 4 groups, 32 edges/thread
    const int j2 = tid & 63, eg = tid >> 6;      // GEMM2: E16 x C2 (eg in 0..7)
    const int wid = tid >> 5, lane = tid & 31;   // scatter: 16 warps x 8 edges
    const float b1v = b1[j];
    const float b2lo = b2[j2], b2hi = b2[j2 + 64];
    float w1c[8];
#pragma unroll
    for (int f = 0; f < 8; f++) w1c[f] = W1[(2 * DD + f) * HH + j];

    int e0 = blockIdx.x * EPB;
    const int step = gridDim.x * EPB;

    for (; e0 < NE; e0 += step) {
        __syncthreads();                         // prior tile fully consumed
        // ---- stage indices + edge attrs ----
        if (tid < 2 * EPB) {
            int le = tid & (EPB - 1);
            int gc = e0 + le; if (gc >= NE) gc = NE - 1;
            if (tid < EPB) sSrc[le] = src[gc];
            else           sDst[le] = dst[gc];
        }
        for (int i = tid; i < EPB * 2; i += 512) {   // 256 float4 = ea tile
            int le = i >> 1, frag = i & 1;
            int gc = e0 + le; if (gc >= NE) gc = NE - 1;
            ((float4*)sEa)[i] = ((const float4*)ea)[(size_t)gc * 2 + frag];
        }
        __syncthreads();

        // ---- phase A: h = relu(Pa[src] + Pb[dst] + ea@W1c + b1), pipelined LDG ----
        {
            float pa[8], pb[8];
#pragma unroll
            for (int c = 0; c < 8; c++) {
                int e = g + 4 * c;
                pa[c] = g_pab[(size_t)sSrc[e] * PP + j];
                pb[c] = g_pab[(size_t)sDst[e] * PP + HH + j];
            }
#pragma unroll
            for (int c = 0; c < 32; c++) {
                int e = g + 4 * c;
                float hv = pa[c & 7] + pb[c & 7] + b1v;
                if (c + 8 < 32) {
                    int e2 = g + 4 * (c + 8);
                    pa[c & 7] = g_pab[(size_t)sSrc[e2] * PP + j];
                    pb[c & 7] = g_pab[(size_t)sDst[e2] * PP + HH + j];
                }
                float4 a0 = ((const float4*)(sEa + e * FE))[0];
                float4 a1 = ((const float4*)(sEa + e * FE))[1];
                hv = fmaf(a0.x, w1c[0], hv); hv = fmaf(a0.y, w1c[1], hv);
                hv = fmaf(a0.z, w1c[2], hv); hv = fmaf(a0.w, w1c[3], hv);
                hv = fmaf(a1.x, w1c[4], hv); hv = fmaf(a1.y, w1c[5], hv);
                hv = fmaf(a1.z, w1c[6], hv); hv = fmaf(a1.w, w1c[7], hv);
                sH[e * HH + j] = fmaxf(hv, 0.f);
            }
        }
        __syncthreads();                         // sH visible

        // ---- GEMM2: E=16 edges x C=2 channels per thread ----
        {
            u64 acc[32];
#pragma unroll
            for (int c = 0; c < 32; c++) acc[c] = 0ull;
            const float* wr0 = sW2t + j2 * W2S;
            const float* wr1 = wr0 + 64 * W2S;
#pragma unroll 2
            for (int k = 0; k < HH; k += 4) {
                ulonglong2 w0 = *(const ulonglong2*)(wr0 + k);
                ulonglong2 w1 = *(const ulonglong2*)(wr1 + k);
#pragma unroll
                for (int c = 0; c < 16; c++) {
                    ulonglong2 v = *(const ulonglong2*)(sH + (eg + 8 * c) * HH + k);
                    ffma2(acc[2 * c],     w0.x, v.x);
                    ffma2(acc[2 * c],     w0.y, v.y);
                    ffma2(acc[2 * c + 1], w1.x, v.x);
                    ffma2(acc[2 * c + 1], w1.y, v.y);
                }
            }
#pragma unroll
            for (int c = 0; c < 16; c++) {
                int e = eg + 8 * c;
                sMsg[e * HH + j2]      = f2sum(acc[2 * c]) + b2lo;
                sMsg[e * HH + 64 + j2] = f2sum(acc[2 * c + 1]) + b2hi;
            }
        }
        __syncthreads();                         // sMsg visible

        // ---- scatter: warp -> its 8 edges ----
#pragma unroll
        for (int t = 0; t < 8; t++) {
            int le = wid * 8 + t;
            if (e0 + le < NE) {
                float4 m = ((const float4*)(sMsg + le * HH))[lane];
                red_add_v4(g_agg + (size_t)sDst[le] * HH + lane * 4, m);
            }
        }
    }
}

// ---------------- fused node update + LayerNorm + agg-zero + node_lin ----------------
#define UPDNL_SMEM ((DD*WUS + 3*DD + PP*NLS + 8*UIN + 8*DD + 32) * 4)

__global__ void __launch_bounds__(512, 1)
updnl_kernel(const float* __restrict__ W, const float* __restrict__ b,
             const float* __restrict__ lg, const float* __restrict__ lb,
             const float* __restrict__ W1next) {
    extern __shared__ float s[];
    float* sWt  = s;                   // [64][196]
    float* sB   = sWt + DD * WUS;
    float* sG   = sB + DD;
    float* sLB  = sG + DD;
    float* sWnl = sLB + DD;            // [256][68]
    float* sNin = sWnl + PP * NLS;     // [8][192]
    float* sXn  = sNin + 8 * UIN;      // [8][64]
    float* sRed = sXn + 8 * DD;        // 32

    const int tid = threadIdx.x;
    for (int i = tid; i < UIN * DD; i += 512) { int k = i >> 6, d = i & 63; sWt[d * WUS + k] = W[i]; }
    for (int i = tid; i < DD * PP; i += 512) {
        int k = i >> 8, j = i & 255;
        sWnl[j * NLS + k] = (j < HH) ? W1next[k * HH + j] : W1next[(DD + k) * HH + (j - HH)];
    }
    if (tid < DD) { sB[tid] = b[tid]; sG[tid] = lg[tid]; sLB[tid] = lb[tid]; }
    __syncthreads();

    const int d = tid & 63, ln = tid >> 6;
    const int wg = (tid >> 5) & 1, lane = tid & 31;
    const int j = tid & 255, grp = tid >> 8;
    const float bv = sB[d], gv = sG[d], lbv = sLB[d];

    for (int n0 = blockIdx.x * 8; n0 < NN; n0 += gridDim.x * 8) {
        for (int i = tid; i < 8 * UIN; i += 512) {
            int c = i / UIN, idx = i - c * UIN;
            int n = n0 + c;
            float v = 0.f;
            if (n < NN) {
                if (idx < DD) v = g_x[n * DD + idx];
                else v = g_agg[(size_t)n * HH + (idx - DD)] * (1.f / (g_cnt[n] + 1e-6f));
            }
            sNin[c * UIN + idx] = v;
        }
        __syncthreads();
        if (tid < 256) {
            int n = n0 + (tid >> 5);
            if (n < NN) ((float4*)(g_agg + (size_t)n * HH))[tid & 31] = make_float4(0.f, 0.f, 0.f, 0.f);
        }

        u64 a0 = 0ull;
        const float* wr = sWt + d * WUS;
        const float* in0 = sNin + ln * UIN;
#pragma unroll 4
        for (int k = 0; k < UIN; k += 4) {
            ulonglong2 w = *(const ulonglong2*)(wr + k);
            ulonglong2 v = *(const ulonglong2*)(in0 + k);
            ffma2(a0, w.x, v.x);
            ffma2(a0, w.y, v.y);
        }
        float outv = in0[d] + fmaxf(f2sum(a0) + bv, 0.f);

        float s1 = outv, s2 = outv * outv;
#pragma unroll
        for (int off = 16; off; off >>= 1) {
            s1 += __shfl_xor_sync(0xFFFFFFFFu, s1, off);
            s2 += __shfl_xor_sync(0xFFFFFFFFu, s2, off);
        }
        if (lane == 0) { sRed[(ln * 2 + wg) * 2] = s1; sRed[(ln * 2 + wg) * 2 + 1] = s2; }
        __syncthreads();
        {
            float t1 = sRed[ln * 4] + sRed[ln * 4 + 2];
            float t2 = sRed[ln * 4 + 1] + sRed[ln * 4 + 3];
            float mu = t1 * (1.f / DD);
            float var = t2 * (1.f / DD) - mu * mu;
            float xn = (outv - mu) * rsqrtf(var + 1e-5f) * gv + lbv;
            int n = n0 + ln;
            if (n < NN) g_x[n * DD + d] = xn;
            sXn[ln * DD + d] = xn;
        }
        __syncthreads();

        u64 acc[4];
#pragma unroll
        for (int c = 0; c < 4; c++) acc[c] = 0ull;
        const float* wr2 = sWnl + j * NLS;
#pragma unroll 4
        for (int k = 0; k < DD; k += 4) {
            ulonglong2 w = *(const ulonglong2*)(wr2 + k);
#pragma unroll
            for (int c = 0; c < 4; c++) {
                ulonglong2 v = *(const ulonglong2*)(sXn + (grp + 2 * c) * DD + k);
                ffma2(acc[c], w.x, v.x);
                ffma2(acc[c], w.y, v.y);
            }
        }
#pragma unroll
        for (int c = 0; c < 4; c++) {
            int n = n0 + grp + 2 * c;
            if (n < NN) g_pab[(size_t)n * PP + j] = f2sum(acc[c]);
        }
        __syncthreads();
    }
}

// ---------------- edge predictor (EPB=128, direct-LDG phaseA, E8C2 GEMM2) ----------------
#define PRED_SMEM ((DD*W2S + DD + EPB*HH + EPB*DD + EPB*FE + 2*EPB) * 4)

__global__ void __launch_bounds__(512, 1)
pred_kernel(const float* __restrict__ ea,
            const int* __restrict__ src, const int* __restrict__ dst,
            const float* __restrict__ W1, const float* __restrict__ b1,
            const float* __restrict__ W2, const float* __restrict__ b2,
            const float* __restrict__ W3, const float* __restrict__ b3,
            float* __restrict__ out) {
    extern __shared__ float s[];
    float* sW2t = s;                   // [64][132]
    float* sW3  = sW2t + DD * W2S;     // [64]
    float* sH1  = sW3 + DD;            // [128][128]
    float* sH2  = sH1 + EPB * HH;      // [128][64]
    float* sEa  = sH2 + EPB * DD;      // [128][8]
    int*   sSrc = (int*)(sEa + EPB * FE);
    int*   sDst = sSrc + EPB;

    const int tid = threadIdx.x;
    for (int i = tid; i < HH * DD; i += 512) { int k = i >> 6, jj = i & 63; sW2t[jj * W2S + k] = W2[i]; }
    if (tid < DD) sW3[tid] = W3[tid];

    const int j = tid & 127, g = tid >> 7;       // phaseA
    const int j2 = tid & 31, eg = tid >> 5;      // GEMM2: E8 x C2 (eg in 0..15)
    const int wid = tid >> 5, lane = tid & 31;
    const float b1v = b1[j], b2lo = b2[j2], b2hi = b2[j2 + 32], b3v = b3[0];
    float w1c[8];
#pragma unroll
    for (int f = 0; f < 8; f++) w1c[f] = W1[(2 * DD + f) * HH + j];

    int e0 = blockIdx.x * EPB;
    const int step = gridDim.x * EPB;

    for (; e0 < NE; e0 += step) {
        __syncthreads();
        if (tid < 2 * EPB) {
            int le = tid & (EPB - 1);
            int gc = e0 + le; if (gc >= NE) gc = NE - 1;
            if (tid < EPB) sSrc[le] = src[gc];
            else           sDst[le] = dst[gc];
        }
        for (int i = tid; i < EPB * 2; i += 512) {
            int le = i >> 1, frag = i & 1;
            int gc = e0 + le; if (gc >= NE) gc = NE - 1;
            ((float4*)sEa)[i] = ((const float4*)ea)[(size_t)gc * 2 + frag];
        }
        __syncthreads();

        // phase A
        {
            float pa[8], pb[8];
#pragma unroll
            for (int c = 0; c < 8; c++) {
                int e = g + 4 * c;
                pa[c] = g_pab[(size_t)sSrc[e] * PP + j];
                pb[c] = g_pab[(size_t)sDst[e] * PP + HH + j];
            }
#pragma unroll
            for (int c = 0; c < 32; c++) {
                int e = g + 4 * c;
                float hv = pa[c & 7] + pb[c & 7] + b1v;
                if (c + 8 < 32) {
                    int e2 = g + 4 * (c + 8);
                    pa[c & 7] = g_pab[(size_t)sSrc[e2] * PP + j];
                    pb[c & 7] = g_pab[(size_t)sDst[e2] * PP + HH + j];
                }
                float4 a0 = ((const float4*)(sEa + e * FE))[0];
                float4 a1 = ((const float4*)(sEa + e * FE))[1];
                hv = fmaf(a0.x, w1c[0], hv); hv = fmaf(a0.y, w1c[1], hv);
                hv = fmaf(a0.z, w1c[2], hv); hv = fmaf(a0.w, w1c[3], hv);
                hv = fmaf(a1.x, w1c[4], hv); hv = fmaf(a1.y, w1c[5], hv);
                hv = fmaf(a1.z, w1c[6], hv); hv = fmaf(a1.w, w1c[7], hv);
                sH1[e * HH + j] = fmaxf(hv, 0.f);
            }
        }
        __syncthreads();

        // GEMM2: 128 -> 64, E=8 x C=2 per thread
        {
            u64 acc[16];
#pragma unroll
            for (int c = 0; c < 16; c++) acc[c] = 0ull;
            const float* wr0 = sW2t + j2 * W2S;
            const float* wr1 = wr0 + 32 * W2S;
#pragma unroll 2
            for (int k = 0; k < HH; k += 4) {
                ulonglong2 w0 = *(const ulonglong2*)(wr0 + k);
                ulonglong2 w1 = *(const ulonglong2*)(wr1 + k);
#pragma unroll
                for (int c = 0; c < 8; c++) {
                    ulonglong2 v = *(const ulonglong2*)(sH1 + (eg + 16 * c) * HH + k);
                    ffma2(acc[2 * c],     w0.x, v.x);
                    ffma2(acc[2 * c],     w0.y, v.y);
                    ffma2(acc[2 * c + 1], w1.x, v.x);
                    ffma2(acc[2 * c + 1], w1.y, v.y);
                }
            }
#pragma unroll
            for (int c = 0; c < 8; c++) {
                int e = eg + 16 * c;
                sH2[e * DD + j2]      = fmaxf(f2sum(acc[2 * c]) + b2lo, 0.f);
                sH2[e * DD + 32 + j2] = fmaxf(f2sum(acc[2 * c + 1]) + b2hi, 0.f);
            }
        }
        __syncthreads();

        // final dot 64 -> 1 + tanh : warp -> its 8 edges
#pragma unroll
        for (int t = 0; t < 8; t++) {
            int le = wid * 8 + t, ge = e0 + le;
            float v = sH2[le * DD + lane] * sW3[lane]
                    + sH2[le * DD + 32 + lane] * sW3[32 + lane];
#pragma unroll
            for (int off = 16; off; off >>= 1) v += __shfl_xor_sync(0xFFFFFFFFu, v, off);
            if (lane == 0 && ge < NE) out[ge] = tanhf(v + b3v);
        }
    }
}

// ---------------- launch ----------------
extern "C" void kernel_launch(void* const* d_in, const int* in_sizes, int n_in,
                              void* d_out, int out_size) {
    const float* node_features = (const float*)d_in[0];
    const float* edge_attr     = (const float*)d_in[1];
    const float* embed_W       = (const float*)d_in[2];
    const float* embed_b       = (const float*)d_in[3];
    const float* msg_W1        = (const float*)d_in[4];
    const float* msg_b1        = (const float*)d_in[5];
    const float* msg_W2        = (const float*)d_in[6];
    const float* msg_b2        = (const float*)d_in[7];
    const float* upd_W         = (const float*)d_in[8];
    const float* upd_b         = (const float*)d_in[9];
    const float* ln_g          = (const float*)d_in[10];
    const float* ln_b          = (const float*)d_in[11];
    const float* pred_W1       = (const float*)d_in[12];
    const float* pred_b1       = (const float*)d_in[13];
    const float* pred_W2       = (const float*)d_in[14];
    const float* pred_b2       = (const float*)d_in[15];
    const float* pred_W3       = (const float*)d_in[16];
    const float* pred_b3       = (const float*)d_in[17];
    const int*   edge_index    = (const int*)d_in[18];
    float* out = (float*)d_out;

    const int* src = edge_index;
    const int* dst = edge_index + NE;

    cudaFuncSetAttribute(msg_kernel,      cudaFuncAttributeMaxDynamicSharedMemorySize, MSG_SMEM);
    cudaFuncSetAttribute(pred_kernel,     cudaFuncAttributeMaxDynamicSharedMemorySize, PRED_SMEM);
    cudaFuncSetAttribute(updnl_kernel,    cudaFuncAttributeMaxDynamicSharedMemorySize, UPDNL_SMEM);
    cudaFuncSetAttribute(embed_nl_kernel, cudaFuncAttributeMaxDynamicSharedMemorySize, EMB_SMEM);

    init_kernel<<<(NN * HH / 4 + NN / 4 + 255) / 256, 256>>>();
    count_kernel<<<(NE + 255) / 256, 256>>>(dst);
    embed_nl_kernel<<<296, 256, EMB_SMEM>>>(node_features, embed_W, embed_b, msg_W1);

    for (int l = 0; l < LL; l++) {
        // launch index 3 on l=0 -> ncu profiles msg_kernel
        msg_kernel<<<148, 512, MSG_SMEM>>>(edge_attr, src, dst,
                                           msg_W1 + l * EIN * HH, msg_b1 + l * HH,
                                           msg_W2 + l * HH * HH, msg_b2 + l * HH);
        const float* nextW1 = (l < LL - 1) ? (msg_W1 + (l + 1) * EIN * HH) : pred_W1;
        updnl_kernel<<<148, 512, UPDNL_SMEM>>>(upd_W + l * UIN * DD, upd_b + l * DD,
                                               ln_g + l * DD, ln_b + l * DD, nextW1);
    }

    pred_kernel<<<148, 512, PRED_SMEM>>>(edge_attr, src, dst,
                                         pred_W1, pred_b1, pred_W2, pred_b2,
                                         pred_W3, pred_b3, out);
}

// round 10
// speedup vs baseline: 1.7390x; 1.4646x over previous
#include <cuda_runtime.h>
#include <math.h>

#define NN 50000
#define NE 500000
#define FN 7
#define FE 8
#define DD 64
#define HH 128
#define PP 256           // Pab width (src-part 128 | dst-part 128)
#define EIN 136
#define UIN 192
#define LL 3
#define EPB 128          // edges per block-iteration (msg/pred)

// padded weight strides (multiple of 4 floats -> 16B aligned)
#define W2S 132
#define WUS 196
#define NLS 68

typedef unsigned long long u64;

__device__ __forceinline__ void ffma2(u64 &d, u64 a, u64 b) {
    asm("fma.rn.f32x2 %0, %1, %2, %0;" : "+l"(d) : "l"(a), "l"(b));
}
__device__ __forceinline__ float f2sum(u64 a) {
    float lo, hi;
    asm("mov.b64 {%0, %1}, %2;" : "=f"(lo), "=f"(hi) : "l"(a));
    return lo + hi;
}
__device__ __forceinline__ void red_add_v4(float* p, float4 v) {
    u64 gp;
    asm("cvta.to.global.u64 %0, %1;" : "=l"(gp) : "l"(p));
    asm volatile("red.global.add.v4.f32 [%0], {%1, %2, %3, %4};"
                 :: "l"(gp), "f"(v.x), "f"(v.y), "f"(v.z), "f"(v.w) : "memory");
}

// ---------------- scratch ----------------
__device__ float g_x[NN * DD];
__device__ float g_agg[NN * HH];     // segment-sum of h (pre-W2!)
__device__ float g_cnt[NN];
__device__ float g_pab[NN * PP];

// ---------------- init ----------------
__global__ void init_kernel() {
    int i = blockIdx.x * blockDim.x + threadIdx.x;
    const int A4 = NN * HH / 4;
    if (i < A4) ((float4*)g_agg)[i] = make_float4(0.f, 0.f, 0.f, 0.f);
    else if (i < A4 + NN / 4) ((float4*)g_cnt)[i - A4] = make_float4(0.f, 0.f, 0.f, 0.f);
}

__global__ void count_kernel(const int* __restrict__ dst) {
    int e = blockIdx.x * blockDim.x + threadIdx.x;
    if (e < NE) atomicAdd(&g_cnt[dst[e]], 1.0f);
}

// ---------------- fused embed + node_lin(layer0) ----------------
#define EMB_SMEM ((PP*NLS + FN*DD + DD + 8*FN + 8*DD) * 4)

__global__ void __launch_bounds__(256, 2)
embed_nl_kernel(const float* __restrict__ nf,
                const float* __restrict__ eW, const float* __restrict__ eb,
                const float* __restrict__ W1) {
    extern __shared__ float s[];
    float* sWt = s;                    // [256][68]
    float* sWe = sWt + PP * NLS;
    float* sBe = sWe + FN * DD;
    float* sNf = sBe + DD;
    float* sX  = sNf + 8 * FN;

    const int tid = threadIdx.x;
    for (int i = tid; i < DD * PP; i += 256) {
        int k = i >> 8, j = i & 255;
        sWt[j * NLS + k] = (j < HH) ? W1[k * HH + j] : W1[(DD + k) * HH + (j - HH)];
    }
    for (int i = tid; i < FN * DD; i += 256) sWe[i] = eW[i];
    if (tid < DD) sBe[tid] = eb[tid];
    __syncthreads();

    const int step = gridDim.x * 8;
    for (int n0 = blockIdx.x * 8; n0 < NN; n0 += step) {
        for (int i = tid; i < 8 * FN; i += 256) {
            int c = i / FN, f = i % FN;
            sNf[i] = nf[(n0 + c) * FN + f];
        }
        __syncthreads();
        for (int i = tid; i < 8 * DD; i += 256) {
            int c = i >> 6, d = i & 63;
            float xv = sBe[d];
#pragma unroll
            for (int f = 0; f < FN; f++) xv += sNf[c * FN + f] * sWe[f * DD + d];
            xv = fmaxf(xv, 0.f);
            sX[c * DD + d] = xv;
            g_x[(n0 + c) * DD + d] = xv;
        }
        __syncthreads();
        u64 acc[8];
#pragma unroll
        for (int c = 0; c < 8; c++) acc[c] = 0ull;
        const float* wr = sWt + tid * NLS;
#pragma unroll 4
        for (int k = 0; k < DD; k += 4) {
            ulonglong2 w = *(const ulonglong2*)(wr + k);
#pragma unroll
            for (int c = 0; c < 8; c++) {
                ulonglong2 v = *(const ulonglong2*)(sX + c * DD + k);
                ffma2(acc[c], w.x, v.x);
                ffma2(acc[c], w.y, v.y);
            }
        }
#pragma unroll
        for (int c = 0; c < 8; c++)
            g_pab[(size_t)(n0 + c) * PP + tid] = f2sum(acc[c]);
        __syncthreads();
    }
}

// ---------------- edge message: phaseA + scatter of h (NO GEMM2) ----------------
#define MSG_SMEM ((EPB*HH + EPB*FE + 2*EPB) * 4)

__global__ void __launch_bounds__(512, 2)
msg_kernel(const float* __restrict__ ea,
           const int* __restrict__ src, const int* __restrict__ dst,
           const float* __restrict__ W1, const float* __restrict__ b1) {
    extern __shared__ float s[];
    float* sH   = s;                       // [128][128]
    float* sEa  = sH + EPB * HH;           // [128][8]
    int*   sSrc = (int*)(sEa + EPB * FE);  // [128]
    int*   sDst = sSrc + EPB;              // [128]

    const int tid = threadIdx.x;
    const int j = tid & 127, g = tid >> 7;       // phaseA: 4 groups, 32 edges/thread
    const int wid = tid >> 5, lane = tid & 31;   // scatter: 16 warps x 8 edges
    const float b1v = b1[j];
    float w1c[8];
#pragma unroll
    for (int f = 0; f < 8; f++) w1c[f] = W1[(2 * DD + f) * HH + j];

    int e0 = blockIdx.x * EPB;
    const int step = gridDim.x * EPB;

    for (; e0 < NE; e0 += step) {
        __syncthreads();                         // prior tile fully scattered
        // ---- stage indices + edge attrs ----
        if (tid < 2 * EPB) {
            int le = tid & (EPB - 1);
            int gc = e0 + le; if (gc >= NE) gc = NE - 1;
            if (tid < EPB) sSrc[le] = src[gc];
            else           sDst[le] = dst[gc];
        }
        for (int i = tid; i < EPB * 2; i += 512) {   // 256 float4 = ea tile
            int le = i >> 1, frag = i & 1;
            int gc = e0 + le; if (gc >= NE) gc = NE - 1;
            ((float4*)sEa)[i] = ((const float4*)ea)[(size_t)gc * 2 + frag];
        }
        __syncthreads();

        // ---- phase A: h = relu(Pa[src] + Pb[dst] + ea@W1c + b1), pipelined LDG ----
        {
            float pa[4], pb[4];
#pragma unroll
            for (int c = 0; c < 4; c++) {
                int e = g + 4 * c;
                pa[c] = g_pab[(size_t)sSrc[e] * PP + j];
                pb[c] = g_pab[(size_t)sDst[e] * PP + HH + j];
            }
#pragma unroll
            for (int c = 0; c < 32; c++) {
                int e = g + 4 * c;
                float hv = pa[c & 3] + pb[c & 3] + b1v;
                if (c + 4 < 32) {
                    int e2 = g + 4 * (c + 4);
                    pa[c & 3] = g_pab[(size_t)sSrc[e2] * PP + j];
                    pb[c & 3] = g_pab[(size_t)sDst[e2] * PP + HH + j];
                }
                float4 a0 = ((const float4*)(sEa + e * FE))[0];
                float4 a1 = ((const float4*)(sEa + e * FE))[1];
                hv = fmaf(a0.x, w1c[0], hv); hv = fmaf(a0.y, w1c[1], hv);
                hv = fmaf(a0.z, w1c[2], hv); hv = fmaf(a0.w, w1c[3], hv);
                hv = fmaf(a1.x, w1c[4], hv); hv = fmaf(a1.y, w1c[5], hv);
                hv = fmaf(a1.z, w1c[6], hv); hv = fmaf(a1.w, w1c[7], hv);
                sH[e * HH + j] = fmaxf(hv, 0.f);
            }
        }
        __syncthreads();                         // sH visible

        // ---- scatter h: warp -> its 8 edges ----
#pragma unroll
        for (int t = 0; t < 8; t++) {
            int le = wid * 8 + t;
            if (e0 + le < NE) {
                float4 m = ((const float4*)(sH + le * HH))[lane];
                red_add_v4(g_agg + (size_t)sDst[le] * HH + lane * 4, m);
            }
        }
    }
}

// ---------------- fused: aggH@W2 + mean + b2, upd MLP, LayerNorm, agg-zero, node_lin ----------------
#define UPDNL_SMEM ((HH*W2S + DD*WUS + PP*NLS + 4*DD + HH + 8*HH + 8 + 8*UIN + 8*DD + 32) * 4)

__global__ void __launch_bounds__(512, 1)
updnl_kernel(const float* __restrict__ W2, const float* __restrict__ b2,
             const float* __restrict__ W, const float* __restrict__ b,
             const float* __restrict__ lg, const float* __restrict__ lb,
             const float* __restrict__ W1next) {
    extern __shared__ float s[];
    float* sW2t  = s;                   // [128][132]  W2^T (rows = out ch)
    float* sWt   = sW2t + HH * W2S;     // [64][196]   upd W^T
    float* sWnl  = sWt + DD * WUS;      // [256][68]   next-layer W1
    float* sB    = sWnl + PP * NLS;     // 64
    float* sG    = sB + DD;             // 64
    float* sLB   = sG + DD;             // 64
    float* sB2   = sLB + DD;            // 128 (+64 pad slot)
    float* sAggH = sB2 + HH + DD;       // [8][128]
    float* sCnt  = sAggH + 8 * HH;      // 8
    float* sNin  = sCnt + 8;            // [8][192]
    float* sXn   = sNin + 8 * UIN;      // [8][64]
    float* sRed  = sXn + 8 * DD;        // 32

    const int tid = threadIdx.x;
    for (int i = tid; i < HH * HH; i += 512) { int k = i >> 7, j = i & 127; sW2t[j * W2S + k] = W2[i]; }
    for (int i = tid; i < UIN * DD; i += 512) { int k = i >> 6, d = i & 63; sWt[d * WUS + k] = W[i]; }
    for (int i = tid; i < DD * PP; i += 512) {
        int k = i >> 8, j = i & 255;
        sWnl[j * NLS + k] = (j < HH) ? W1next[k * HH + j] : W1next[(DD + k) * HH + (j - HH)];
    }
    if (tid < DD) { sB[tid] = b[tid]; sG[tid] = lg[tid]; sLB[tid] = lb[tid]; }
    if (tid < HH) sB2[tid] = b2[tid];
    __syncthreads();

    const int d = tid & 63, ln = tid >> 6;       // upd: 8 nodes x 64 ch
    const int wg = (tid >> 5) & 1, lane = tid & 31;
    const int jm = tid & 127, gm = tid >> 7;     // magg: 4 groups x 128 ch, 2 nodes each
    const int j = tid & 255, grp = tid >> 8;     // node_lin: 2 groups x 256 ch, 4 nodes each
    const float bv = sB[d], gv = sG[d], lbv = sLB[d];
    const float b2v = sB2[jm];

    for (int n0 = blockIdx.x * 8; n0 < NN; n0 += gridDim.x * 8) {
        // ---- stage x, aggH, cnt ----
        for (int i = tid; i < 8 * DD; i += 512) {
            int c = i >> 6, dd = i & 63;
            int n = n0 + c;
            sNin[c * UIN + dd] = (n < NN) ? g_x[n * DD + dd] : 0.f;
        }
        for (int i = tid; i < 8 * HH; i += 512) {
            int c = i >> 7, k = i & 127;
            int n = n0 + c;
            sAggH[c * HH + k] = (n < NN) ? g_agg[(size_t)n * HH + k] : 0.f;
        }
        if (tid < 8) sCnt[tid] = (n0 + tid < NN) ? g_cnt[n0 + tid] : 0.f;
        __syncthreads();
        // zero agg rows for next layer (reads complete)
        if (tid < 256) {
            int n = n0 + (tid >> 5);
            if (n < NN) ((float4*)(g_agg + (size_t)n * HH))[tid & 31] = make_float4(0.f, 0.f, 0.f, 0.f);
        }

        // ---- magg = (aggH @ W2 + cnt*b2) / (cnt + eps) : nodes {gm, gm+4} ----
        {
            u64 a0 = 0ull, a1 = 0ull;
            const float* wr2 = sW2t + jm * W2S;
            const float* v0p = sAggH + gm * HH;
            const float* v1p = sAggH + (gm + 4) * HH;
#pragma unroll 4
            for (int k = 0; k < HH; k += 4) {
                ulonglong2 w = *(const ulonglong2*)(wr2 + k);
                ulonglong2 v0 = *(const ulonglong2*)(v0p + k);
                ulonglong2 v1 = *(const ulonglong2*)(v1p + k);
                ffma2(a0, w.x, v0.x); ffma2(a0, w.y, v0.y);
                ffma2(a1, w.x, v1.x); ffma2(a1, w.y, v1.y);
            }
            float c0 = sCnt[gm],     i0 = 1.f / (c0 + 1e-6f);
            float c1 = sCnt[gm + 4], i1 = 1.f / (c1 + 1e-6f);
            sNin[gm * UIN + DD + jm]       = (f2sum(a0) + c0 * b2v) * i0;
            sNin[(gm + 4) * UIN + DD + jm] = (f2sum(a1) + c1 * b2v) * i1;
        }
        __syncthreads();

        // ---- upd MLP + residual ----
        u64 a0 = 0ull;
        const float* wr = sWt + d * WUS;
        const float* in0 = sNin + ln * UIN;
#pragma unroll 4
        for (int k = 0; k < UIN; k += 4) {
            ulonglong2 w = *(const ulonglong2*)(wr + k);
            ulonglong2 v = *(const ulonglong2*)(in0 + k);
            ffma2(a0, w.x, v.x);
            ffma2(a0, w.y, v.y);
        }
        float outv = in0[d] + fmaxf(f2sum(a0) + bv, 0.f);

        // ---- LayerNorm ----
        float s1 = outv, s2 = outv * outv;
#pragma unroll
        for (int off = 16; off; off >>= 1) {
            s1 += __shfl_xor_sync(0xFFFFFFFFu, s1, off);
            s2 += __shfl_xor_sync(0xFFFFFFFFu, s2, off);
        }
        if (lane == 0) { sRed[(ln * 2 + wg) * 2] = s1; sRed[(ln * 2 + wg) * 2 + 1] = s2; }
        __syncthreads();
        {
            float t1 = sRed[ln * 4] + sRed[ln * 4 + 2];
            float t2 = sRed[ln * 4 + 1] + sRed[ln * 4 + 3];
            float mu = t1 * (1.f / DD);
            float var = t2 * (1.f / DD) - mu * mu;
            float xn = (outv - mu) * rsqrtf(var + 1e-5f) * gv + lbv;
            int n = n0 + ln;
            if (n < NN) g_x[n * DD + d] = xn;
            sXn[ln * DD + d] = xn;
        }
        __syncthreads();

        // ---- node_lin for next layer ----
        u64 acc[4];
#pragma unroll
        for (int c = 0; c < 4; c++) acc[c] = 0ull;
        const float* wr2 = sWnl + j * NLS;
#pragma unroll 4
        for (int k = 0; k < DD; k += 4) {
            ulonglong2 w = *(const ulonglong2*)(wr2 + k);
#pragma unroll
            for (int c = 0; c < 4; c++) {
                ulonglong2 v = *(const ulonglong2*)(sXn + (grp + 2 * c) * DD + k);
                ffma2(acc[c], w.x, v.x);
                ffma2(acc[c], w.y, v.y);
            }
        }
#pragma unroll
        for (int c = 0; c < 4; c++) {
            int n = n0 + grp + 2 * c;
            if (n < NN) g_pab[(size_t)n * PP + j] = f2sum(acc[c]);
        }
        __syncthreads();
    }
}

// ---------------- edge predictor (unchanged from R9) ----------------
#define PRED_SMEM ((DD*W2S + DD + EPB*HH + EPB*DD + EPB*FE + 2*EPB) * 4)

__global__ void __launch_bounds__(512, 1)
pred_kernel(const float* __restrict__ ea,
            const int* __restrict__ src, const int* __restrict__ dst,
            const float* __restrict__ W1, const float* __restrict__ b1,
            const float* __restrict__ W2, const float* __restrict__ b2,
            const float* __restrict__ W3, const float* __restrict__ b3,
            float* __restrict__ out) {
    extern __shared__ float s[];
    float* sW2t = s;                   // [64][132]
    float* sW3  = sW2t + DD * W2S;     // [64]
    float* sH1  = sW3 + DD;            // [128][128]
    float* sH2  = sH1 + EPB * HH;      // [128][64]
    float* sEa  = sH2 + EPB * DD;      // [128][8]
    int*   sSrc = (int*)(sEa + EPB * FE);
    int*   sDst = sSrc + EPB;

    const int tid = threadIdx.x;
    for (int i = tid; i < HH * DD; i += 512) { int k = i >> 6, jj = i & 63; sW2t[jj * W2S + k] = W2[i]; }
    if (tid < DD) sW3[tid] = W3[tid];

    const int j = tid & 127, g = tid >> 7;
    const int j2 = tid & 31, eg = tid >> 5;      // GEMM2: E8 x C2
    const int wid = tid >> 5, lane = tid & 31;
    const float b1v = b1[j], b2lo = b2[j2], b2hi = b2[j2 + 32], b3v = b3[0];
    float w1c[8];
#pragma unroll
    for (int f = 0; f < 8; f++) w1c[f] = W1[(2 * DD + f) * HH + j];

    int e0 = blockIdx.x * EPB;
    const int step = gridDim.x * EPB;

    for (; e0 < NE; e0 += step) {
        __syncthreads();
        if (tid < 2 * EPB) {
            int le = tid & (EPB - 1);
            int gc = e0 + le; if (gc >= NE) gc = NE - 1;
            if (tid < EPB) sSrc[le] = src[gc];
            else           sDst[le] = dst[gc];
        }
        for (int i = tid; i < EPB * 2; i += 512) {
            int le = i >> 1, frag = i & 1;
            int gc = e0 + le; if (gc >= NE) gc = NE - 1;
            ((float4*)sEa)[i] = ((const float4*)ea)[(size_t)gc * 2 + frag];
        }
        __syncthreads();

        // phase A
        {
            float pa[8], pb[8];
#pragma unroll
            for (int c = 0; c < 8; c++) {
                int e = g + 4 * c;
                pa[c] = g_pab[(size_t)sSrc[e] * PP + j];
                pb[c] = g_pab[(size_t)sDst[e] * PP + HH + j];
            }
#pragma unroll
            for (int c = 0; c < 32; c++) {
                int e = g + 4 * c;
                float hv = pa[c & 7] + pb[c & 7] + b1v;
                if (c + 8 < 32) {
                    int e2 = g + 4 * (c + 8);
                    pa[c & 7] = g_pab[(size_t)sSrc[e2] * PP + j];
                    pb[c & 7] = g_pab[(size_t)sDst[e2] * PP + HH + j];
                }
                float4 a0 = ((const float4*)(sEa + e * FE))[0];
                float4 a1 = ((const float4*)(sEa + e * FE))[1];
                hv = fmaf(a0.x, w1c[0], hv); hv = fmaf(a0.y, w1c[1], hv);
                hv = fmaf(a0.z, w1c[2], hv); hv = fmaf(a0.w, w1c[3], hv);
                hv = fmaf(a1.x, w1c[4], hv); hv = fmaf(a1.y, w1c[5], hv);
                hv = fmaf(a1.z, w1c[6], hv); hv = fmaf(a1.w, w1c[7], hv);
                sH1[e * HH + j] = fmaxf(hv, 0.f);
            }
        }
        __syncthreads();

        // GEMM2: 128 -> 64, E=8 x C=2 per thread
        {
            u64 acc[16];
#pragma unroll
            for (int c = 0; c < 16; c++) acc[c] = 0ull;
            const float* wr0 = sW2t + j2 * W2S;
            const float* wr1 = wr0 + 32 * W2S;
#pragma unroll 2
            for (int k = 0; k < HH; k += 4) {
                ulonglong2 w0 = *(const ulonglong2*)(wr0 + k);
                ulonglong2 w1 = *(const ulonglong2*)(wr1 + k);
#pragma unroll
                for (int c = 0; c < 8; c++) {
                    ulonglong2 v = *(const ulonglong2*)(sH1 + (eg + 16 * c) * HH + k);
                    ffma2(acc[2 * c],     w0.x, v.x);
                    ffma2(acc[2 * c],     w0.y, v.y);
                    ffma2(acc[2 * c + 1], w1.x, v.x);
                    ffma2(acc[2 * c + 1], w1.y, v.y);
                }
            }
#pragma unroll
            for (int c = 0; c < 8; c++) {
                int e = eg + 16 * c;
                sH2[e * DD + j2]      = fmaxf(f2sum(acc[2 * c]) + b2lo, 0.f);
                sH2[e * DD + 32 + j2] = fmaxf(f2sum(acc[2 * c + 1]) + b2hi, 0.f);
            }
        }
        __syncthreads();

        // final dot 64 -> 1 + tanh : warp -> its 8 edges
#pragma unroll
        for (int t = 0; t < 8; t++) {
            int le = wid * 8 + t, ge = e0 + le;
            float v = sH2[le * DD + lane] * sW3[lane]
                    + sH2[le * DD + 32 + lane] * sW3[32 + lane];
#pragma unroll
            for (int off = 16; off; off >>= 1) v += __shfl_xor_sync(0xFFFFFFFFu, v, off);
            if (lane == 0 && ge < NE) out[ge] = tanhf(v + b3v);
        }
    }
}

// ---------------- launch ----------------
extern "C" void kernel_launch(void* const* d_in, const int* in_sizes, int n_in,
                              void* d_out, int out_size) {
    const float* node_features = (const float*)d_in[0];
    const float* edge_attr     = (const float*)d_in[1];
    const float* embed_W       = (const float*)d_in[2];
    const float* embed_b       = (const float*)d_in[3];
    const float* msg_W1        = (const float*)d_in[4];
    const float* msg_b1        = (const float*)d_in[5];
    const float* msg_W2        = (const float*)d_in[6];
    const float* msg_b2        = (const float*)d_in[7];
    const float* upd_W         = (const float*)d_in[8];
    const float* upd_b         = (const float*)d_in[9];
    const float* ln_g          = (const float*)d_in[10];
    const float* ln_b          = (const float*)d_in[11];
    const float* pred_W1       = (const float*)d_in[12];
    const float* pred_b1       = (const float*)d_in[13];
    const float* pred_W2       = (const float*)d_in[14];
    const float* pred_b2       = (const float*)d_in[15];
    const float* pred_W3       = (const float*)d_in[16];
    const float* pred_b3       = (const float*)d_in[17];
    const int*   edge_index    = (const int*)d_in[18];
    float* out = (float*)d_out;

    const int* src = edge_index;
    const int* dst = edge_index + NE;

    cudaFuncSetAttribute(msg_kernel,      cudaFuncAttributeMaxDynamicSharedMemorySize, MSG_SMEM);
    cudaFuncSetAttribute(pred_kernel,     cudaFuncAttributeMaxDynamicSharedMemorySize, PRED_SMEM);
    cudaFuncSetAttribute(updnl_kernel,    cudaFuncAttributeMaxDynamicSharedMemorySize, UPDNL_SMEM);
    cudaFuncSetAttribute(embed_nl_kernel, cudaFuncAttributeMaxDynamicSharedMemorySize, EMB_SMEM);

    init_kernel<<<(NN * HH / 4 + NN / 4 + 255) / 256, 256>>>();
    count_kernel<<<(NE + 255) / 256, 256>>>(dst);
    embed_nl_kernel<<<296, 256, EMB_SMEM>>>(node_features, embed_W, embed_b, msg_W1);

    for (int l = 0; l < LL; l++) {
        // launch index 3 on l=0 -> ncu profiles msg_kernel
        msg_kernel<<<296, 512, MSG_SMEM>>>(edge_attr, src, dst,
                                           msg_W1 + l * EIN * HH, msg_b1 + l * HH);
        const float* nextW1 = (l < LL - 1) ? (msg_W1 + (l + 1) * EIN * HH) : pred_W1;
        updnl_kernel<<<148, 512, UPDNL_SMEM>>>(msg_W2 + l * HH * HH, msg_b2 + l * HH,
                                               upd_W + l * UIN * DD, upd_b + l * DD,
                                               ln_g + l * DD, ln_b + l * DD, nextW1);
    }

    pred_kernel<<<148, 512, PRED_SMEM>>>(edge_attr, src, dst,
                                         pred_W1, pred_b1, pred_W2, pred_b2,
                                         pred_W3, pred_b3, out);
}

// round 11
// speedup vs baseline: 2.0240x; 1.1639x over previous
#include <cuda_runtime.h>
#include <math.h>

#define NN 50000
#define NE 500000
#define FN 7
#define FE 8
#define DD 64
#define HH 128
#define PP 256           // Pab width (src-part 128 | dst-part 128)
#define EIN 136
#define UIN 192
#define LL 3
#define EPB 128          // edges per block-iteration (msg)
#define EPP 64           // edges per block-iteration (pred)

// padded weight strides (multiple of 4 floats -> 16B aligned)
#define W2S 132
#define WUS 196
#define NLS 68

typedef unsigned long long u64;

__device__ __forceinline__ void ffma2(u64 &d, u64 a, u64 b) {
    asm("fma.rn.f32x2 %0, %1, %2, %0;" : "+l"(d) : "l"(a), "l"(b));
}
__device__ __forceinline__ float f2sum(u64 a) {
    float lo, hi;
    asm("mov.b64 {%0, %1}, %2;" : "=f"(lo), "=f"(hi) : "l"(a));
    return lo + hi;
}
__device__ __forceinline__ void red_add_v4(float* p, float4 v) {
    u64 gp;
    asm("cvta.to.global.u64 %0, %1;" : "=l"(gp) : "l"(p));
    asm volatile("red.global.add.v4.f32 [%0], {%1, %2, %3, %4};"
                 :: "l"(gp), "f"(v.x), "f"(v.y), "f"(v.z), "f"(v.w) : "memory");
}
__device__ __forceinline__ void cp16(unsigned saddr, const void* g) {
    asm volatile("cp.async.cg.shared.global [%0], [%1], 16;" :: "r"(saddr), "l"(g));
}
#define CP_COMMIT()   asm volatile("cp.async.commit_group;" ::: "memory")
#define CP_WAIT_ALL() asm volatile("cp.async.wait_group 0;" ::: "memory")

// ---------------- scratch ----------------
__device__ float g_x[NN * DD];
__device__ float g_agg[NN * HH];     // segment-sum of h (pre-W2)
__device__ float g_cnt[NN];
__device__ float g_pab[NN * PP];

// ---------------- init ----------------
__global__ void init_kernel() {
    int i = blockIdx.x * blockDim.x + threadIdx.x;
    const int A4 = NN * HH / 4;
    if (i < A4) ((float4*)g_agg)[i] = make_float4(0.f, 0.f, 0.f, 0.f);
    else if (i < A4 + NN / 4) ((float4*)g_cnt)[i - A4] = make_float4(0.f, 0.f, 0.f, 0.f);
}

__global__ void count_kernel(const int* __restrict__ dst) {
    int e = blockIdx.x * blockDim.x + threadIdx.x;
    if (e < NE) atomicAdd(&g_cnt[dst[e]], 1.0f);
}

// ---------------- fused embed + node_lin(layer0) ----------------
#define EMB_SMEM ((PP*NLS + FN*DD + DD + 8*FN + 8*DD) * 4)

__global__ void __launch_bounds__(256, 2)
embed_nl_kernel(const float* __restrict__ nf,
                const float* __restrict__ eW, const float* __restrict__ eb,
                const float* __restrict__ W1) {
    extern __shared__ float s[];
    float* sWt = s;                    // [256][68]
    float* sWe = sWt + PP * NLS;
    float* sBe = sWe + FN * DD;
    float* sNf = sBe + DD;
    float* sX  = sNf + 8 * FN;

    const int tid = threadIdx.x;
    for (int i = tid; i < DD * PP; i += 256) {
        int k = i >> 8, j = i & 255;
        sWt[j * NLS + k] = (j < HH) ? W1[k * HH + j] : W1[(DD + k) * HH + (j - HH)];
    }
    for (int i = tid; i < FN * DD; i += 256) sWe[i] = eW[i];
    if (tid < DD) sBe[tid] = eb[tid];
    __syncthreads();

    const int step = gridDim.x * 8;
    for (int n0 = blockIdx.x * 8; n0 < NN; n0 += step) {
        for (int i = tid; i < 8 * FN; i += 256) {
            int c = i / FN, f = i % FN;
            sNf[i] = nf[(n0 + c) * FN + f];
        }
        __syncthreads();
        for (int i = tid; i < 8 * DD; i += 256) {
            int c = i >> 6, d = i & 63;
            float xv = sBe[d];
#pragma unroll
            for (int f = 0; f < FN; f++) xv += sNf[c * FN + f] * sWe[f * DD + d];
            xv = fmaxf(xv, 0.f);
            sX[c * DD + d] = xv;
            g_x[(n0 + c) * DD + d] = xv;
        }
        __syncthreads();
        u64 acc[8];
#pragma unroll
        for (int c = 0; c < 8; c++) acc[c] = 0ull;
        const float* wr = sWt + tid * NLS;
#pragma unroll 4
        for (int k = 0; k < DD; k += 4) {
            ulonglong2 w = *(const ulonglong2*)(wr + k);
#pragma unroll
            for (int c = 0; c < 8; c++) {
                ulonglong2 v = *(const ulonglong2*)(sX + c * DD + k);
                ffma2(acc[c], w.x, v.x);
                ffma2(acc[c], w.y, v.y);
            }
        }
#pragma unroll
        for (int c = 0; c < 8; c++)
            g_pab[(size_t)(n0 + c) * PP + tid] = f2sum(acc[c]);
        __syncthreads();
    }
}

// ---------------- edge message: phaseA + scatter of h (NO GEMM2) ----------------
#define MSG_SMEM ((EPB*HH + EPB*FE + 2*EPB) * 4)

__global__ void __launch_bounds__(512, 2)
msg_kernel(const float* __restrict__ ea,
           const int* __restrict__ src, const int* __restrict__ dst,
           const float* __restrict__ W1, const float* __restrict__ b1) {
    extern __shared__ float s[];
    float* sH   = s;                       // [128][128]
    float* sEa  = sH + EPB * HH;           // [128][8]
    int*   sSrc = (int*)(sEa + EPB * FE);  // [128]
    int*   sDst = sSrc + EPB;              // [128]

    const int tid = threadIdx.x;
    const int j = tid & 127, g = tid >> 7;       // phaseA: 4 groups, 32 edges/thread
    const int wid = tid >> 5, lane = tid & 31;   // scatter: 16 warps x 8 edges
    const float b1v = b1[j];
    float w1c[8];
#pragma unroll
    for (int f = 0; f < 8; f++) w1c[f] = W1[(2 * DD + f) * HH + j];

    int e0 = blockIdx.x * EPB;
    const int step = gridDim.x * EPB;

    for (; e0 < NE; e0 += step) {
        __syncthreads();                         // prior tile fully scattered
        if (tid < 2 * EPB) {
            int le = tid & (EPB - 1);
            int gc = e0 + le; if (gc >= NE) gc = NE - 1;
            if (tid < EPB) sSrc[le] = src[gc];
            else           sDst[le] = dst[gc];
        }
        for (int i = tid; i < EPB * 2; i += 512) {
            int le = i >> 1, frag = i & 1;
            int gc = e0 + le; if (gc >= NE) gc = NE - 1;
            ((float4*)sEa)[i] = ((const float4*)ea)[(size_t)gc * 2 + frag];
        }
        __syncthreads();

        // phase A: h = relu(Pa[src] + Pb[dst] + ea@W1c + b1), pipelined LDG
        {
            float pa[4], pb[4];
#pragma unroll
            for (int c = 0; c < 4; c++) {
                int e = g + 4 * c;
                pa[c] = g_pab[(size_t)sSrc[e] * PP + j];
                pb[c] = g_pab[(size_t)sDst[e] * PP + HH + j];
            }
#pragma unroll
            for (int c = 0; c < 32; c++) {
                int e = g + 4 * c;
                float hv = pa[c & 3] + pb[c & 3] + b1v;
                if (c + 4 < 32) {
                    int e2 = g + 4 * (c + 4);
                    pa[c & 3] = g_pab[(size_t)sSrc[e2] * PP + j];
                    pb[c & 3] = g_pab[(size_t)sDst[e2] * PP + HH + j];
                }
                float4 a0 = ((const float4*)(sEa + e * FE))[0];
                float4 a1 = ((const float4*)(sEa + e * FE))[1];
                hv = fmaf(a0.x, w1c[0], hv); hv = fmaf(a0.y, w1c[1], hv);
                hv = fmaf(a0.z, w1c[2], hv); hv = fmaf(a0.w, w1c[3], hv);
                hv = fmaf(a1.x, w1c[4], hv); hv = fmaf(a1.y, w1c[5], hv);
                hv = fmaf(a1.z, w1c[6], hv); hv = fmaf(a1.w, w1c[7], hv);
                sH[e * HH + j] = fmaxf(hv, 0.f);
            }
        }
        __syncthreads();

        // scatter h: warp -> its 8 edges
#pragma unroll
        for (int t = 0; t < 8; t++) {
            int le = wid * 8 + t;
            if (e0 + le < NE) {
                float4 m = ((const float4*)(sH + le * HH))[lane];
                red_add_v4(g_agg + (size_t)sDst[le] * HH + lane * 4, m);
            }
        }
    }
}

// ---------------- fused node kernel with cp.async double-buffered staging ----------------
// NN % 8 == 0 -> no tail guards anywhere here.
#define NPT 8    // nodes per tile
#define STG (NPT*DD + NPT*HH + NPT)   // staged floats per buffer (x | aggH | cnt)
#define UPDNL_SMEM ((HH*W2S + DD*WUS + PP*NLS + 3*DD + HH + 2*STG + NPT*HH + NPT*DD + 32) * 4)

__global__ void __launch_bounds__(512, 1)
updnl_kernel(const float* __restrict__ W2, const float* __restrict__ b2,
             const float* __restrict__ W, const float* __restrict__ b,
             const float* __restrict__ lg, const float* __restrict__ lb,
             const float* __restrict__ W1next) {
    extern __shared__ float s[];
    float* sW2t  = s;                   // [128][132]
    float* sWt   = sW2t + HH * W2S;     // [64][196]
    float* sWnl  = sWt + DD * WUS;      // [256][68]
    float* sB    = sWnl + PP * NLS;     // 64
    float* sG    = sB + DD;             // 64
    float* sLB   = sG + DD;             // 64
    float* sB2   = sLB + DD;            // 128
    float* sStg  = sB2 + HH;            // [2][STG]   x[8*64] | aggH[8*128] | cnt[8]
    float* sMagg = sStg + 2 * STG;      // [8][128]
    float* sXn   = sMagg + NPT * HH;    // [8][64]
    float* sRed  = sXn + NPT * DD;      // 32

    const unsigned aStg = (unsigned)__cvta_generic_to_shared(sStg);

    const int tid = threadIdx.x;
    for (int i = tid; i < HH * HH; i += 512) { int k = i >> 7, j = i & 127; sW2t[j * W2S + k] = W2[i]; }
    for (int i = tid; i < UIN * DD; i += 512) { int k = i >> 6, d = i & 63; sWt[d * WUS + k] = W[i]; }
    for (int i = tid; i < DD * PP; i += 512) {
        int k = i >> 8, j = i & 255;
        sWnl[j * NLS + k] = (j < HH) ? W1next[k * HH + j] : W1next[(DD + k) * HH + (j - HH)];
    }
    if (tid < DD) { sB[tid] = b[tid]; sG[tid] = lg[tid]; sLB[tid] = lb[tid]; }
    if (tid < HH) sB2[tid] = b2[tid];

    const int d = tid & 63, ln = tid >> 6;
    const int wg = (tid >> 5) & 1, lane = tid & 31;
    const int jm = tid & 127, gm = tid >> 7;
    const int j = tid & 255, grp = tid >> 8;
    const float bv = b[d], gv = lg[d], lbv = lb[d];
    const float b2v = b2[jm];

    const int stride = gridDim.x * NPT;

    // staging maps: x -> 128 cp16 (tid<128), aggH -> 256 cp16 (tid<256 with 2 each), cnt -> 2 cp16
#define STAGE(N0, B) { \
    unsigned base = aStg + (B) * STG * 4; \
    if (tid < 128) { \
        int node = tid >> 4, frag = tid & 15; \
        cp16(base + (node * DD + frag * 4) * 4, g_x + (size_t)((N0) + node) * DD + frag * 4); } \
    else if (tid < 384) { \
        int t2 = tid - 128; \
        int node = t2 >> 5, frag = t2 & 31; \
        cp16(base + (NPT * DD + node * HH + frag * 4) * 4, \
             g_agg + (size_t)((N0) + node) * HH + frag * 4); } \
    else if (tid < 386) { \
        cp16(base + (NPT * DD + NPT * HH + (tid - 384) * 4) * 4, g_cnt + (N0) + (tid - 384) * 4); } }

    int n0 = blockIdx.x * NPT;
    if (n0 < NN) { STAGE(n0, 0); }
    CP_COMMIT();
    __syncthreads();          // also covers weight staging

    int buf = 0;
    for (; n0 < NN; n0 += stride, buf ^= 1) {
        CP_WAIT_ALL();
        __syncthreads();                         // staged tile visible; old buf free

        const float* sX   = sStg + buf * STG;
        const float* sAgg = sX + NPT * DD;
        const float* sCnt = sAgg + NPT * HH;

        // zero agg rows of this tile (staged copy already in smem)
        if (tid < 256) {
            int nn = n0 + (tid >> 5);
            ((float4*)(g_agg + (size_t)nn * HH))[tid & 31] = make_float4(0.f, 0.f, 0.f, 0.f);
        }
        // prefetch next tile
        int nnext = n0 + stride;
        if (nnext < NN) { STAGE(nnext, buf ^ 1); }
        CP_COMMIT();

        // ---- magg = (aggH @ W2 + cnt*b2)/(cnt+eps) : nodes {gm, gm+4} ----
        {
            u64 a0 = 0ull, a1 = 0ull;
            const float* wr2 = sW2t + jm * W2S;
            const float* v0p = sAgg + gm * HH;
            const float* v1p = sAgg + (gm + 4) * HH;
#pragma unroll 4
            for (int k = 0; k < HH; k += 4) {
                ulonglong2 w = *(const ulonglong2*)(wr2 + k);
                ulonglong2 v0 = *(const ulonglong2*)(v0p + k);
                ulonglong2 v1 = *(const ulonglong2*)(v1p + k);
                ffma2(a0, w.x, v0.x); ffma2(a0, w.y, v0.y);
                ffma2(a1, w.x, v1.x); ffma2(a1, w.y, v1.y);
            }
            float c0 = sCnt[gm],     i0 = 1.f / (c0 + 1e-6f);
            float c1 = sCnt[gm + 4], i1 = 1.f / (c1 + 1e-6f);
            sMagg[gm * HH + jm]       = (f2sum(a0) + c0 * b2v) * i0;
            sMagg[(gm + 4) * HH + jm] = (f2sum(a1) + c1 * b2v) * i1;
        }
        __syncthreads();

        // ---- upd MLP + residual (split-k: x part + magg part) ----
        u64 a0 = 0ull;
        const float* wr = sWt + d * WUS;
        const float* xin = sX + ln * DD;
        const float* min = sMagg + ln * HH;
#pragma unroll 4
        for (int k = 0; k < DD; k += 4) {
            ulonglong2 w = *(const ulonglong2*)(wr + k);
            ulonglong2 v = *(const ulonglong2*)(xin + k);
            ffma2(a0, w.x, v.x);
            ffma2(a0, w.y, v.y);
        }
#pragma unroll 4
        for (int k = 0; k < HH; k += 4) {
            ulonglong2 w = *(const ulonglong2*)(wr + DD + k);
            ulonglong2 v = *(const ulonglong2*)(min + k);
            ffma2(a0, w.x, v.x);
            ffma2(a0, w.y, v.y);
        }
        float outv = xin[d] + fmaxf(f2sum(a0) + bv, 0.f);

        // ---- LayerNorm ----
        float s1 = outv, s2 = outv * outv;
#pragma unroll
        for (int off = 16; off; off >>= 1) {
            s1 += __shfl_xor_sync(0xFFFFFFFFu, s1, off);
            s2 += __shfl_xor_sync(0xFFFFFFFFu, s2, off);
        }
        if (lane == 0) { sRed[(ln * 2 + wg) * 2] = s1; sRed[(ln * 2 + wg) * 2 + 1] = s2; }
        __syncthreads();
        {
            float t1 = sRed[ln * 4] + sRed[ln * 4 + 2];
            float t2 = sRed[ln * 4 + 1] + sRed[ln * 4 + 3];
            float mu = t1 * (1.f / DD);
            float var = t2 * (1.f / DD) - mu * mu;
            float xn = (outv - mu) * rsqrtf(var + 1e-5f) * gv + lbv;
            g_x[(size_t)(n0 + ln) * DD + d] = xn;
            sXn[ln * DD + d] = xn;
        }
        __syncthreads();

        // ---- node_lin for next layer ----
        u64 acc[4];
#pragma unroll
        for (int c = 0; c < 4; c++) acc[c] = 0ull;
        const float* wr2 = sWnl + j * NLS;
#pragma unroll 4
        for (int k = 0; k < DD; k += 4) {
            ulonglong2 w = *(const ulonglong2*)(wr2 + k);
#pragma unroll
            for (int c = 0; c < 4; c++) {
                ulonglong2 v = *(const ulonglong2*)(sXn + (grp + 2 * c) * DD + k);
                ffma2(acc[c], w.x, v.x);
                ffma2(acc[c], w.y, v.y);
            }
        }
#pragma unroll
        for (int c = 0; c < 4; c++)
            g_pab[(size_t)(n0 + grp + 2 * c) * PP + j] = f2sum(acc[c]);
        __syncthreads();
    }
#undef STAGE
}

// ---------------- edge predictor (EPP=64, 2 CTAs/SM) ----------------
#define PRED_SMEM ((DD*W2S + DD + EPP*HH + EPP*DD + EPP*FE + 2*EPP) * 4)

__global__ void __launch_bounds__(512, 2)
pred_kernel(const float* __restrict__ ea,
            const int* __restrict__ src, const int* __restrict__ dst,
            const float* __restrict__ W1, const float* __restrict__ b1,
            const float* __restrict__ W2, const float* __restrict__ b2,
            const float* __restrict__ W3, const float* __restrict__ b3,
            float* __restrict__ out) {
    extern __shared__ float s[];
    float* sW2t = s;                   // [64][132]
    float* sW3  = sW2t + DD * W2S;     // [64]
    float* sH1  = sW3 + DD;            // [64][128]
    float* sH2  = sH1 + EPP * HH;      // [64][64]
    float* sEa  = sH2 + EPP * DD;      // [64][8]
    int*   sSrc = (int*)(sEa + EPP * FE);
    int*   sDst = sSrc + EPP;

    const int tid = threadIdx.x;
    for (int i = tid; i < HH * DD; i += 512) { int k = i >> 6, jj = i & 63; sW2t[jj * W2S + k] = W2[i]; }
    if (tid < DD) sW3[tid] = W3[tid];

    const int j = tid & 127, g = tid >> 7;       // phaseA: 4 groups, 16 edges/thread
    const int j2 = tid & 31, eg = tid >> 5;      // GEMM2: E4 x C2 (eg in 0..15)
    const int wid = tid >> 5, lane = tid & 31;
    const float b1v = b1[j], b2lo = b2[j2], b2hi = b2[j2 + 32], b3v = b3[0];
    float w1c[8];
#pragma unroll
    for (int f = 0; f < 8; f++) w1c[f] = W1[(2 * DD + f) * HH + j];

    int e0 = blockIdx.x * EPP;
    const int step = gridDim.x * EPP;

    for (; e0 < NE; e0 += step) {
        __syncthreads();
        if (tid < 2 * EPP) {
            int le = tid & (EPP - 1);
            int gc = e0 + le; if (gc >= NE) gc = NE - 1;
            if (tid < EPP) sSrc[le] = src[gc];
            else           sDst[le] = dst[gc];
        }
        if (tid < EPP * 2) {
            int le = tid >> 1, frag = tid & 1;
            int gc = e0 + le; if (gc >= NE) gc = NE - 1;
            ((float4*)sEa)[tid] = ((const float4*)ea)[(size_t)gc * 2 + frag];
        }
        __syncthreads();

        // phase A: h1 = relu(Pa + Pb + ea@W1c + b1) : 16 edges/thread, pipelined
        {
            float pa[4], pb[4];
#pragma unroll
            for (int c = 0; c < 4; c++) {
                int e = g + 4 * c;
                pa[c] = g_pab[(size_t)sSrc[e] * PP + j];
                pb[c] = g_pab[(size_t)sDst[e] * PP + HH + j];
            }
#pragma unroll
            for (int c = 0; c < 16; c++) {
                int e = g + 4 * c;
                float hv = pa[c & 3] + pb[c & 3] + b1v;
                if (c + 4 < 16) {
                    int e2 = g + 4 * (c + 4);
                    pa[c & 3] = g_pab[(size_t)sSrc[e2] * PP + j];
                    pb[c & 3] = g_pab[(size_t)sDst[e2] * PP + HH + j];
                }
                float4 a0 = ((const float4*)(sEa + e * FE))[0];
                float4 a1 = ((const float4*)(sEa + e * FE))[1];
                hv = fmaf(a0.x, w1c[0], hv); hv = fmaf(a0.y, w1c[1], hv);
                hv = fmaf(a0.z, w1c[2], hv); hv = fmaf(a0.w, w1c[3], hv);
                hv = fmaf(a1.x, w1c[4], hv); hv = fmaf(a1.y, w1c[5], hv);
                hv = fmaf(a1.z, w1c[6], hv); hv = fmaf(a1.w, w1c[7], hv);
                sH1[e * HH + j] = fmaxf(hv, 0.f);
            }
        }
        __syncthreads();

        // GEMM2: 128 -> 64, E=4 x C=2 per thread
        {
            u64 acc[8];
#pragma unroll
            for (int c = 0; c < 8; c++) acc[c] = 0ull;
            const float* wr0 = sW2t + j2 * W2S;
            const float* wr1 = wr0 + 32 * W2S;
#pragma unroll 2
            for (int k = 0; k < HH; k += 4) {
                ulonglong2 w0 = *(const ulonglong2*)(wr0 + k);
                ulonglong2 w1 = *(const ulonglong2*)(wr1 + k);
#pragma unroll
                for (int c = 0; c < 4; c++) {
                    ulonglong2 v = *(const ulonglong2*)(sH1 + (eg + 16 * c) * HH + k);
                    ffma2(acc[2 * c],     w0.x, v.x);
                    ffma2(acc[2 * c],     w0.y, v.y);
                    ffma2(acc[2 * c + 1], w1.x, v.x);
                    ffma2(acc[2 * c + 1], w1.y, v.y);
                }
            }
#pragma unroll
            for (int c = 0; c < 4; c++) {
                int e = eg + 16 * c;
                sH2[e * DD + j2]      = fmaxf(f2sum(acc[2 * c]) + b2lo, 0.f);
                sH2[e * DD + 32 + j2] = fmaxf(f2sum(acc[2 * c + 1]) + b2hi, 0.f);
            }
        }
        __syncthreads();

        // final dot 64 -> 1 + tanh : warp -> its 4 edges
#pragma unroll
        for (int t = 0; t < 4; t++) {
            int le = wid * 4 + t, ge = e0 + le;
            float v = sH2[le * DD + lane] * sW3[lane]
                    + sH2[le * DD + 32 + lane] * sW3[32 + lane];
#pragma unroll
            for (int off = 16; off; off >>= 1) v += __shfl_xor_sync(0xFFFFFFFFu, v, off);
            if (lane == 0 && ge < NE) out[ge] = tanhf(v + b3v);
        }
    }
}

// ---------------- launch ----------------
extern "C" void kernel_launch(void* const* d_in, const int* in_sizes, int n_in,
                              void* d_out, int out_size) {
    const float* node_features = (const float*)d_in[0];
    const float* edge_attr     = (const float*)d_in[1];
    const float* embed_W       = (const float*)d_in[2];
    const float* embed_b       = (const float*)d_in[3];
    const float* msg_W1        = (const float*)d_in[4];
    const float* msg_b1        = (const float*)d_in[5];
    const float* msg_W2        = (const float*)d_in[6];
    const float* msg_b2        = (const float*)d_in[7];
    const float* upd_W         = (const float*)d_in[8];
    const float* upd_b         = (const float*)d_in[9];
    const float* ln_g          = (const float*)d_in[10];
    const float* ln_b          = (const float*)d_in[11];
    const float* pred_W1       = (const float*)d_in[12];
    const float* pred_b1       = (const float*)d_in[13];
    const float* pred_W2       = (const float*)d_in[14];
    const float* pred_b2       = (const float*)d_in[15];
    const float* pred_W3       = (const float*)d_in[16];
    const float* pred_b3       = (const float*)d_in[17];
    const int*   edge_index    = (const int*)d_in[18];
    float* out = (float*)d_out;

    const int* src = edge_index;
    const int* dst = edge_index + NE;

    cudaFuncSetAttribute(msg_kernel,      cudaFuncAttributeMaxDynamicSharedMemorySize, MSG_SMEM);
    cudaFuncSetAttribute(pred_kernel,     cudaFuncAttributeMaxDynamicSharedMemorySize, PRED_SMEM);
    cudaFuncSetAttribute(updnl_kernel,    cudaFuncAttributeMaxDynamicSharedMemorySize, UPDNL_SMEM);
    cudaFuncSetAttribute(embed_nl_kernel, cudaFuncAttributeMaxDynamicSharedMemorySize, EMB_SMEM);

    init_kernel<<<(NN * HH / 4 + NN / 4 + 255) / 256, 256>>>();
    count_kernel<<<(NE + 255) / 256, 256>>>(dst);
    embed_nl_kernel<<<296, 256, EMB_SMEM>>>(node_features, embed_W, embed_b, msg_W1);

    for (int l = 0; l < LL; l++) {
        // launch index 3 on l=0 -> ncu profiles msg_kernel
        msg_kernel<<<296, 512, MSG_SMEM>>>(edge_attr, src, dst,
                                           msg_W1 + l * EIN * HH, msg_b1 + l * HH);
        const float* nextW1 = (l < LL - 1) ? (msg_W1 + (l + 1) * EIN * HH) : pred_W1;
        updnl_kernel<<<148, 512, UPDNL_SMEM>>>(msg_W2 + l * HH * HH, msg_b2 + l * HH,
                                               upd_W + l * UIN * DD, upd_b + l * DD,
                                               ln_g + l * DD, ln_b + l * DD, nextW1);
    }

    pred_kernel<<<296, 512, PRED_SMEM>>>(edge_attr, src, dst,
                                         pred_W1, pred_b1, pred_W2, pred_b2,
                                         pred_W3, pred_b3, out);
}

// round 13
// speedup vs baseline: 2.2840x; 1.1284x over previous
#include <cuda_runtime.h>
#include <cuda_fp16.h>
#include <math.h>

#define NN 50000
#define NE 500000
#define FN 7
#define FE 8
#define DD 64
#define HH 128
#define PP 256           // Pab width (src-part 128 | dst-part 128)
#define EIN 136
#define UIN 192
#define LL 3
#define EPB 128          // edges per block-iteration (msg, pred)

// padded weight strides (multiple of 4 floats -> 16B aligned)
#define W2S 132
#define WUS 196
#define NLS 68
#define H1S 136          // pred h1/W2 fp16 row stride (halves): 272B, conflict-free ldmatrix
#define H2S 68           // pred h2 f32 row stride

typedef unsigned long long u64;

__device__ __forceinline__ void ffma2(u64 &d, u64 a, u64 b) {
    asm("fma.rn.f32x2 %0, %1, %2, %0;" : "+l"(d) : "l"(a), "l"(b));
}
__device__ __forceinline__ float f2sum(u64 a) {
    float lo, hi;
    asm("mov.b64 {%0, %1}, %2;" : "=f"(lo), "=f"(hi) : "l"(a));
    return lo + hi;
}
__device__ __forceinline__ void red_add_v4(float* p, float4 v) {
    u64 gp;
    asm("cvta.to.global.u64 %0, %1;" : "=l"(gp) : "l"(p));
    asm volatile("red.global.add.v4.f32 [%0], {%1, %2, %3, %4};"
                 :: "l"(gp), "f"(v.x), "f"(v.y), "f"(v.z), "f"(v.w) : "memory");
}
__device__ __forceinline__ void cp16(unsigned saddr, const void* g) {
    asm volatile("cp.async.cg.shared.global [%0], [%1], 16;" :: "r"(saddr), "l"(g));
}
#define CP_COMMIT()   asm volatile("cp.async.commit_group;" ::: "memory")
#define CP_WAIT_ALL() asm volatile("cp.async.wait_group 0;" ::: "memory")

__device__ __forceinline__ unsigned smem_u32(const void* p) {
    unsigned a;
    asm("{ .reg .u64 t; cvta.to.shared.u64 t, %1; cvt.u32.u64 %0, t; }" : "=r"(a) : "l"(p));
    return a;
}
__device__ __forceinline__ void ldsm_x4(unsigned &r0, unsigned &r1, unsigned &r2, unsigned &r3,
                                        unsigned addr) {
    asm volatile("ldmatrix.sync.aligned.m8n8.x4.shared.b16 {%0,%1,%2,%3}, [%4];"
                 : "=r"(r0), "=r"(r1), "=r"(r2), "=r"(r3) : "r"(addr));
}
__device__ __forceinline__ void ldsm_x2(unsigned &r0, unsigned &r1, unsigned addr) {
    asm volatile("ldmatrix.sync.aligned.m8n8.x2.shared.b16 {%0,%1}, [%2];"
                 : "=r"(r0), "=r"(r1) : "r"(addr));
}
__device__ __forceinline__ void mma16816(float* d,
                                         unsigned a0, unsigned a1, unsigned a2, unsigned a3,
                                         unsigned b0, unsigned b1) {
    asm volatile("mma.sync.aligned.m16n8k16.row.col.f32.f16.f16.f32 "
                 "{%0,%1,%2,%3}, {%4,%5,%6,%7}, {%8,%9}, {%0,%1,%2,%3};"
                 : "+f"(d[0]), "+f"(d[1]), "+f"(d[2]), "+f"(d[3])
                 : "r"(a0), "r"(a1), "r"(a2), "r"(a3), "r"(b0), "r"(b1));
}

// ---------------- scratch ----------------
__device__ float g_x[NN * DD];
__device__ float g_agg[NN * HH];     // segment-sum of h (pre-W2)
__device__ float g_cnt[NN];
__device__ float g_pab[NN * PP];

// ---------------- init ----------------
__global__ void init_kernel() {
    int i = blockIdx.x * blockDim.x + threadIdx.x;
    const int A4 = NN * HH / 4;
    if (i < A4) ((float4*)g_agg)[i] = make_float4(0.f, 0.f, 0.f, 0.f);
    else if (i < A4 + NN / 4) ((float4*)g_cnt)[i - A4] = make_float4(0.f, 0.f, 0.f, 0.f);
}

__global__ void count_kernel(const int* __restrict__ dst) {
    int e = blockIdx.x * blockDim.x + threadIdx.x;
    if (e < NE) atomicAdd(&g_cnt[dst[e]], 1.0f);
}

// ---------------- fused embed + node_lin(layer0) ----------------
#define EMB_SMEM ((PP*NLS + FN*DD + DD + 8*FN + 8*DD) * 4)

__global__ void __launch_bounds__(256, 2)
embed_nl_kernel(const float* __restrict__ nf,
                const float* __restrict__ eW, const float* __restrict__ eb,
                const float* __restrict__ W1) {
    extern __shared__ float s[];
    float* sWt = s;                    // [256][68]
    float* sWe = sWt + PP * NLS;
    float* sBe = sWe + FN * DD;
    float* sNf = sBe + DD;
    float* sX  = sNf + 8 * FN;

    const int tid = threadIdx.x;
    for (int i = tid; i < DD * PP; i += 256) {
        int k = i >> 8, j = i & 255;
        sWt[j * NLS + k] = (j < HH) ? W1[k * HH + j] : W1[(DD + k) * HH + (j - HH)];
    }
    for (int i = tid; i < FN * DD; i += 256) sWe[i] = eW[i];
    if (tid < DD) sBe[tid] = eb[tid];
    __syncthreads();

    const int step = gridDim.x * 8;
    for (int n0 = blockIdx.x * 8; n0 < NN; n0 += step) {
        for (int i = tid; i < 8 * FN; i += 256) {
            int c = i / FN, f = i % FN;
            sNf[i] = nf[(n0 + c) * FN + f];
        }
        __syncthreads();
        for (int i = tid; i < 8 * DD; i += 256) {
            int c = i >> 6, d = i & 63;
            float xv = sBe[d];
#pragma unroll
            for (int f = 0; f < FN; f++) xv += sNf[c * FN + f] * sWe[f * DD + d];
            xv = fmaxf(xv, 0.f);
            sX[c * DD + d] = xv;
            g_x[(n0 + c) * DD + d] = xv;
        }
        __syncthreads();
        u64 acc[8];
#pragma unroll
        for (int c = 0; c < 8; c++) acc[c] = 0ull;
        const float* wr = sWt + tid * NLS;
#pragma unroll 4
        for (int k = 0; k < DD; k += 4) {
            ulonglong2 w = *(const ulonglong2*)(wr + k);
#pragma unroll
            for (int c = 0; c < 8; c++) {
                ulonglong2 v = *(const ulonglong2*)(sX + c * DD + k);
                ffma2(acc[c], w.x, v.x);
                ffma2(acc[c], w.y, v.y);
            }
        }
#pragma unroll
        for (int c = 0; c < 8; c++)
            g_pab[(size_t)(n0 + c) * PP + tid] = f2sum(acc[c]);
        __syncthreads();
    }
}

// ---------------- edge message: phaseA + scatter of h (NO GEMM2) ----------------
#define MSG_SMEM ((EPB*HH + EPB*FE + 2*EPB) * 4)

__global__ void __launch_bounds__(512, 2)
msg_kernel(const float* __restrict__ ea,
           const int* __restrict__ src, const int* __restrict__ dst,
           const float* __restrict__ W1, const float* __restrict__ b1) {
    extern __shared__ float s[];
    float* sH   = s;                       // [128][128]
    float* sEa  = sH + EPB * HH;           // [128][8]
    int*   sSrc = (int*)(sEa + EPB * FE);  // [128]
    int*   sDst = sSrc + EPB;              // [128]

    const int tid = threadIdx.x;
    const int j = tid & 127, g = tid >> 7;
    const int wid = tid >> 5, lane = tid & 31;
    const float b1v = b1[j];
    float w1c[8];
#pragma unroll
    for (int f = 0; f < 8; f++) w1c[f] = W1[(2 * DD + f) * HH + j];

    int e0 = blockIdx.x * EPB;
    const int step = gridDim.x * EPB;

    for (; e0 < NE; e0 += step) {
        __syncthreads();
        if (tid < 2 * EPB) {
            int le = tid & (EPB - 1);
            int gc = e0 + le; if (gc >= NE) gc = NE - 1;
            if (tid < EPB) sSrc[le] = src[gc];
            else           sDst[le] = dst[gc];
        }
        for (int i = tid; i < EPB * 2; i += 512) {
            int le = i >> 1, frag = i & 1;
            int gc = e0 + le; if (gc >= NE) gc = NE - 1;
            ((float4*)sEa)[i] = ((const float4*)ea)[(size_t)gc * 2 + frag];
        }
        __syncthreads();

        {
            float pa[4], pb[4];
#pragma unroll
            for (int c = 0; c < 4; c++) {
                int e = g + 4 * c;
                pa[c] = g_pab[(size_t)sSrc[e] * PP + j];
                pb[c] = g_pab[(size_t)sDst[e] * PP + HH + j];
            }
#pragma unroll
            for (int c = 0; c < 32; c++) {
                int e = g + 4 * c;
                float hv = pa[c & 3] + pb[c & 3] + b1v;
                if (c + 4 < 32) {
                    int e2 = g + 4 * (c + 4);
                    pa[c & 3] = g_pab[(size_t)sSrc[e2] * PP + j];
                    pb[c & 3] = g_pab[(size_t)sDst[e2] * PP + HH + j];
                }
                float4 a0 = ((const float4*)(sEa + e * FE))[0];
                float4 a1 = ((const float4*)(sEa + e * FE))[1];
                hv = fmaf(a0.x, w1c[0], hv); hv = fmaf(a0.y, w1c[1], hv);
                hv = fmaf(a0.z, w1c[2], hv); hv = fmaf(a0.w, w1c[3], hv);
                hv = fmaf(a1.x, w1c[4], hv); hv = fmaf(a1.y, w1c[5], hv);
                hv = fmaf(a1.z, w1c[6], hv); hv = fmaf(a1.w, w1c[7], hv);
                sH[e * HH + j] = fmaxf(hv, 0.f);
            }
        }
        __syncthreads();

#pragma unroll
        for (int t = 0; t < 8; t++) {
            int le = wid * 8 + t;
            if (e0 + le < NE) {
                float4 m = ((const float4*)(sH + le * HH))[lane];
                red_add_v4(g_agg + (size_t)sDst[le] * HH + lane * 4, m);
            }
        }
    }
}

// ---------------- fused node kernel with cp.async double-buffered staging ----------------
#define NPT 8
#define STG (NPT*DD + NPT*HH + NPT)
#define UPDNL_SMEM ((HH*W2S + DD*WUS + PP*NLS + 3*DD + HH + 2*STG + NPT*HH + NPT*DD + 32) * 4)

__global__ void __launch_bounds__(512, 1)
updnl_kernel(const float* __restrict__ W2, const float* __restrict__ b2,
             const float* __restrict__ W, const float* __restrict__ b,
             const float* __restrict__ lg, const float* __restrict__ lb,
             const float* __restrict__ W1next) {
    extern __shared__ float s[];
    float* sW2t  = s;
    float* sWt   = sW2t + HH * W2S;
    float* sWnl  = sWt + DD * WUS;
    float* sB    = sWnl + PP * NLS;
    float* sG    = sB + DD;
    float* sLB   = sG + DD;
    float* sB2   = sLB + DD;
    float* sStg  = sB2 + HH;
    float* sMagg = sStg + 2 * STG;
    float* sXn   = sMagg + NPT * HH;
    float* sRed  = sXn + NPT * DD;

    const unsigned aStg = (unsigned)__cvta_generic_to_shared(sStg);

    const int tid = threadIdx.x;
    for (int i = tid; i < HH * HH; i += 512) { int k = i >> 7, j = i & 127; sW2t[j * W2S + k] = W2[i]; }
    for (int i = tid; i < UIN * DD; i += 512) { int k = i >> 6, d = i & 63; sWt[d * WUS + k] = W[i]; }
    for (int i = tid; i < DD * PP; i += 512) {
        int k = i >> 8, j = i & 255;
        sWnl[j * NLS + k] = (j < HH) ? W1next[k * HH + j] : W1next[(DD + k) * HH + (j - HH)];
    }
    if (tid < DD) { sB[tid] = b[tid]; sG[tid] = lg[tid]; sLB[tid] = lb[tid]; }
    if (tid < HH) sB2[tid] = b2[tid];

    const int d = tid & 63, ln = tid >> 6;
    const int wg = (tid >> 5) & 1, lane = tid & 31;
    const int jm = tid & 127, gm = tid >> 7;
    const int j = tid & 255, grp = tid >> 8;
    const float bv = b[d], gv = lg[d], lbv = lb[d];
    const float b2v = b2[jm];

    const int stride = gridDim.x * NPT;

#define STAGE(N0, B) { \
    unsigned base = aStg + (B) * STG * 4; \
    if (tid < 128) { \
        int node = tid >> 4, frag = tid & 15; \
        cp16(base + (node * DD + frag * 4) * 4, g_x + (size_t)((N0) + node) * DD + frag * 4); } \
    else if (tid < 384) { \
        int t2 = tid - 128; \
        int node = t2 >> 5, frag = t2 & 31; \
        cp16(base + (NPT * DD + node * HH + frag * 4) * 4, \
             g_agg + (size_t)((N0) + node) * HH + frag * 4); } \
    else if (tid < 386) { \
        cp16(base + (NPT * DD + NPT * HH + (tid - 384) * 4) * 4, g_cnt + (N0) + (tid - 384) * 4); } }

    int n0 = blockIdx.x * NPT;
    if (n0 < NN) { STAGE(n0, 0); }
    CP_COMMIT();
    __syncthreads();

    int buf = 0;
    for (; n0 < NN; n0 += stride, buf ^= 1) {
        CP_WAIT_ALL();
        __syncthreads();

        const float* sX   = sStg + buf * STG;
        const float* sAgg = sX + NPT * DD;
        const float* sCnt = sAgg + NPT * HH;

        if (tid < 256) {
            int nn = n0 + (tid >> 5);
            ((float4*)(g_agg + (size_t)nn * HH))[tid & 31] = make_float4(0.f, 0.f, 0.f, 0.f);
        }
        int nnext = n0 + stride;
        if (nnext < NN) { STAGE(nnext, buf ^ 1); }
        CP_COMMIT();

        {
            u64 a0 = 0ull, a1 = 0ull;
            const float* wr2 = sW2t + jm * W2S;
            const float* v0p = sAgg + gm * HH;
            const float* v1p = sAgg + (gm + 4) * HH;
#pragma unroll 4
            for (int k = 0; k < HH; k += 4) {
                ulonglong2 w = *(const ulonglong2*)(wr2 + k);
                ulonglong2 v0 = *(const ulonglong2*)(v0p + k);
                ulonglong2 v1 = *(const ulonglong2*)(v1p + k);
                ffma2(a0, w.x, v0.x); ffma2(a0, w.y, v0.y);
                ffma2(a1, w.x, v1.x); ffma2(a1, w.y, v1.y);
            }
            float c0 = sCnt[gm],     i0 = 1.f / (c0 + 1e-6f);
            float c1 = sCnt[gm + 4], i1 = 1.f / (c1 + 1e-6f);
            sMagg[gm * HH + jm]       = (f2sum(a0) + c0 * b2v) * i0;
            sMagg[(gm + 4) * HH + jm] = (f2sum(a1) + c1 * b2v) * i1;
        }
        __syncthreads();

        u64 a0 = 0ull;
        const float* wr = sWt + d * WUS;
        const float* xin = sX + ln * DD;
        const float* min = sMagg + ln * HH;
#pragma unroll 4
        for (int k = 0; k < DD; k += 4) {
            ulonglong2 w = *(const ulonglong2*)(wr + k);
            ulonglong2 v = *(const ulonglong2*)(xin + k);
            ffma2(a0, w.x, v.x);
            ffma2(a0, w.y, v.y);
        }
#pragma unroll 4
        for (int k = 0; k < HH; k += 4) {
            ulonglong2 w = *(const ulonglong2*)(wr + DD + k);
            ulonglong2 v = *(const ulonglong2*)(min + k);
            ffma2(a0, w.x, v.x);
            ffma2(a0, w.y, v.y);
        }
        float outv = xin[d] + fmaxf(f2sum(a0) + bv, 0.f);

        float s1 = outv, s2 = outv * outv;
#pragma unroll
        for (int off = 16; off; off >>= 1) {
            s1 += __shfl_xor_sync(0xFFFFFFFFu, s1, off);
            s2 += __shfl_xor_sync(0xFFFFFFFFu, s2, off);
        }
        if (lane == 0) { sRed[(ln * 2 + wg) * 2] = s1; sRed[(ln * 2 + wg) * 2 + 1] = s2; }
        __syncthreads();
        {
            float t1 = sRed[ln * 4] + sRed[ln * 4 + 2];
            float t2 = sRed[ln * 4 + 1] + sRed[ln * 4 + 3];
            float mu = t1 * (1.f / DD);
            float var = t2 * (1.f / DD) - mu * mu;
            float xn = (outv - mu) * rsqrtf(var + 1e-5f) * gv + lbv;
            g_x[(size_t)(n0 + ln) * DD + d] = xn;
            sXn[ln * DD + d] = xn;
        }
        __syncthreads();

        u64 acc[4];
#pragma unroll
        for (int c = 0; c < 4; c++) acc[c] = 0ull;
        const float* wr2 = sWnl + j * NLS;
#pragma unroll 4
        for (int k = 0; k < DD; k += 4) {
            ulonglong2 w = *(const ulonglong2*)(wr2 + k);
#pragma unroll
            for (int c = 0; c < 4; c++) {
                ulonglong2 v = *(const ulonglong2*)(sXn + (grp + 2 * c) * DD + k);
                ffma2(acc[c], w.x, v.x);
                ffma2(acc[c], w.y, v.y);
            }
        }
#pragma unroll
        for (int c = 0; c < 4; c++)
            g_pab[(size_t)(n0 + grp + 2 * c) * PP + j] = f2sum(acc[c]);
        __syncthreads();
    }
#undef STAGE
}

// ---------------- edge predictor: phaseA fp32 -> fp16 -> mma.sync GEMM2 -> epilogue ----------------
// smem floats/halves layout (16B aligned segments):
//   sH1  fp16 [128][136]  = 34816 B
//   sBW  fp16 [64][136]   = 17408 B   (W2^T rows = out-channel)
//   sH2  f32  [128][68]   = 34816 B
//   sEa  f32  [128][8]    = 4096 B
//   sSrc/sDst int [128]x2 = 1024 B
//   sW3/sB2 f32 64+64     = 512 B
#define PRED_SMEM (34816 + 17408 + 34816 + 4096 + 1024 + 512)

__global__ void __launch_bounds__(512, 2)
pred_kernel(const float* __restrict__ ea,
            const int* __restrict__ src, const int* __restrict__ dst,
            const float* __restrict__ W1, const float* __restrict__ b1,
            const float* __restrict__ W2, const float* __restrict__ b2,
            const float* __restrict__ W3, const float* __restrict__ b3,
            float* __restrict__ out) {
    extern __shared__ char sc[];
    __half* sH1 = (__half*)sc;                       // [128][136] fp16
    __half* sBW = (__half*)(sc + 34816);             // [64][136] fp16
    float*  sH2 = (float*)(sc + 34816 + 17408);      // [128][68]
    float*  sEa = (float*)(sc + 34816 + 17408 + 34816);
    int*    sSrc = (int*)(sEa + EPB * FE);
    int*    sDst = sSrc + EPB;
    float*  sW3 = (float*)(sDst + EPB);              // 64
    float*  sB2 = sW3 + DD;                          // 64

    const int tid = threadIdx.x;
    const int wid = tid >> 5, lane = tid & 31;
    const int j = tid & 127, g = tid >> 7;

    // one-time: W2 [k=128][n=64] -> sBW[n][k] fp16; W3, b2
    for (int i = tid; i < HH * DD; i += 512) {
        int k = i >> 6, n = i & 63;
        sBW[n * H1S + k] = __float2half(W2[i]);
    }
    if (tid < DD) { sW3[tid] = W3[tid]; sB2[tid] = b2[tid]; }

    const unsigned aH1 = smem_u32(sH1);
    const unsigned aBW = smem_u32(sBW);

    const float b1v = b1[j], b3v = b3[0];
    float w1c[8];
#pragma unroll
    for (int f = 0; f < 8; f++) w1c[f] = W1[(2 * DD + f) * HH + j];

    // mma mapping: warp -> m-stripe (wid&7)*16, n-half (wid>>3)*32
    const int mrow = (wid & 7) * 16;
    const int nbase = (wid >> 3) * 32;
    // A ldmatrix lane address components
    const int a_row = (lane & 7) + ((lane >> 3) & 1) * 8;  // 0..15
    const int a_kof = (lane >> 4) * 8;                     // 0 or 8
    // B ldmatrix lane address components (lanes 0..15 used)
    const int b_row = lane & 7;
    const int b_kof = ((lane >> 3) & 1) * 8;

    int e0 = blockIdx.x * EPB;
    const int step = gridDim.x * EPB;

    for (; e0 < NE; e0 += step) {
        __syncthreads();                       // prior epilogue done
        if (tid < 2 * EPB) {
            int le = tid & (EPB - 1);
            int gc = e0 + le; if (gc >= NE) gc = NE - 1;
            if (tid < EPB) sSrc[le] = src[gc];
            else           sDst[le] = dst[gc];
        }
        for (int i = tid; i < EPB * 2; i += 512) {
            int le = i >> 1, frag = i & 1;
            int gc = e0 + le; if (gc >= NE) gc = NE - 1;
            ((float4*)sEa)[i] = ((const float4*)ea)[(size_t)gc * 2 + frag];
        }
        __syncthreads();

        // ---- phase A: h1 = relu(Pa + Pb + ea@W1c + b1) -> fp16 [e][136] ----
        {
            float pa[4], pb[4];
#pragma unroll
            for (int c = 0; c < 4; c++) {
                int e = g + 4 * c;
                pa[c] = g_pab[(size_t)sSrc[e] * PP + j];
                pb[c] = g_pab[(size_t)sDst[e] * PP + HH + j];
            }
#pragma unroll
            for (int c = 0; c < 32; c++) {
                int e = g + 4 * c;
                float hv = pa[c & 3] + pb[c & 3] + b1v;
                if (c + 4 < 32) {
                    int e2 = g + 4 * (c + 4);
                    pa[c & 3] = g_pab[(size_t)sSrc[e2] * PP + j];
                    pb[c & 3] = g_pab[(size_t)sDst[e2] * PP + HH + j];
                }
                float4 a0 = ((const float4*)(sEa + e * FE))[0];
                float4 a1 = ((const float4*)(sEa + e * FE))[1];
                hv = fmaf(a0.x, w1c[0], hv); hv = fmaf(a0.y, w1c[1], hv);
                hv = fmaf(a0.z, w1c[2], hv); hv = fmaf(a0.w, w1c[3], hv);
                hv = fmaf(a1.x, w1c[4], hv); hv = fmaf(a1.y, w1c[5], hv);
                hv = fmaf(a1.z, w1c[6], hv); hv = fmaf(a1.w, w1c[7], hv);
                sH1[e * H1S + j] = __float2half(fmaxf(hv, 0.f));
            }
        }
        __syncthreads();

        // ---- GEMM2 on tensor cores: D[128x64] = h1[128x128] @ W2 (fp16, f32 accum) ----
        {
            float dfr[4][4];
#pragma unroll
            for (int t = 0; t < 4; t++)
#pragma unroll
                for (int q = 0; q < 4; q++) dfr[t][q] = 0.f;

#pragma unroll
            for (int ks = 0; ks < 8; ks++) {
                int k0 = ks * 16;
                unsigned fa0, fa1, fa2, fa3;
                ldsm_x4(fa0, fa1, fa2, fa3,
                        aH1 + ((mrow + a_row) * H1S + k0 + a_kof) * 2);
#pragma unroll
                for (int t = 0; t < 4; t++) {
                    unsigned fb0, fb1;
                    ldsm_x2(fb0, fb1,
                            aBW + ((nbase + t * 8 + b_row) * H1S + k0 + b_kof) * 2);
                    mma16816(dfr[t], fa0, fa1, fa2, fa3, fb0, fb1);
                }
            }
            // store h2 = relu(D + b2) to sH2 [e][68]
            int r0 = mrow + (lane >> 2);
            int r1 = r0 + 8;
#pragma unroll
            for (int t = 0; t < 4; t++) {
                int c0 = nbase + t * 8 + 2 * (lane & 3);
                sH2[r0 * H2S + c0]     = fmaxf(dfr[t][0] + sB2[c0], 0.f);
                sH2[r0 * H2S + c0 + 1] = fmaxf(dfr[t][1] + sB2[c0 + 1], 0.f);
                sH2[r1 * H2S + c0]     = fmaxf(dfr[t][2] + sB2[c0], 0.f);
                sH2[r1 * H2S + c0 + 1] = fmaxf(dfr[t][3] + sB2[c0 + 1], 0.f);
            }
        }
        __syncthreads();

        // ---- final dot 64 -> 1 + tanh : warp -> its 8 edges ----
#pragma unroll
        for (int t = 0; t < 8; t++) {
            int le = wid * 8 + t, ge = e0 + le;
            float v = sH2[le * H2S + lane] * sW3[lane]
                    + sH2[le * H2S + 32 + lane] * sW3[32 + lane];
#pragma unroll
            for (int off = 16; off; off >>= 1) v += __shfl_xor_sync(0xFFFFFFFFu, v, off);
            if (lane == 0 && ge < NE) out[ge] = tanhf(v + b3v);
        }
    }
}

// ---------------- launch ----------------
extern "C" void kernel_launch(void* const* d_in, const int* in_sizes, int n_in,
                              void* d_out, int out_size) {
    const float* node_features = (const float*)d_in[0];
    const float* edge_attr     = (const float*)d_in[1];
    const float* embed_W       = (const float*)d_in[2];
    const float* embed_b       = (const float*)d_in[3];
    const float* msg_W1        = (const float*)d_in[4];
    const float* msg_b1        = (const float*)d_in[5];
    const float* msg_W2        = (const float*)d_in[6];
    const float* msg_b2        = (const float*)d_in[7];
    const float* upd_W         = (const float*)d_in[8];
    const float* upd_b         = (const float*)d_in[9];
    const float* ln_g          = (const float*)d_in[10];
    const float* ln_b          = (const float*)d_in[11];
    const float* pred_W1       = (const float*)d_in[12];
    const float* pred_b1       = (const float*)d_in[13];
    const float* pred_W2       = (const float*)d_in[14];
    const float* pred_b2       = (const float*)d_in[15];
    const float* pred_W3       = (const float*)d_in[16];
    const float* pred_b3       = (const float*)d_in[17];
    const int*   edge_index    = (const int*)d_in[18];
    float* out = (float*)d_out;

    const int* src = edge_index;
    const int* dst = edge_index + NE;

    cudaFuncSetAttribute(msg_kernel,      cudaFuncAttributeMaxDynamicSharedMemorySize, MSG_SMEM);
    cudaFuncSetAttribute(pred_kernel,     cudaFuncAttributeMaxDynamicSharedMemorySize, PRED_SMEM);
    cudaFuncSetAttribute(updnl_kernel,    cudaFuncAttributeMaxDynamicSharedMemorySize, UPDNL_SMEM);
    cudaFuncSetAttribute(embed_nl_kernel, cudaFuncAttributeMaxDynamicSharedMemorySize, EMB_SMEM);

    init_kernel<<<(NN * HH / 4 + NN / 4 + 255) / 256, 256>>>();
    count_kernel<<<(NE + 255) / 256, 256>>>(dst);
    embed_nl_kernel<<<296, 256, EMB_SMEM>>>(node_features, embed_W, embed_b, msg_W1);

    for (int l = 0; l < LL; l++) {
        msg_kernel<<<296, 512, MSG_SMEM>>>(edge_attr, src, dst,
                                           msg_W1 + l * EIN * HH, msg_b1 + l * HH);
        const float* nextW1 = (l < LL - 1) ? (msg_W1 + (l + 1) * EIN * HH) : pred_W1;
        updnl_kernel<<<148, 512, UPDNL_SMEM>>>(msg_W2 + l * HH * HH, msg_b2 + l * HH,
                                               upd_W + l * UIN * DD, upd_b + l * DD,
                                               ln_g + l * DD, ln_b + l * DD, nextW1);
    }

    pred_kernel<<<296, 512, PRED_SMEM>>>(edge_attr, src, dst,
                                         pred_W1, pred_b1, pred_W2, pred_b2,
                                         pred_W3, pred_b3, out);
}

// round 14
// speedup vs baseline: 2.6989x; 1.1817x over previous
#include <cuda_runtime.h>
#include <cuda_fp16.h>
#include <math.h>

#define NN 50000
#define NE 500000
#define FN 7
#define FE 8
#define DD 64
#define HH 128
#define PP 256
#define EIN 136
#define UIN 192
#define LL 3
#define EPB 128

#define WXS 68
#define WCS 132
#define NLS 68
#define H1S 136
#define H2S 68

typedef unsigned long long u64;

__device__ __forceinline__ void ffma2(u64 &d, u64 a, u64 b) {
    asm("fma.rn.f32x2 %0, %1, %2, %0;" : "+l"(d) : "l"(a), "l"(b));
}
__device__ __forceinline__ float f2sum(u64 a) {
    float lo, hi;
    asm("mov.b64 {%0, %1}, %2;" : "=f"(lo), "=f"(hi) : "l"(a));
    return lo + hi;
}
__device__ __forceinline__ void red_add_v4(float* p, float4 v) {
    u64 gp;
    asm("cvta.to.global.u64 %0, %1;" : "=l"(gp) : "l"(p));
    asm volatile("red.global.add.v4.f32 [%0], {%1, %2, %3, %4};"
                 :: "l"(gp), "f"(v.x), "f"(v.y), "f"(v.z), "f"(v.w) : "memory");
}
__device__ __forceinline__ void cp16(unsigned saddr, const void* g) {
    asm volatile("cp.async.cg.shared.global [%0], [%1], 16;" :: "r"(saddr), "l"(g));
}
#define CP_COMMIT()   asm volatile("cp.async.commit_group;" ::: "memory")
#define CP_WAIT_ALL() asm volatile("cp.async.wait_group 0;" ::: "memory")

__device__ __forceinline__ unsigned smem_u32(const void* p) {
    unsigned a;
    asm("{ .reg .u64 t; cvta.to.shared.u64 t, %1; cvt.u32.u64 %0, t; }" : "=r"(a) : "l"(p));
    return a;
}
__device__ __forceinline__ void ldsm_x4(unsigned &r0, unsigned &r1, unsigned &r2, unsigned &r3,
                                        unsigned addr) {
    asm volatile("ldmatrix.sync.aligned.m8n8.x4.shared.b16 {%0,%1,%2,%3}, [%4];"
                 : "=r"(r0), "=r"(r1), "=r"(r2), "=r"(r3) : "r"(addr));
}
__device__ __forceinline__ void ldsm_x2(unsigned &r0, unsigned &r1, unsigned addr) {
    asm volatile("ldmatrix.sync.aligned.m8n8.x2.shared.b16 {%0,%1}, [%2];"
                 : "=r"(r0), "=r"(r1) : "r"(addr));
}
__device__ __forceinline__ void mma16816(float* d,
                                         unsigned a0, unsigned a1, unsigned a2, unsigned a3,
                                         unsigned b0, unsigned b1) {
    asm volatile("mma.sync.aligned.m16n8k16.row.col.f32.f16.f16.f32 "
                 "{%0,%1,%2,%3}, {%4,%5,%6,%7}, {%8,%9}, {%0,%1,%2,%3};"
                 : "+f"(d[0]), "+f"(d[1]), "+f"(d[2]), "+f"(d[3])
                 : "r"(a0), "r"(a1), "r"(a2), "r"(a3), "r"(b0), "r"(b1));
}

// ---------------- scratch ----------------
__device__ float g_x[NN * DD];
__device__ float g_agg[NN * HH];
__device__ float g_cnt[NN];
__device__ float g_pab[NN * PP];
__device__ float g_wc[LL * HH * DD];
__device__ float g_bm[LL * DD];

// ---------------- init ----------------
__global__ void init_kernel() {
    int i = blockIdx.x * blockDim.x + threadIdx.x;
    const int A4 = NN * HH / 4;
    if (i < A4) ((float4*)g_agg)[i] = make_float4(0.f, 0.f, 0.f, 0.f);
    else if (i < A4 + NN / 4) ((float4*)g_cnt)[i - A4] = make_float4(0.f, 0.f, 0.f, 0.f);
}

__global__ void count_kernel(const int* __restrict__ dst) {
    int e = blockIdx.x * blockDim.x + threadIdx.x;
    if (e < NE) atomicAdd(&g_cnt[dst[e]], 1.0f);
}

// ---------------- fused embed + node_lin(layer0) ----------------
#define EMB_SMEM ((PP*NLS + FN*DD + DD + 8*FN + 8*DD) * 4)

__global__ void __launch_bounds__(256, 2)
embed_nl_kernel(const float* __restrict__ nf,
                const float* __restrict__ eW, const float* __restrict__ eb,
                const float* __restrict__ W1) {
    extern __shared__ float s[];
    float* sWt = s;
    float* sWe = sWt + PP * NLS;
    float* sBe = sWe + FN * DD;
    float* sNf = sBe + DD;
    float* sX  = sNf + 8 * FN;

    const int tid = threadIdx.x;
    for (int i = tid; i < DD * PP; i += 256) {
        int k = i >> 8, j = i & 255;
        sWt[j * NLS + k] = (j < HH) ? W1[k * HH + j] : W1[(DD + k) * HH + (j - HH)];
    }
    for (int i = tid; i < FN * DD; i += 256) sWe[i] = eW[i];
    if (tid < DD) sBe[tid] = eb[tid];
    __syncthreads();

    const int step = gridDim.x * 8;
    for (int n0 = blockIdx.x * 8; n0 < NN; n0 += step) {
        for (int i = tid; i < 8 * FN; i += 256) {
            int c = i / FN, f = i % FN;
            sNf[i] = nf[(n0 + c) * FN + f];
        }
        __syncthreads();
        for (int i = tid; i < 8 * DD; i += 256) {
            int c = i >> 6, d = i & 63;
            float xv = sBe[d];
#pragma unroll
            for (int f = 0; f < FN; f++) xv += sNf[c * FN + f] * sWe[f * DD + d];
            xv = fmaxf(xv, 0.f);
            sX[c * DD + d] = xv;
            g_x[(n0 + c) * DD + d] = xv;
        }
        __syncthreads();
        u64 acc[8];
#pragma unroll
        for (int c = 0; c < 8; c++) acc[c] = 0ull;
        const float* wr = sWt + tid * NLS;
#pragma unroll 4
        for (int k = 0; k < DD; k += 4) {
            ulonglong2 w = *(const ulonglong2*)(wr + k);
#pragma unroll
            for (int c = 0; c < 8; c++) {
                ulonglong2 v = *(const ulonglong2*)(sX + c * DD + k);
                ffma2(acc[c], w.x, v.x);
                ffma2(acc[c], w.y, v.y);
            }
        }
#pragma unroll
        for (int c = 0; c < 8; c++)
            g_pab[(size_t)(n0 + c) * PP + tid] = f2sum(acc[c]);
        __syncthreads();
    }
}

// ---------------- precompute Wc = W2 @ Wm, bm = b2 @ Wm ----------------
#define WC_SMEM ((HH*HH + HH*DD) * 4)

__global__ void __launch_bounds__(512)
wc_kernel(const float* __restrict__ W2all, const float* __restrict__ b2all,
          const float* __restrict__ Wall) {
    extern __shared__ float s[];
    float* sW2 = s;
    float* sWm = sW2 + HH * HH;

    const int l = blockIdx.x;
    const float* W2 = W2all + l * HH * HH;
    const float* b2 = b2all + l * HH;
    const float* Wm = Wall + (size_t)l * UIN * DD + DD * DD;

    const int tid = threadIdx.x;
    for (int i = tid; i < HH * HH; i += 512) sW2[i] = W2[i];
    for (int i = tid; i < HH * DD; i += 512) sWm[i] = Wm[i];
    __syncthreads();

    for (int o = tid; o < HH * DD; o += 512) {
        int k = o >> 6, d = o & 63;
        float acc = 0.f;
#pragma unroll 4
        for (int j = 0; j < HH; j++)
            acc += sW2[k * HH + j] * sWm[j * DD + d];
        g_wc[l * HH * DD + o] = acc;
    }
    if (tid < DD) {
        float acc = 0.f;
        for (int j = 0; j < HH; j++) acc += b2[j] * sWm[j * DD + tid];
        g_bm[l * DD + tid] = acc;
    }
}

// ---------------- edge message ----------------
#define MSG_SMEM ((EPB*HH + EPB*FE + 2*EPB) * 4)

__global__ void __launch_bounds__(512, 2)
msg_kernel(const float* __restrict__ ea,
           const int* __restrict__ src, const int* __restrict__ dst,
           const float* __restrict__ W1, const float* __restrict__ b1) {
    extern __shared__ float s[];
    float* sH   = s;
    float* sEa  = sH + EPB * HH;
    int*   sSrc = (int*)(sEa + EPB * FE);
    int*   sDst = sSrc + EPB;

    const int tid = threadIdx.x;
    const int j = tid & 127, g = tid >> 7;
    const int wid = tid >> 5, lane = tid & 31;
    const float b1v = b1[j];
    float w1c[8];
#pragma unroll
    for (int f = 0; f < 8; f++) w1c[f] = W1[(2 * DD + f) * HH + j];

    int e0 = blockIdx.x * EPB;
    const int step = gridDim.x * EPB;

    for (; e0 < NE; e0 += step) {
        __syncthreads();
        if (tid < 2 * EPB) {
            int le = tid & (EPB - 1);
            int gc = e0 + le; if (gc >= NE) gc = NE - 1;
            if (tid < EPB) sSrc[le] = src[gc];
            else           sDst[le] = dst[gc];
        }
        for (int i = tid; i < EPB * 2; i += 512) {
            int le = i >> 1, frag = i & 1;
            int gc = e0 + le; if (gc >= NE) gc = NE - 1;
            ((float4*)sEa)[i] = ((const float4*)ea)[(size_t)gc * 2 + frag];
        }
        __syncthreads();

        {
            float pa[4], pb[4];
#pragma unroll
            for (int c = 0; c < 4; c++) {
                int e = g + 4 * c;
                pa[c] = g_pab[(size_t)sSrc[e] * PP + j];
                pb[c] = g_pab[(size_t)sDst[e] * PP + HH + j];
            }
#pragma unroll
            for (int c = 0; c < 32; c++) {
                int e = g + 4 * c;
                float hv = pa[c & 3] + pb[c & 3] + b1v;
                if (c + 4 < 32) {
                    int e2 = g + 4 * (c + 4);
                    pa[c & 3] = g_pab[(size_t)sSrc[e2] * PP + j];
                    pb[c & 3] = g_pab[(size_t)sDst[e2] * PP + HH + j];
                }
                float4 a0 = ((const float4*)(sEa + e * FE))[0];
                float4 a1 = ((const float4*)(sEa + e * FE))[1];
                hv = fmaf(a0.x, w1c[0], hv); hv = fmaf(a0.y, w1c[1], hv);
                hv = fmaf(a0.z, w1c[2], hv); hv = fmaf(a0.w, w1c[3], hv);
                hv = fmaf(a1.x, w1c[4], hv); hv = fmaf(a1.y, w1c[5], hv);
                hv = fmaf(a1.z, w1c[6], hv); hv = fmaf(a1.w, w1c[7], hv);
                sH[e * HH + j] = fmaxf(hv, 0.f);
            }
        }
        __syncthreads();

#pragma unroll
        for (int t = 0; t < 8; t++) {
            int le = wid * 8 + t;
            if (e0 + le < NE) {
                float4 m = ((const float4*)(sH + le * HH))[lane];
                red_add_v4(g_agg + (size_t)sDst[le] * HH + lane * 4, m);
            }
        }
    }
}

// ---------------- fused node kernel (folded Wc) ----------------
#define NPT 8
#define STG (NPT*DD + NPT*HH + NPT)
#define UPDNL_SMEM ((DD*WXS + DD*WCS + PP*NLS + 2*STG + NPT*DD + 32) * 4)

__global__ void __launch_bounds__(512, 1)
updnl_kernel(const float* __restrict__ W, const float* __restrict__ b,
             const float* __restrict__ lg, const float* __restrict__ lb,
             const float* __restrict__ W1next, int layer) {
    extern __shared__ float s[];
    float* sWxt = s;
    float* sWct = sWxt + DD * WXS;
    float* sWnl = sWct + DD * WCS;
    float* sStg = sWnl + PP * NLS;
    float* sXn  = sStg + 2 * STG;
    float* sRed = sXn + NPT * DD;

    const unsigned aStg = (unsigned)__cvta_generic_to_shared(sStg);
    const float* wc = g_wc + layer * HH * DD;
    const float* bm = g_bm + layer * DD;

    const int tid = threadIdx.x;
    for (int i = tid; i < DD * DD; i += 512) { int t = i >> 6, d = i & 63; sWxt[d * WXS + t] = W[t * DD + d]; }
    for (int i = tid; i < HH * DD; i += 512) { int k = i >> 6, d = i & 63; sWct[d * WCS + k] = wc[k * DD + d]; }
    for (int i = tid; i < DD * PP; i += 512) {
        int k = i >> 8, j = i & 255;
        sWnl[j * NLS + k] = (j < HH) ? W1next[k * HH + j] : W1next[(DD + k) * HH + (j - HH)];
    }

    const int d = tid & 63, ln = tid >> 6;
    const int wg = (tid >> 5) & 1, lane = tid & 31;
    const int j = tid & 255, grp = tid >> 8;
    const float bv = b[d], gv = lg[d], lbv = lb[d], bmv = bm[d];

    const int stride = gridDim.x * NPT;

#define STAGE(N0, B) { \
    unsigned base = aStg + (B) * STG * 4; \
    if (tid < 128) { \
        int node = tid >> 4, frag = tid & 15; \
        cp16(base + (node * DD + frag * 4) * 4, g_x + (size_t)((N0) + node) * DD + frag * 4); } \
    else if (tid < 384) { \
        int t2 = tid - 128; \
        int node = t2 >> 5, frag = t2 & 31; \
        cp16(base + (NPT * DD + node * HH + frag * 4) * 4, \
             g_agg + (size_t)((N0) + node) * HH + frag * 4); } \
    else if (tid < 386) { \
        cp16(base + (NPT * DD + NPT * HH + (tid - 384) * 4) * 4, g_cnt + (N0) + (tid - 384) * 4); } }

    int n0 = blockIdx.x * NPT;
    if (n0 < NN) { STAGE(n0, 0); }
    CP_COMMIT();
    __syncthreads();

    int buf = 0;
    for (; n0 < NN; n0 += stride, buf ^= 1) {
        CP_WAIT_ALL();
        __syncthreads();

        const float* sX   = sStg + buf * STG;
        const float* sAgg = sX + NPT * DD;
        const float* sCnt = sAgg + NPT * HH;

        if (tid < 256) {
            int nn = n0 + (tid >> 5);
            ((float4*)(g_agg + (size_t)nn * HH))[tid & 31] = make_float4(0.f, 0.f, 0.f, 0.f);
        }
        int nnext = n0 + stride;
        if (nnext < NN) { STAGE(nnext, buf ^ 1); }
        CP_COMMIT();

        // u = x@Wx + (aggH@Wc)*inv + cnt*inv*bm + b ; out = x + relu(u)
        u64 ax = 0ull, ac = 0ull;
        const float* wrx = sWxt + d * WXS;
        const float* wrc = sWct + d * WCS;
        const float* xin = sX + ln * DD;
        const float* ain = sAgg + ln * HH;
#pragma unroll 4
        for (int k = 0; k < DD; k += 4) {
            ulonglong2 w = *(const ulonglong2*)(wrx + k);
            ulonglong2 v = *(const ulonglong2*)(xin + k);
            ffma2(ax, w.x, v.x);
            ffma2(ax, w.y, v.y);
        }
#pragma unroll 4
        for (int k = 0; k < HH; k += 4) {
            ulonglong2 w = *(const ulonglong2*)(wrc + k);
            ulonglong2 v = *(const ulonglong2*)(ain + k);
            ffma2(ac, w.x, v.x);
            ffma2(ac, w.y, v.y);
        }
        float cntv = sCnt[ln];
        float inv = 1.f / (cntv + 1e-6f);
        float outv = xin[d] + fmaxf(f2sum(ax) + f2sum(ac) * inv + cntv * inv * bmv + bv, 0.f);

        float s1 = outv, s2 = outv * outv;
#pragma unroll
        for (int off = 16; off; off >>= 1) {
            s1 += __shfl_xor_sync(0xFFFFFFFFu, s1, off);
            s2 += __shfl_xor_sync(0xFFFFFFFFu, s2, off);
        }
        if (lane == 0) { sRed[(ln * 2 + wg) * 2] = s1; sRed[(ln * 2 + wg) * 2 + 1] = s2; }
        __syncthreads();
        {
            float t1 = sRed[ln * 4] + sRed[ln * 4 + 2];
            float t2 = sRed[ln * 4 + 1] + sRed[ln * 4 + 3];
            float mu = t1 * (1.f / DD);
            float var = t2 * (1.f / DD) - mu * mu;
            float xn = (outv - mu) * rsqrtf(var + 1e-5f) * gv + lbv;
            g_x[(size_t)(n0 + ln) * DD + d] = xn;
            sXn[ln * DD + d] = xn;
        }
        __syncthreads();

        u64 acc[4];
#pragma unroll
        for (int c = 0; c < 4; c++) acc[c] = 0ull;
        const float* wr2 = sWnl + j * NLS;
#pragma unroll 4
        for (int k = 0; k < DD; k += 4) {
            ulonglong2 w = *(const ulonglong2*)(wr2 + k);
#pragma unroll
            for (int c = 0; c < 4; c++) {
                ulonglong2 v = *(const ulonglong2*)(sXn + (grp + 2 * c) * DD + k);
                ffma2(acc[c], w.x, v.x);
                ffma2(acc[c], w.y, v.y);
            }
        }
#pragma unroll
        for (int c = 0; c < 4; c++)
            g_pab[(size_t)(n0 + grp + 2 * c) * PP + j] = f2sum(acc[c]);
        __syncthreads();
    }
#undef STAGE
}

// ---------------- edge predictor (fp16 mma.sync) ----------------
#define PRED_SMEM (34816 + 17408 + 34816 + 4096 + 1024 + 512)

__global__ void __launch_bounds__(512, 2)
pred_kernel(const float* __restrict__ ea,
            const int* __restrict__ src, const int* __restrict__ dst,
            const float* __restrict__ W1, const float* __restrict__ b1,
            const float* __restrict__ W2, const float* __restrict__ b2,
            const float* __restrict__ W3, const float* __restrict__ b3,
            float* __restrict__ out) {
    extern __shared__ char sc[];
    __half* sH1 = (__half*)sc;
    __half* sBW = (__half*)(sc + 34816);
    float*  sH2 = (float*)(sc + 34816 + 17408);
    float*  sEa = (float*)(sc + 34816 + 17408 + 34816);
    int*    sSrc = (int*)(sEa + EPB * FE);
    int*    sDst = sSrc + EPB;
    float*  sW3 = (float*)(sDst + EPB);
    float*  sB2 = sW3 + DD;

    const int tid = threadIdx.x;
    const int wid = tid >> 5, lane = tid & 31;
    const int j = tid & 127, g = tid >> 7;

    for (int i = tid; i < HH * DD; i += 512) {
        int k = i >> 6, n = i & 63;
        sBW[n * H1S + k] = __float2half(W2[i]);
    }
    if (tid < DD) { sW3[tid] = W3[tid]; sB2[tid] = b2[tid]; }

    const unsigned aH1 = smem_u32(sH1);
    const unsigned aBW = smem_u32(sBW);

    const float b1v = b1[j], b3v = b3[0];
    float w1c[8];
#pragma unroll
    for (int f = 0; f < 8; f++) w1c[f] = W1[(2 * DD + f) * HH + j];

    const int mrow = (wid & 7) * 16;
    const int nbase = (wid >> 3) * 32;
    const int a_row = (lane & 7) + ((lane >> 3) & 1) * 8;
    const int a_kof = (lane >> 4) * 8;
    const int b_row = lane & 7;
    const int b_kof = ((lane >> 3) & 1) * 8;

    int e0 = blockIdx.x * EPB;
    const int step = gridDim.x * EPB;

    for (; e0 < NE; e0 += step) {
        __syncthreads();
        if (tid < 2 * EPB) {
            int le = tid & (EPB - 1);
            int gc = e0 + le; if (gc >= NE) gc = NE - 1;
            if (tid < EPB) sSrc[le] = src[gc];
            else           sDst[le] = dst[gc];
        }
        for (int i = tid; i < EPB * 2; i += 512) {
            int le = i >> 1, frag = i & 1;
            int gc = e0 + le; if (gc >= NE) gc = NE - 1;
            ((float4*)sEa)[i] = ((const float4*)ea)[(size_t)gc * 2 + frag];
        }
        __syncthreads();

        {
            float pa[4], pb[4];
#pragma unroll
            for (int c = 0; c < 4; c++) {
                int e = g + 4 * c;
                pa[c] = g_pab[(size_t)sSrc[e] * PP + j];
                pb[c] = g_pab[(size_t)sDst[e] * PP + HH + j];
            }
#pragma unroll
            for (int c = 0; c < 32; c++) {
                int e = g + 4 * c;
                float hv = pa[c & 3] + pb[c & 3] + b1v;
                if (c + 4 < 32) {
                    int e2 = g + 4 * (c + 4);
                    pa[c & 3] = g_pab[(size_t)sSrc[e2] * PP + j];
                    pb[c & 3] = g_pab[(size_t)sDst[e2] * PP + HH + j];
                }
                float4 a0 = ((const float4*)(sEa + e * FE))[0];
                float4 a1 = ((const float4*)(sEa + e * FE))[1];
                hv = fmaf(a0.x, w1c[0], hv); hv = fmaf(a0.y, w1c[1], hv);
                hv = fmaf(a0.z, w1c[2], hv); hv = fmaf(a0.w, w1c[3], hv);
                hv = fmaf(a1.x, w1c[4], hv); hv = fmaf(a1.y, w1c[5], hv);
                hv = fmaf(a1.z, w1c[6], hv); hv = fmaf(a1.w, w1c[7], hv);
                sH1[e * H1S + j] = __float2half(fmaxf(hv, 0.f));
            }
        }
        __syncthreads();

        {
            float dfr[4][4];
#pragma unroll
            for (int t = 0; t < 4; t++)
#pragma unroll
                for (int q = 0; q < 4; q++) dfr[t][q] = 0.f;

#pragma unroll
            for (int ks = 0; ks < 8; ks++) {
                int k0 = ks * 16;
                unsigned fa0, fa1, fa2, fa3;
                ldsm_x4(fa0, fa1, fa2, fa3,
                        aH1 + ((mrow + a_row) * H1S + k0 + a_kof) * 2);
#pragma unroll
                for (int t = 0; t < 4; t++) {
                    unsigned fb0, fb1;
                    ldsm_x2(fb0, fb1,
                            aBW + ((nbase + t * 8 + b_row) * H1S + k0 + b_kof) * 2);
                    mma16816(dfr[t], fa0, fa1, fa2, fa3, fb0, fb1);
                }
            }
            int r0 = mrow + (lane >> 2);
            int r1 = r0 + 8;
#pragma unroll
            for (int t = 0; t < 4; t++) {
                int c0 = nbase + t * 8 + 2 * (lane & 3);
                sH2[r0 * H2S + c0]     = fmaxf(dfr[t][0] + sB2[c0], 0.f);
                sH2[r0 * H2S + c0 + 1] = fmaxf(dfr[t][1] + sB2[c0 + 1], 0.f);
                sH2[r1 * H2S + c0]     = fmaxf(dfr[t][2] + sB2[c0], 0.f);
                sH2[r1 * H2S + c0 + 1] = fmaxf(dfr[t][3] + sB2[c0 + 1], 0.f);
            }
        }
        __syncthreads();

#pragma unroll
        for (int t = 0; t < 8; t++) {
            int le = wid * 8 + t, ge = e0 + le;
            float v = sH2[le * H2S + lane] * sW3[lane]
                    + sH2[le * H2S + 32 + lane] * sW3[32 + lane];
#pragma unroll
            for (int off = 16; off; off >>= 1) v += __shfl_xor_sync(0xFFFFFFFFu, v, off);
            if (lane == 0 && ge < NE) out[ge] = tanhf(v + b3v);
        }
    }
}

// ---------------- launch ----------------
extern "C" void kernel_launch(void* const* d_in, const int* in_sizes, int n_in,
                              void* d_out, int out_size) {
    const float* node_features = (const float*)d_in[0];
    const float* edge_attr     = (const float*)d_in[1];
    const float* embed_W       = (const float*)d_in[2];
    const float* embed_b       = (const float*)d_in[3];
    const float* msg_W1        = (const float*)d_in[4];
    const float* msg_b1        = (const float*)d_in[5];
    const float* msg_W2        = (const float*)d_in[6];
    const float* msg_b2        = (const float*)d_in[7];
    const float* upd_W         = (const float*)d_in[8];
    const float* upd_b         = (const float*)d_in[9];
    const float* ln_g          = (const float*)d_in[10];
    const float* ln_b          = (const float*)d_in[11];
    const float* pred_W1       = (const float*)d_in[12];
    const float* pred_b1       = (const float*)d_in[13];
    const float* pred_W2       = (const float*)d_in[14];
    const float* pred_b2       = (const float*)d_in[15];
    const float* pred_W3       = (const float*)d_in[16];
    const float* pred_b3       = (const float*)d_in[17];
    const int*   edge_index    = (const int*)d_in[18];
    float* out = (float*)d_out;

    const int* src = edge_index;
    const int* dst = edge_index + NE;

    cudaFuncSetAttribute(msg_kernel,      cudaFuncAttributeMaxDynamicSharedMemorySize, MSG_SMEM);
    cudaFuncSetAttribute(pred_kernel,     cudaFuncAttributeMaxDynamicSharedMemorySize, PRED_SMEM);
    cudaFuncSetAttribute(updnl_kernel,    cudaFuncAttributeMaxDynamicSharedMemorySize, UPDNL_SMEM);
    cudaFuncSetAttribute(embed_nl_kernel, cudaFuncAttributeMaxDynamicSharedMemorySize, EMB_SMEM);
    cudaFuncSetAttribute(wc_kernel,       cudaFuncAttributeMaxDynamicSharedMemorySize, WC_SMEM);

    init_kernel<<<(NN * HH / 4 + NN / 4 + 255) / 256, 256>>>();
    count_kernel<<<(NE + 255) / 256, 256>>>(dst);
    embed_nl_kernel<<<296, 256, EMB_SMEM>>>(node_features, embed_W, embed_b, msg_W1);
    wc_kernel<<<LL, 512, WC_SMEM>>>(msg_W2, msg_b2, upd_W);

    for (int l = 0; l < LL; l++) {
        // launch 4 = msg l0, launch 5 = updnl l0 -> ncu (-s 5) profiles updnl this round
        msg_kernel<<<296, 512, MSG_SMEM>>>(edge_attr, src, dst,
                                           msg_W1 + l * EIN * HH, msg_b1 + l * HH);
        const float* nextW1 = (l < LL - 1) ? (msg_W1 + (l + 1) * EIN * HH) : pred_W1;
        updnl_kernel<<<148, 512, UPDNL_SMEM>>>(upd_W + (size_t)l * UIN * DD, upd_b + l * DD,
                                               ln_g + l * DD, ln_b + l * DD, nextW1, l);
    }

    pred_kernel<<<296, 512, PRED_SMEM>>>(edge_attr, src, dst,
                                         pred_W1, pred_b1, pred_W2, pred_b2,
                                         pred_W3, pred_b3, out);
}

// round 15
// speedup vs baseline: 2.8016x; 1.0380x over previous
#include <cuda_runtime.h>
#include <cuda_fp16.h>
#include <math.h>

#define NN 50000
#define NE 500000
#define FN 7
#define FE 8
#define DD 64
#define HH 128
#define PP 256
#define EIN 136
#define UIN 192
#define LL 3
#define EPB 128

#define WXS 68
#define WCS 132
#define NLS 68
#define H1S 136

typedef unsigned long long u64;

__device__ __forceinline__ void ffma2(u64 &d, u64 a, u64 b) {
    asm("fma.rn.f32x2 %0, %1, %2, %0;" : "+l"(d) : "l"(a), "l"(b));
}
__device__ __forceinline__ float f2sum(u64 a) {
    float lo, hi;
    asm("mov.b64 {%0, %1}, %2;" : "=f"(lo), "=f"(hi) : "l"(a));
    return lo + hi;
}
__device__ __forceinline__ void red_add_v4(float* p, float4 v) {
    u64 gp;
    asm("cvta.to.global.u64 %0, %1;" : "=l"(gp) : "l"(p));
    asm volatile("red.global.add.v4.f32 [%0], {%1, %2, %3, %4};"
                 :: "l"(gp), "f"(v.x), "f"(v.y), "f"(v.z), "f"(v.w) : "memory");
}
__device__ __forceinline__ void cp16(unsigned saddr, const void* g) {
    asm volatile("cp.async.cg.shared.global [%0], [%1], 16;" :: "r"(saddr), "l"(g));
}
#define CP_COMMIT()   asm volatile("cp.async.commit_group;" ::: "memory")
#define CP_WAIT_ALL() asm volatile("cp.async.wait_group 0;" ::: "memory")

__device__ __forceinline__ unsigned smem_u32(const void* p) {
    unsigned a;
    asm("{ .reg .u64 t; cvta.to.shared.u64 t, %1; cvt.u32.u64 %0, t; }" : "=r"(a) : "l"(p));
    return a;
}
__device__ __forceinline__ void ldsm_x4(unsigned &r0, unsigned &r1, unsigned &r2, unsigned &r3,
                                        unsigned addr) {
    asm volatile("ldmatrix.sync.aligned.m8n8.x4.shared.b16 {%0,%1,%2,%3}, [%4];"
                 : "=r"(r0), "=r"(r1), "=r"(r2), "=r"(r3) : "r"(addr));
}
__device__ __forceinline__ void ldsm_x2(unsigned &r0, unsigned &r1, unsigned addr) {
    asm volatile("ldmatrix.sync.aligned.m8n8.x2.shared.b16 {%0,%1}, [%2];"
                 : "=r"(r0), "=r"(r1) : "r"(addr));
}
__device__ __forceinline__ void mma16816(float* d,
                                         unsigned a0, unsigned a1, unsigned a2, unsigned a3,
                                         unsigned b0, unsigned b1) {
    asm volatile("mma.sync.aligned.m16n8k16.row.col.f32.f16.f16.f32 "
                 "{%0,%1,%2,%3}, {%4,%5,%6,%7}, {%8,%9}, {%0,%1,%2,%3};"
                 : "+f"(d[0]), "+f"(d[1]), "+f"(d[2]), "+f"(d[3])
                 : "r"(a0), "r"(a1), "r"(a2), "r"(a3), "r"(b0), "r"(b1));
}

// ---------------- scratch ----------------
__device__ float g_x[NN * DD];
__device__ float g_agg[NN * HH];
__device__ float g_cnt[NN];
__device__ float g_pab[NN * PP];
__device__ float g_wc[LL * HH * DD];
__device__ float g_bm[LL * DD];

// ---------------- init ----------------
__global__ void init_kernel() {
    int i = blockIdx.x * blockDim.x + threadIdx.x;
    const int A4 = NN * HH / 4;
    if (i < A4) ((float4*)g_agg)[i] = make_float4(0.f, 0.f, 0.f, 0.f);
    else if (i < A4 + NN / 4) ((float4*)g_cnt)[i - A4] = make_float4(0.f, 0.f, 0.f, 0.f);
}

__global__ void count_kernel(const int* __restrict__ dst) {
    int e = blockIdx.x * blockDim.x + threadIdx.x;
    if (e < NE) atomicAdd(&g_cnt[dst[e]], 1.0f);
}

// ---------------- fused embed + node_lin(layer0) ----------------
#define EMB_SMEM ((PP*NLS + FN*DD + DD + 8*FN + 8*DD) * 4)

__global__ void __launch_bounds__(256, 2)
embed_nl_kernel(const float* __restrict__ nf,
                const float* __restrict__ eW, const float* __restrict__ eb,
                const float* __restrict__ W1) {
    extern __shared__ float s[];
    float* sWt = s;
    float* sWe = sWt + PP * NLS;
    float* sBe = sWe + FN * DD;
    float* sNf = sBe + DD;
    float* sX  = sNf + 8 * FN;

    const int tid = threadIdx.x;
    for (int i = tid; i < DD * PP; i += 256) {
        int k = i >> 8, j = i & 255;
        sWt[j * NLS + k] = (j < HH) ? W1[k * HH + j] : W1[(DD + k) * HH + (j - HH)];
    }
    for (int i = tid; i < FN * DD; i += 256) sWe[i] = eW[i];
    if (tid < DD) sBe[tid] = eb[tid];
    __syncthreads();

    const int step = gridDim.x * 8;
    for (int n0 = blockIdx.x * 8; n0 < NN; n0 += step) {
        for (int i = tid; i < 8 * FN; i += 256) {
            int c = i / FN, f = i % FN;
            sNf[i] = nf[(n0 + c) * FN + f];
        }
        __syncthreads();
        for (int i = tid; i < 8 * DD; i += 256) {
            int c = i >> 6, d = i & 63;
            float xv = sBe[d];
#pragma unroll
            for (int f = 0; f < FN; f++) xv += sNf[c * FN + f] * sWe[f * DD + d];
            xv = fmaxf(xv, 0.f);
            sX[c * DD + d] = xv;
            g_x[(n0 + c) * DD + d] = xv;
        }
        __syncthreads();
        u64 acc[8];
#pragma unroll
        for (int c = 0; c < 8; c++) acc[c] = 0ull;
        const float* wr = sWt + tid * NLS;
#pragma unroll 4
        for (int k = 0; k < DD; k += 4) {
            ulonglong2 w = *(const ulonglong2*)(wr + k);
#pragma unroll
            for (int c = 0; c < 8; c++) {
                ulonglong2 v = *(const ulonglong2*)(sX + c * DD + k);
                ffma2(acc[c], w.x, v.x);
                ffma2(acc[c], w.y, v.y);
            }
        }
#pragma unroll
        for (int c = 0; c < 8; c++)
            g_pab[(size_t)(n0 + c) * PP + tid] = f2sum(acc[c]);
        __syncthreads();
    }
}

// ---------------- precompute Wc = W2 @ Wm, bm = b2 @ Wm (grid LL*4) ----------------
#define WC_SMEM ((32*HH + HH*DD) * 4)

__global__ void __launch_bounds__(512)
wc_kernel(const float* __restrict__ W2all, const float* __restrict__ b2all,
          const float* __restrict__ Wall) {
    extern __shared__ float s[];
    float* sW2 = s;              // [32][128]  quarter of W2 rows
    float* sWm = sW2 + 32 * HH;  // [128][64]

    const int l = blockIdx.x >> 2, q = blockIdx.x & 3;
    const float* W2 = W2all + l * HH * HH;
    const float* b2 = b2all + l * HH;
    const float* Wm = Wall + (size_t)l * UIN * DD + DD * DD;

    const int tid = threadIdx.x;
    for (int i = tid; i < 32 * HH; i += 512) sW2[i] = W2[q * 32 * HH + i];
    for (int i = tid; i < HH * DD; i += 512) sWm[i] = Wm[i];
    __syncthreads();

    // 2048 outputs / 512 threads = 4 each; even/odd split accumulators for ILP
    for (int o = tid; o < 32 * DD; o += 512) {
        int k = o >> 6, d = o & 63;
        float a0 = 0.f, a1 = 0.f;
#pragma unroll 8
        for (int j = 0; j < HH; j += 2) {
            a0 += sW2[k * HH + j] * sWm[j * DD + d];
            a1 += sW2[k * HH + j + 1] * sWm[(j + 1) * DD + d];
        }
        g_wc[l * HH * DD + (q * 32 + k) * DD + d] = a0 + a1;
    }
    if (q == 0 && tid < DD) {
        float a0 = 0.f, a1 = 0.f;
        for (int j = 0; j < HH; j += 2) {
            a0 += b2[j] * sWm[j * DD + tid];
            a1 += b2[j + 1] * sWm[(j + 1) * DD + tid];
        }
        g_bm[l * DD + tid] = a0 + a1;
    }
}

// ---------------- edge message ----------------
#define MSG_SMEM ((EPB*HH + EPB*FE + 2*EPB) * 4)

__global__ void __launch_bounds__(512, 2)
msg_kernel(const float* __restrict__ ea,
           const int* __restrict__ src, const int* __restrict__ dst,
           const float* __restrict__ W1, const float* __restrict__ b1) {
    extern __shared__ float s[];
    float* sH   = s;
    float* sEa  = sH + EPB * HH;
    int*   sSrc = (int*)(sEa + EPB * FE);
    int*   sDst = sSrc + EPB;

    const int tid = threadIdx.x;
    const int j = tid & 127, g = tid >> 7;
    const int wid = tid >> 5, lane = tid & 31;
    const float b1v = b1[j];
    float w1c[8];
#pragma unroll
    for (int f = 0; f < 8; f++) w1c[f] = W1[(2 * DD + f) * HH + j];

    int e0 = blockIdx.x * EPB;
    const int step = gridDim.x * EPB;

    for (; e0 < NE; e0 += step) {
        __syncthreads();
        if (tid < 2 * EPB) {
            int le = tid & (EPB - 1);
            int gc = e0 + le; if (gc >= NE) gc = NE - 1;
            if (tid < EPB) sSrc[le] = src[gc];
            else           sDst[le] = dst[gc];
        }
        for (int i = tid; i < EPB * 2; i += 512) {
            int le = i >> 1, frag = i & 1;
            int gc = e0 + le; if (gc >= NE) gc = NE - 1;
            ((float4*)sEa)[i] = ((const float4*)ea)[(size_t)gc * 2 + frag];
        }
        __syncthreads();

        {
            float pa[4], pb[4];
#pragma unroll
            for (int c = 0; c < 4; c++) {
                int e = g + 4 * c;
                pa[c] = g_pab[(size_t)sSrc[e] * PP + j];
                pb[c] = g_pab[(size_t)sDst[e] * PP + HH + j];
            }
#pragma unroll
            for (int c = 0; c < 32; c++) {
                int e = g + 4 * c;
                float hv = pa[c & 3] + pb[c & 3] + b1v;
                if (c + 4 < 32) {
                    int e2 = g + 4 * (c + 4);
                    pa[c & 3] = g_pab[(size_t)sSrc[e2] * PP + j];
                    pb[c & 3] = g_pab[(size_t)sDst[e2] * PP + HH + j];
                }
                float4 a0 = ((const float4*)(sEa + e * FE))[0];
                float4 a1 = ((const float4*)(sEa + e * FE))[1];
                hv = fmaf(a0.x, w1c[0], hv); hv = fmaf(a0.y, w1c[1], hv);
                hv = fmaf(a0.z, w1c[2], hv); hv = fmaf(a0.w, w1c[3], hv);
                hv = fmaf(a1.x, w1c[4], hv); hv = fmaf(a1.y, w1c[5], hv);
                hv = fmaf(a1.z, w1c[6], hv); hv = fmaf(a1.w, w1c[7], hv);
                sH[e * HH + j] = fmaxf(hv, 0.f);
            }
        }
        __syncthreads();

#pragma unroll
        for (int t = 0; t < 8; t++) {
            int le = wid * 8 + t;
            if (e0 + le < NE) {
                float4 m = ((const float4*)(sH + le * HH))[lane];
                red_add_v4(g_agg + (size_t)sDst[le] * HH + lane * 4, m);
            }
        }
    }
}

// ---------------- fused node kernel (folded Wc) ----------------
#define NPT 8
#define STG (NPT*DD + NPT*HH + NPT)
#define UPDNL_SMEM ((DD*WXS + DD*WCS + PP*NLS + 2*STG + NPT*DD + 32) * 4)

__global__ void __launch_bounds__(512, 1)
updnl_kernel(const float* __restrict__ W, const float* __restrict__ b,
             const float* __restrict__ lg, const float* __restrict__ lb,
             const float* __restrict__ W1next, int layer) {
    extern __shared__ float s[];
    float* sWxt = s;
    float* sWct = sWxt + DD * WXS;
    float* sWnl = sWct + DD * WCS;
    float* sStg = sWnl + PP * NLS;
    float* sXn  = sStg + 2 * STG;
    float* sRed = sXn + NPT * DD;

    const unsigned aStg = (unsigned)__cvta_generic_to_shared(sStg);
    const float* wc = g_wc + layer * HH * DD;
    const float* bm = g_bm + layer * DD;

    const int tid = threadIdx.x;
    for (int i = tid; i < DD * DD; i += 512) { int t = i >> 6, d = i & 63; sWxt[d * WXS + t] = W[t * DD + d]; }
    for (int i = tid; i < HH * DD; i += 512) { int k = i >> 6, d = i & 63; sWct[d * WCS + k] = wc[k * DD + d]; }
    for (int i = tid; i < DD * PP; i += 512) {
        int k = i >> 8, j = i & 255;
        sWnl[j * NLS + k] = (j < HH) ? W1next[k * HH + j] : W1next[(DD + k) * HH + (j - HH)];
    }

    const int d = tid & 63, ln = tid >> 6;
    const int wg = (tid >> 5) & 1, lane = tid & 31;
    const int j = tid & 255, grp = tid >> 8;
    const float bv = b[d], gv = lg[d], lbv = lb[d], bmv = bm[d];

    const int stride = gridDim.x * NPT;

#define STAGE(N0, B) { \
    unsigned base = aStg + (B) * STG * 4; \
    if (tid < 128) { \
        int node = tid >> 4, frag = tid & 15; \
        cp16(base + (node * DD + frag * 4) * 4, g_x + (size_t)((N0) + node) * DD + frag * 4); } \
    else if (tid < 384) { \
        int t2 = tid - 128; \
        int node = t2 >> 5, frag = t2 & 31; \
        cp16(base + (NPT * DD + node * HH + frag * 4) * 4, \
             g_agg + (size_t)((N0) + node) * HH + frag * 4); } \
    else if (tid < 386) { \
        cp16(base + (NPT * DD + NPT * HH + (tid - 384) * 4) * 4, g_cnt + (N0) + (tid - 384) * 4); } }

    int n0 = blockIdx.x * NPT;
    if (n0 < NN) { STAGE(n0, 0); }
    CP_COMMIT();
    __syncthreads();

    int buf = 0;
    for (; n0 < NN; n0 += stride, buf ^= 1) {
        CP_WAIT_ALL();
        __syncthreads();

        const float* sX   = sStg + buf * STG;
        const float* sAgg = sX + NPT * DD;
        const float* sCnt = sAgg + NPT * HH;

        if (tid < 256) {
            int nn = n0 + (tid >> 5);
            ((float4*)(g_agg + (size_t)nn * HH))[tid & 31] = make_float4(0.f, 0.f, 0.f, 0.f);
        }
        int nnext = n0 + stride;
        if (nnext < NN) { STAGE(nnext, buf ^ 1); }
        CP_COMMIT();

        u64 ax = 0ull, ac = 0ull;
        const float* wrx = sWxt + d * WXS;
        const float* wrc = sWct + d * WCS;
        const float* xin = sX + ln * DD;
        const float* ain = sAgg + ln * HH;
#pragma unroll 4
        for (int k = 0; k < DD; k += 4) {
            ulonglong2 w = *(const ulonglong2*)(wrx + k);
            ulonglong2 v = *(const ulonglong2*)(xin + k);
            ffma2(ax, w.x, v.x);
            ffma2(ax, w.y, v.y);
        }
#pragma unroll 4
        for (int k = 0; k < HH; k += 4) {
            ulonglong2 w = *(const ulonglong2*)(wrc + k);
            ulonglong2 v = *(const ulonglong2*)(ain + k);
            ffma2(ac, w.x, v.x);
            ffma2(ac, w.y, v.y);
        }
        float cntv = sCnt[ln];
        float inv = 1.f / (cntv + 1e-6f);
        float outv = xin[d] + fmaxf(f2sum(ax) + f2sum(ac) * inv + cntv * inv * bmv + bv, 0.f);

        float s1 = outv, s2 = outv * outv;
#pragma unroll
        for (int off = 16; off; off >>= 1) {
            s1 += __shfl_xor_sync(0xFFFFFFFFu, s1, off);
            s2 += __shfl_xor_sync(0xFFFFFFFFu, s2, off);
        }
        if (lane == 0) { sRed[(ln * 2 + wg) * 2] = s1; sRed[(ln * 2 + wg) * 2 + 1] = s2; }
        __syncthreads();
        {
            float t1 = sRed[ln * 4] + sRed[ln * 4 + 2];
            float t2 = sRed[ln * 4 + 1] + sRed[ln * 4 + 3];
            float mu = t1 * (1.f / DD);
            float var = t2 * (1.f / DD) - mu * mu;
            float xn = (outv - mu) * rsqrtf(var + 1e-5f) * gv + lbv;
            g_x[(size_t)(n0 + ln) * DD + d] = xn;
            sXn[ln * DD + d] = xn;
        }
        __syncthreads();

        u64 acc[4];
#pragma unroll
        for (int c = 0; c < 4; c++) acc[c] = 0ull;
        const float* wr2 = sWnl + j * NLS;
#pragma unroll 4
        for (int k = 0; k < DD; k += 4) {
            ulonglong2 w = *(const ulonglong2*)(wr2 + k);
#pragma unroll
            for (int c = 0; c < 4; c++) {
                ulonglong2 v = *(const ulonglong2*)(sXn + (grp + 2 * c) * DD + k);
                ffma2(acc[c], w.x, v.x);
                ffma2(acc[c], w.y, v.y);
            }
        }
#pragma unroll
        for (int c = 0; c < 4; c++)
            g_pab[(size_t)(n0 + grp + 2 * c) * PP + j] = f2sum(acc[c]);
        __syncthreads();
    }
#undef STAGE
}

// ---------------- edge predictor (fp16 mma.sync, fragment-resident epilogue) ----------------
// smem: sH1 34816 + sBW 17408 + sEa 4096 + src/dst 1024 + W3/B2 512 + sPart 1024 = 58880 B
#define PRED_SMEM (34816 + 17408 + 4096 + 1024 + 512 + 1024)

__global__ void __launch_bounds__(512, 2)
pred_kernel(const float* __restrict__ ea,
            const int* __restrict__ src, const int* __restrict__ dst,
            const float* __restrict__ W1, const float* __restrict__ b1,
            const float* __restrict__ W2, const float* __restrict__ b2,
            const float* __restrict__ W3, const float* __restrict__ b3,
            float* __restrict__ out) {
    extern __shared__ char sc[];
    __half* sH1 = (__half*)sc;                       // [128][136] fp16
    __half* sBW = (__half*)(sc + 34816);             // [64][136] fp16
    float*  sEa = (float*)(sc + 34816 + 17408);      // [128][8]
    int*    sSrc = (int*)(sEa + EPB * FE);
    int*    sDst = sSrc + EPB;
    float*  sW3 = (float*)(sDst + EPB);              // 64
    float*  sB2 = sW3 + DD;                          // 64
    float*  sPart = sB2 + DD;                        // [128][2]

    const int tid = threadIdx.x;
    const int wid = tid >> 5, lane = tid & 31;
    const int j = tid & 127, g = tid >> 7;

    for (int i = tid; i < HH * DD; i += 512) {
        int k = i >> 6, n = i & 63;
        sBW[n * H1S + k] = __float2half(W2[i]);
    }
    if (tid < DD) { sW3[tid] = W3[tid]; sB2[tid] = b2[tid]; }

    const unsigned aH1 = smem_u32(sH1);
    const unsigned aBW = smem_u32(sBW);

    const float b1v = b1[j], b3v = b3[0];
    float w1c[8];
#pragma unroll
    for (int f = 0; f < 8; f++) w1c[f] = W1[(2 * DD + f) * HH + j];

    const int mrow = (wid & 7) * 16;
    const int nbase = (wid >> 3) * 32;
    const int half = wid >> 3;
    const int a_row = (lane & 7) + ((lane >> 3) & 1) * 8;
    const int a_kof = (lane >> 4) * 8;
    const int b_row = lane & 7;
    const int b_kof = ((lane >> 3) & 1) * 8;

    int e0 = blockIdx.x * EPB;
    const int step = gridDim.x * EPB;

    for (; e0 < NE; e0 += step) {
        __syncthreads();                       // prior iter's sPart reads done; sH1 free
        if (tid < 2 * EPB) {
            int le = tid & (EPB - 1);
            int gc = e0 + le; if (gc >= NE) gc = NE - 1;
            if (tid < EPB) sSrc[le] = src[gc];
            else           sDst[le] = dst[gc];
        }
        for (int i = tid; i < EPB * 2; i += 512) {
            int le = i >> 1, frag = i & 1;
            int gc = e0 + le; if (gc >= NE) gc = NE - 1;
            ((float4*)sEa)[i] = ((const float4*)ea)[(size_t)gc * 2 + frag];
        }
        __syncthreads();

        // ---- phase A: h1 = relu(Pa + Pb + ea@W1c + b1) -> fp16 [e][136] ----
        {
            float pa[4], pb[4];
#pragma unroll
            for (int c = 0; c < 4; c++) {
                int e = g + 4 * c;
                pa[c] = g_pab[(size_t)sSrc[e] * PP + j];
                pb[c] = g_pab[(size_t)sDst[e] * PP + HH + j];
            }
#pragma unroll
            for (int c = 0; c < 32; c++) {
                int e = g + 4 * c;
                float hv = pa[c & 3] + pb[c & 3] + b1v;
                if (c + 4 < 32) {
                    int e2 = g + 4 * (c + 4);
                    pa[c & 3] = g_pab[(size_t)sSrc[e2] * PP + j];
                    pb[c & 3] = g_pab[(size_t)sDst[e2] * PP + HH + j];
                }
                float4 a0 = ((const float4*)(sEa + e * FE))[0];
                float4 a1 = ((const float4*)(sEa + e * FE))[1];
                hv = fmaf(a0.x, w1c[0], hv); hv = fmaf(a0.y, w1c[1], hv);
                hv = fmaf(a0.z, w1c[2], hv); hv = fmaf(a0.w, w1c[3], hv);
                hv = fmaf(a1.x, w1c[4], hv); hv = fmaf(a1.y, w1c[5], hv);
                hv = fmaf(a1.z, w1c[6], hv); hv = fmaf(a1.w, w1c[7], hv);
                sH1[e * H1S + j] = __float2half(fmaxf(hv, 0.f));
            }
        }
        __syncthreads();

        // ---- GEMM2 (mma.sync) + fragment-resident epilogue ----
        {
            float dfr[4][4];
#pragma unroll
            for (int t = 0; t < 4; t++)
#pragma unroll
                for (int q = 0; q < 4; q++) dfr[t][q] = 0.f;

#pragma unroll
            for (int ks = 0; ks < 8; ks++) {
                int k0 = ks * 16;
                unsigned fa0, fa1, fa2, fa3;
                ldsm_x4(fa0, fa1, fa2, fa3,
                        aH1 + ((mrow + a_row) * H1S + k0 + a_kof) * 2);
#pragma unroll
                for (int t = 0; t < 4; t++) {
                    unsigned fb0, fb1;
                    ldsm_x2(fb0, fb1,
                            aBW + ((nbase + t * 8 + b_row) * H1S + k0 + b_kof) * 2);
                    mma16816(dfr[t], fa0, fa1, fa2, fa3, fb0, fb1);
                }
            }

            // per-thread partial dot over its 8 columns, rows r0 and r1
            float p0 = 0.f, p1 = 0.f;
#pragma unroll
            for (int t = 0; t < 4; t++) {
                int c0 = nbase + t * 8 + 2 * (lane & 3);
                float w0 = sW3[c0], w1 = sW3[c0 + 1];
                float bb0 = sB2[c0], bb1 = sB2[c0 + 1];
                p0 = fmaf(fmaxf(dfr[t][0] + bb0, 0.f), w0, p0);
                p0 = fmaf(fmaxf(dfr[t][1] + bb1, 0.f), w1, p0);
                p1 = fmaf(fmaxf(dfr[t][2] + bb0, 0.f), w0, p1);
                p1 = fmaf(fmaxf(dfr[t][3] + bb1, 0.f), w1, p1);
            }
            p0 += __shfl_xor_sync(0xFFFFFFFFu, p0, 1);
            p0 += __shfl_xor_sync(0xFFFFFFFFu, p0, 2);
            p1 += __shfl_xor_sync(0xFFFFFFFFu, p1, 1);
            p1 += __shfl_xor_sync(0xFFFFFFFFu, p1, 2);
            int r0 = mrow + (lane >> 2), r1 = r0 + 8;
            if ((lane & 3) == 0) {
                sPart[r0 * 2 + half] = p0;
                sPart[r1 * 2 + half] = p1;
            }
        }
        __syncthreads();

        // combine two n-halves, tanh, store
        if (tid < EPB) {
            int ge = e0 + tid;
            float v = sPart[tid * 2] + sPart[tid * 2 + 1];
            if (ge < NE) out[ge] = tanhf(v + b3v);
        }
    }
}

// ---------------- launch ----------------
extern "C" void kernel_launch(void* const* d_in, const int* in_sizes, int n_in,
                              void* d_out, int out_size) {
    const float* node_features = (const float*)d_in[0];
    const float* edge_attr     = (const float*)d_in[1];
    const float* embed_W       = (const float*)d_in[2];
    const float* embed_b       = (const float*)d_in[3];
    const float* msg_W1        = (const float*)d_in[4];
    const float* msg_b1        = (const float*)d_in[5];
    const float* msg_W2        = (const float*)d_in[6];
    const float* msg_b2        = (const float*)d_in[7];
    const float* upd_W         = (const float*)d_in[8];
    const float* upd_b         = (const float*)d_in[9];
    const float* ln_g          = (const float*)d_in[10];
    const float* ln_b          = (const float*)d_in[11];
    const float* pred_W1       = (const float*)d_in[12];
    const float* pred_b1       = (const float*)d_in[13];
    const float* pred_W2       = (const float*)d_in[14];
    const float* pred_b2       = (const float*)d_in[15];
    const float* pred_W3       = (const float*)d_in[16];
    const float* pred_b3       = (const float*)d_in[17];
    const int*   edge_index    = (const int*)d_in[18];
    float* out = (float*)d_out;

    const int* src = edge_index;
    const int* dst = edge_index + NE;

    cudaFuncSetAttribute(msg_kernel,      cudaFuncAttributeMaxDynamicSharedMemorySize, MSG_SMEM);
    cudaFuncSetAttribute(pred_kernel,     cudaFuncAttributeMaxDynamicSharedMemorySize, PRED_SMEM);
    cudaFuncSetAttribute(updnl_kernel,    cudaFuncAttributeMaxDynamicSharedMemorySize, UPDNL_SMEM);
    cudaFuncSetAttribute(embed_nl_kernel, cudaFuncAttributeMaxDynamicSharedMemorySize, EMB_SMEM);
    cudaFuncSetAttribute(wc_kernel,       cudaFuncAttributeMaxDynamicSharedMemorySize, WC_SMEM);

    init_kernel<<<(NN * HH / 4 + NN / 4 + 255) / 256, 256>>>();
    count_kernel<<<(NE + 255) / 256, 256>>>(dst);
    embed_nl_kernel<<<296, 256, EMB_SMEM>>>(node_features, embed_W, embed_b, msg_W1);
    wc_kernel<<<LL * 4, 512, WC_SMEM>>>(msg_W2, msg_b2, upd_W);

    for (int l = 0; l < LL; l++) {
        msg_kernel<<<296, 512, MSG_SMEM>>>(edge_attr, src, dst,
                                           msg_W1 + l * EIN * HH, msg_b1 + l * HH);
        const float* nextW1 = (l < LL - 1) ? (msg_W1 + (l + 1) * EIN * HH) : pred_W1;
        updnl_kernel<<<148, 512, UPDNL_SMEM>>>(upd_W + (size_t)l * UIN * DD, upd_b + l * DD,
                                               ln_g + l * DD, ln_b + l * DD, nextW1, l);
    }

    pred_kernel<<<296, 512, PRED_SMEM>>>(edge_attr, src, dst,
                                         pred_W1, pred_b1, pred_W2, pred_b2,
                                         pred_W3, pred_b3, out);
}

// round 16
// speedup vs baseline: 3.1976x; 1.1414x over previous
#include <cuda_runtime.h>
#include <cuda_fp16.h>
#include <math.h>

#define NN 50000
#define NE 500000
#define FN 7
#define FE 8
#define DD 64
#define HH 128
#define PP 256
#define EIN 136
#define UIN 192
#define LL 3
#define EPB 128

#define WXS 68
#define WCS 132
#define NLS 68
#define H1S 136

typedef unsigned long long u64;

__device__ __forceinline__ void ffma2(u64 &d, u64 a, u64 b) {
    asm("fma.rn.f32x2 %0, %1, %2, %0;" : "+l"(d) : "l"(a), "l"(b));
}
__device__ __forceinline__ float f2sum(u64 a) {
    float lo, hi;
    asm("mov.b64 {%0, %1}, %2;" : "=f"(lo), "=f"(hi) : "l"(a));
    return lo + hi;
}
__device__ __forceinline__ void red_add_v4(float* p, float4 v) {
    u64 gp;
    asm("cvta.to.global.u64 %0, %1;" : "=l"(gp) : "l"(p));
    asm volatile("red.global.add.v4.f32 [%0], {%1, %2, %3, %4};"
                 :: "l"(gp), "f"(v.x), "f"(v.y), "f"(v.z), "f"(v.w) : "memory");
}
__device__ __forceinline__ void cp16(unsigned saddr, const void* g) {
    asm volatile("cp.async.cg.shared.global [%0], [%1], 16;" :: "r"(saddr), "l"(g));
}
#define CP_COMMIT()   asm volatile("cp.async.commit_group;" ::: "memory")
#define CP_WAIT_ALL() asm volatile("cp.async.wait_group 0;" ::: "memory")

__device__ __forceinline__ unsigned smem_u32(const void* p) {
    unsigned a;
    asm("{ .reg .u64 t; cvta.to.shared.u64 t, %1; cvt.u32.u64 %0, t; }" : "=r"(a) : "l"(p));
    return a;
}
__device__ __forceinline__ void ldsm_x4(unsigned &r0, unsigned &r1, unsigned &r2, unsigned &r3,
                                        unsigned addr) {
    asm volatile("ldmatrix.sync.aligned.m8n8.x4.shared.b16 {%0,%1,%2,%3}, [%4];"
                 : "=r"(r0), "=r"(r1), "=r"(r2), "=r"(r3) : "r"(addr));
}
__device__ __forceinline__ void ldsm_x2(unsigned &r0, unsigned &r1, unsigned addr) {
    asm volatile("ldmatrix.sync.aligned.m8n8.x2.shared.b16 {%0,%1}, [%2];"
                 : "=r"(r0), "=r"(r1) : "r"(addr));
}
__device__ __forceinline__ void mma16816(float* d,
                                         unsigned a0, unsigned a1, unsigned a2, unsigned a3,
                                         unsigned b0, unsigned b1) {
    asm volatile("mma.sync.aligned.m16n8k16.row.col.f32.f16.f16.f32 "
                 "{%0,%1,%2,%3}, {%4,%5,%6,%7}, {%8,%9}, {%0,%1,%2,%3};"
                 : "+f"(d[0]), "+f"(d[1]), "+f"(d[2]), "+f"(d[3])
                 : "r"(a0), "r"(a1), "r"(a2), "r"(a3), "r"(b0), "r"(b1));
}

// ---------------- scratch ----------------
__device__ float g_x[NN * DD];
__device__ float g_agg[NN * HH];
__device__ float g_cnt[NN];
__device__ float g_pab[NN * PP];
__device__ float g_wc[LL * HH * DD];
__device__ float g_bm[LL * DD];

// ---------------- init ----------------
__global__ void init_kernel() {
    int i = blockIdx.x * blockDim.x + threadIdx.x;
    const int A4 = NN * HH / 4;
    if (i < A4) ((float4*)g_agg)[i] = make_float4(0.f, 0.f, 0.f, 0.f);
    else if (i < A4 + NN / 4) ((float4*)g_cnt)[i - A4] = make_float4(0.f, 0.f, 0.f, 0.f);
}

__global__ void count_kernel(const int* __restrict__ dst) {
    int e = blockIdx.x * blockDim.x + threadIdx.x;
    if (e < NE) atomicAdd(&g_cnt[dst[e]], 1.0f);
}

// ---------------- fused embed + node_lin(layer0) ----------------
#define EMB_SMEM ((PP*NLS + FN*DD + DD + 8*FN + 8*DD) * 4)

__global__ void __launch_bounds__(256, 2)
embed_nl_kernel(const float* __restrict__ nf,
                const float* __restrict__ eW, const float* __restrict__ eb,
                const float* __restrict__ W1) {
    extern __shared__ float s[];
    float* sWt = s;
    float* sWe = sWt + PP * NLS;
    float* sBe = sWe + FN * DD;
    float* sNf = sBe + DD;
    float* sX  = sNf + 8 * FN;

    const int tid = threadIdx.x;
    for (int i = tid; i < DD * PP; i += 256) {
        int k = i >> 8, j = i & 255;
        sWt[j * NLS + k] = (j < HH) ? W1[k * HH + j] : W1[(DD + k) * HH + (j - HH)];
    }
    for (int i = tid; i < FN * DD; i += 256) sWe[i] = eW[i];
    if (tid < DD) sBe[tid] = eb[tid];
    __syncthreads();

    const int step = gridDim.x * 8;
    for (int n0 = blockIdx.x * 8; n0 < NN; n0 += step) {
        for (int i = tid; i < 8 * FN; i += 256) {
            int c = i / FN, f = i % FN;
            sNf[i] = nf[(n0 + c) * FN + f];
        }
        __syncthreads();
        for (int i = tid; i < 8 * DD; i += 256) {
            int c = i >> 6, d = i & 63;
            float xv = sBe[d];
#pragma unroll
            for (int f = 0; f < FN; f++) xv += sNf[c * FN + f] * sWe[f * DD + d];
            xv = fmaxf(xv, 0.f);
            sX[c * DD + d] = xv;
            g_x[(n0 + c) * DD + d] = xv;
        }
        __syncthreads();
        u64 acc[8];
#pragma unroll
        for (int c = 0; c < 8; c++) acc[c] = 0ull;
        const float* wr = sWt + tid * NLS;
#pragma unroll 4
        for (int k = 0; k < DD; k += 4) {
            ulonglong2 w = *(const ulonglong2*)(wr + k);
#pragma unroll
            for (int c = 0; c < 8; c++) {
                ulonglong2 v = *(const ulonglong2*)(sX + c * DD + k);
                ffma2(acc[c], w.x, v.x);
                ffma2(acc[c], w.y, v.y);
            }
        }
#pragma unroll
        for (int c = 0; c < 8; c++)
            g_pab[(size_t)(n0 + c) * PP + tid] = f2sum(acc[c]);
        __syncthreads();
    }
}

// ---------------- precompute Wc = W2 @ Wm, bm = b2 @ Wm (grid LL*16) ----------------
#define WC_SMEM ((8*HH + HH*DD) * 4)

__global__ void __launch_bounds__(512)
wc_kernel(const float* __restrict__ W2all, const float* __restrict__ b2all,
          const float* __restrict__ Wall) {
    extern __shared__ float s[];
    float* sW2 = s;             // [8][128]  8 rows of W2
    float* sWm = sW2 + 8 * HH;  // [128][64]

    const int l = blockIdx.x >> 4, q = blockIdx.x & 15;
    const float* W2 = W2all + l * HH * HH;
    const float* b2 = b2all + l * HH;
    const float* Wm = Wall + (size_t)l * UIN * DD + DD * DD;

    const int tid = threadIdx.x;
    for (int i = tid; i < 8 * HH; i += 512) sW2[i] = W2[q * 8 * HH + i];
    for (int i = tid; i < HH * DD; i += 512) sWm[i] = Wm[i];
    __syncthreads();

    // 512 outputs, 1 per thread, 2-way ILP
    {
        int k = tid >> 6, d = tid & 63;
        float a0 = 0.f, a1 = 0.f;
#pragma unroll 16
        for (int j = 0; j < HH; j += 2) {
            a0 += sW2[k * HH + j] * sWm[j * DD + d];
            a1 += sW2[k * HH + j + 1] * sWm[(j + 1) * DD + d];
        }
        g_wc[l * HH * DD + (q * 8 + k) * DD + d] = a0 + a1;
    }
    if (q == 0 && tid < DD) {
        float a0 = 0.f, a1 = 0.f;
        for (int j = 0; j < HH; j += 2) {
            a0 += b2[j] * sWm[j * DD + tid];
            a1 += b2[j + 1] * sWm[(j + 1) * DD + tid];
        }
        g_bm[l * DD + tid] = a0 + a1;
    }
}

// ---------------- edge message ----------------
#define MSG_SMEM ((EPB*HH + EPB*FE + 2*EPB) * 4)

__global__ void __launch_bounds__(512, 2)
msg_kernel(const float* __restrict__ ea,
           const int* __restrict__ src, const int* __restrict__ dst,
           const float* __restrict__ W1, const float* __restrict__ b1) {
    extern __shared__ float s[];
    float* sH   = s;
    float* sEa  = sH + EPB * HH;
    int*   sSrc = (int*)(sEa + EPB * FE);
    int*   sDst = sSrc + EPB;

    const int tid = threadIdx.x;
    const int j = tid & 127, g = tid >> 7;
    const int wid = tid >> 5, lane = tid & 31;
    const float b1v = b1[j];
    float w1c[8];
#pragma unroll
    for (int f = 0; f < 8; f++) w1c[f] = W1[(2 * DD + f) * HH + j];

    int e0 = blockIdx.x * EPB;
    const int step = gridDim.x * EPB;

    for (; e0 < NE; e0 += step) {
        __syncthreads();
        if (tid < 2 * EPB) {
            int le = tid & (EPB - 1);
            int gc = e0 + le; if (gc >= NE) gc = NE - 1;
            if (tid < EPB) sSrc[le] = src[gc];
            else           sDst[le] = dst[gc];
        }
        for (int i = tid; i < EPB * 2; i += 512) {
            int le = i >> 1, frag = i & 1;
            int gc = e0 + le; if (gc >= NE) gc = NE - 1;
            ((float4*)sEa)[i] = ((const float4*)ea)[(size_t)gc * 2 + frag];
        }
        __syncthreads();

        {
            float pa[4], pb[4];
#pragma unroll
            for (int c = 0; c < 4; c++) {
                int e = g + 4 * c;
                pa[c] = g_pab[(size_t)sSrc[e] * PP + j];
                pb[c] = g_pab[(size_t)sDst[e] * PP + HH + j];
            }
#pragma unroll
            for (int c = 0; c < 32; c++) {
                int e = g + 4 * c;
                float hv = pa[c & 3] + pb[c & 3] + b1v;
                if (c + 4 < 32) {
                    int e2 = g + 4 * (c + 4);
                    pa[c & 3] = g_pab[(size_t)sSrc[e2] * PP + j];
                    pb[c & 3] = g_pab[(size_t)sDst[e2] * PP + HH + j];
                }
                float4 a0 = ((const float4*)(sEa + e * FE))[0];
                float4 a1 = ((const float4*)(sEa + e * FE))[1];
                hv = fmaf(a0.x, w1c[0], hv); hv = fmaf(a0.y, w1c[1], hv);
                hv = fmaf(a0.z, w1c[2], hv); hv = fmaf(a0.w, w1c[3], hv);
                hv = fmaf(a1.x, w1c[4], hv); hv = fmaf(a1.y, w1c[5], hv);
                hv = fmaf(a1.z, w1c[6], hv); hv = fmaf(a1.w, w1c[7], hv);
                sH[e * HH + j] = fmaxf(hv, 0.f);
            }
        }
        __syncthreads();

#pragma unroll
        for (int t = 0; t < 8; t++) {
            int le = wid * 8 + t;
            if (e0 + le < NE) {
                float4 m = ((const float4*)(sH + le * HH))[lane];
                red_add_v4(g_agg + (size_t)sDst[le] * HH + lane * 4, m);
            }
        }
    }
}

// ---------------- fused node kernel (folded Wc, NPT=16) ----------------
#define NPT 16
#define STG (NPT*DD + NPT*HH + NPT)
#define UPDNL_SMEM ((DD*WXS + DD*WCS + PP*NLS + 2*STG + NPT*DD + 64) * 4)

__global__ void __launch_bounds__(512, 1)
updnl_kernel(const float* __restrict__ W, const float* __restrict__ b,
             const float* __restrict__ lg, const float* __restrict__ lb,
             const float* __restrict__ W1next, int layer) {
    extern __shared__ float s[];
    float* sWxt = s;                    // [64][68]
    float* sWct = sWxt + DD * WXS;      // [64][132]
    float* sWnl = sWct + DD * WCS;      // [256][68]
    float* sStg = sWnl + PP * NLS;      // [2][STG]
    float* sXn  = sStg + 2 * STG;       // [16][64]
    float* sRed = sXn + NPT * DD;       // [16 nodes][2 warps][2]

    const unsigned aStg = (unsigned)__cvta_generic_to_shared(sStg);
    const float* wc = g_wc + layer * HH * DD;
    const float* bm = g_bm + layer * DD;

    const int tid = threadIdx.x;
    for (int i = tid; i < DD * DD; i += 512) { int t = i >> 6, d = i & 63; sWxt[d * WXS + t] = W[t * DD + d]; }
    for (int i = tid; i < HH * DD; i += 512) { int k = i >> 6, d = i & 63; sWct[d * WCS + k] = wc[k * DD + d]; }
    for (int i = tid; i < DD * PP; i += 512) {
        int k = i >> 8, j = i & 255;
        sWnl[j * NLS + k] = (j < HH) ? W1next[k * HH + j] : W1next[(DD + k) * HH + (j - HH)];
    }

    const int d = tid & 63, ln = tid >> 6;       // upd: 2 nodes/thread (ln, ln+8)
    const int wg = (tid >> 5) & 1, lane = tid & 31;
    const int j = tid & 255, grp = tid >> 8;     // node_lin: 8 nodes/thread
    const float bv = b[d], gv = lg[d], lbv = lb[d], bmv = bm[d];

    const int stride = gridDim.x * NPT;

    // staging: aggH 512 cp16 (1/thread), x 256 cp16 (tid<256), cnt 4 cp16
#define STAGE(N0, B) { \
    unsigned base = aStg + (B) * STG * 4; \
    cp16(base + (NPT * DD + (tid >> 5) * HH + (tid & 31) * 4) * 4, \
         g_agg + (size_t)((N0) + (tid >> 5)) * HH + (tid & 31) * 4); \
    if (tid < 256) \
        cp16(base + ((tid >> 4) * DD + (tid & 15) * 4) * 4, \
             g_x + (size_t)((N0) + (tid >> 4)) * DD + (tid & 15) * 4); \
    if (tid < 4) \
        cp16(base + (NPT * DD + NPT * HH + tid * 4) * 4, g_cnt + (N0) + tid * 4); }

    int n0 = blockIdx.x * NPT;
    if (n0 < NN) { STAGE(n0, 0); }
    CP_COMMIT();
    __syncthreads();

    int buf = 0;
    for (; n0 < NN; n0 += stride, buf ^= 1) {
        CP_WAIT_ALL();
        __syncthreads();

        const float* sX   = sStg + buf * STG;
        const float* sAgg = sX + NPT * DD;
        const float* sCnt = sAgg + NPT * HH;

        // zero agg rows of this tile
        {
            int nn = n0 + (tid >> 5);
            ((float4*)(g_agg + (size_t)nn * HH))[tid & 31] = make_float4(0.f, 0.f, 0.f, 0.f);
        }
        int nnext = n0 + stride;
        if (nnext < NN) { STAGE(nnext, buf ^ 1); }
        CP_COMMIT();

        // ---- upd: 2 nodes/thread, interleaved chains ----
        float outv[2];
        {
            u64 ax0 = 0ull, ax1 = 0ull, ac0 = 0ull, ac1 = 0ull;
            const float* wrx = sWxt + d * WXS;
            const float* wrc = sWct + d * WCS;
            const float* x0 = sX + ln * DD;
            const float* x1 = sX + (ln + 8) * DD;
            const float* a0p = sAgg + ln * HH;
            const float* a1p = sAgg + (ln + 8) * HH;
#pragma unroll 4
            for (int k = 0; k < DD; k += 4) {
                ulonglong2 w = *(const ulonglong2*)(wrx + k);
                ulonglong2 v0 = *(const ulonglong2*)(x0 + k);
                ulonglong2 v1 = *(const ulonglong2*)(x1 + k);
                ffma2(ax0, w.x, v0.x); ffma2(ax0, w.y, v0.y);
                ffma2(ax1, w.x, v1.x); ffma2(ax1, w.y, v1.y);
            }
#pragma unroll 4
            for (int k = 0; k < HH; k += 4) {
                ulonglong2 w = *(const ulonglong2*)(wrc + k);
                ulonglong2 v0 = *(const ulonglong2*)(a0p + k);
                ulonglong2 v1 = *(const ulonglong2*)(a1p + k);
                ffma2(ac0, w.x, v0.x); ffma2(ac0, w.y, v0.y);
                ffma2(ac1, w.x, v1.x); ffma2(ac1, w.y, v1.y);
            }
            float c0 = sCnt[ln],     i0 = 1.f / (c0 + 1e-6f);
            float c1 = sCnt[ln + 8], i1 = 1.f / (c1 + 1e-6f);
            outv[0] = x0[d] + fmaxf(f2sum(ax0) + f2sum(ac0) * i0 + c0 * i0 * bmv + bv, 0.f);
            outv[1] = x1[d] + fmaxf(f2sum(ax1) + f2sum(ac1) * i1 + c1 * i1 * bmv + bv, 0.f);
        }

        // ---- LayerNorm for both nodes ----
#pragma unroll
        for (int c = 0; c < 2; c++) {
            int nc = ln + 8 * c;
            float s1 = outv[c], s2 = outv[c] * outv[c];
#pragma unroll
            for (int off = 16; off; off >>= 1) {
                s1 += __shfl_xor_sync(0xFFFFFFFFu, s1, off);
                s2 += __shfl_xor_sync(0xFFFFFFFFu, s2, off);
            }
            if (lane == 0) { sRed[(nc * 2 + wg) * 2] = s1; sRed[(nc * 2 + wg) * 2 + 1] = s2; }
        }
        __syncthreads();
#pragma unroll
        for (int c = 0; c < 2; c++) {
            int nc = ln + 8 * c;
            float t1 = sRed[nc * 4] + sRed[nc * 4 + 2];
            float t2 = sRed[nc * 4 + 1] + sRed[nc * 4 + 3];
            float mu = t1 * (1.f / DD);
            float var = t2 * (1.f / DD) - mu * mu;
            float xn = (outv[c] - mu) * rsqrtf(var + 1e-5f) * gv + lbv;
            g_x[(size_t)(n0 + nc) * DD + d] = xn;
            sXn[nc * DD + d] = xn;
        }
        __syncthreads();

        // ---- node_lin: 8 nodes/thread ----
        u64 acc[8];
#pragma unroll
        for (int c = 0; c < 8; c++) acc[c] = 0ull;
        const float* wr2 = sWnl + j * NLS;
#pragma unroll 4
        for (int k = 0; k < DD; k += 4) {
            ulonglong2 w = *(const ulonglong2*)(wr2 + k);
#pragma unroll
            for (int c = 0; c < 8; c++) {
                ulonglong2 v = *(const ulonglong2*)(sXn + (grp + 2 * c) * DD + k);
                ffma2(acc[c], w.x, v.x);
                ffma2(acc[c], w.y, v.y);
            }
        }
#pragma unroll
        for (int c = 0; c < 8; c++)
            g_pab[(size_t)(n0 + grp + 2 * c) * PP + j] = f2sum(acc[c]);
        __syncthreads();
    }
#undef STAGE
}

// ---------------- edge predictor (fp16 mma.sync, fragment-resident epilogue) ----------------
#define PRED_SMEM (34816 + 17408 + 4096 + 1024 + 512 + 1024)

__global__ void __launch_bounds__(512, 2)
pred_kernel(const float* __restrict__ ea,
            const int* __restrict__ src, const int* __restrict__ dst,
            const float* __restrict__ W1, const float* __restrict__ b1,
            const float* __restrict__ W2, const float* __restrict__ b2,
            const float* __restrict__ W3, const float* __restrict__ b3,
            float* __restrict__ out) {
    extern __shared__ char sc[];
    __half* sH1 = (__half*)sc;                       // [128][136] fp16
    __half* sBW = (__half*)(sc + 34816);             // [64][136] fp16
    float*  sEa = (float*)(sc + 34816 + 17408);      // [128][8]
    int*    sSrc = (int*)(sEa + EPB * FE);
    int*    sDst = sSrc + EPB;
    float*  sW3 = (float*)(sDst + EPB);              // 64
    float*  sB2 = sW3 + DD;                          // 64
    float*  sPart = sB2 + DD;                        // [128][2]

    const int tid = threadIdx.x;
    const int wid = tid >> 5, lane = tid & 31;
    const int j = tid & 127, g = tid >> 7;

    for (int i = tid; i < HH * DD; i += 512) {
        int k = i >> 6, n = i & 63;
        sBW[n * H1S + k] = __float2half(W2[i]);
    }
    if (tid < DD) { sW3[tid] = W3[tid]; sB2[tid] = b2[tid]; }

    const unsigned aH1 = smem_u32(sH1);
    const unsigned aBW = smem_u32(sBW);

    const float b1v = b1[j], b3v = b3[0];
    float w1c[8];
#pragma unroll
    for (int f = 0; f < 8; f++) w1c[f] = W1[(2 * DD + f) * HH + j];

    const int mrow = (wid & 7) * 16;
    const int nbase = (wid >> 3) * 32;
    const int half = wid >> 3;
    const int a_row = (lane & 7) + ((lane >> 3) & 1) * 8;
    const int a_kof = (lane >> 4) * 8;
    const int b_row = lane & 7;
    const int b_kof = ((lane >> 3) & 1) * 8;

    int e0 = blockIdx.x * EPB;
    const int step = gridDim.x * EPB;

    for (; e0 < NE; e0 += step) {
        __syncthreads();
        if (tid < 2 * EPB) {
            int le = tid & (EPB - 1);
            int gc = e0 + le; if (gc >= NE) gc = NE - 1;
            if (tid < EPB) sSrc[le] = src[gc];
            else           sDst[le] = dst[gc];
        }
        for (int i = tid; i < EPB * 2; i += 512) {
            int le = i >> 1, frag = i & 1;
            int gc = e0 + le; if (gc >= NE) gc = NE - 1;
            ((float4*)sEa)[i] = ((const float4*)ea)[(size_t)gc * 2 + frag];
        }
        __syncthreads();

        {
            float pa[4], pb[4];
#pragma unroll
            for (int c = 0; c < 4; c++) {
                int e = g + 4 * c;
                pa[c] = g_pab[(size_t)sSrc[e] * PP + j];
                pb[c] = g_pab[(size_t)sDst[e] * PP + HH + j];
            }
#pragma unroll
            for (int c = 0; c < 32; c++) {
                int e = g + 4 * c;
                float hv = pa[c & 3] + pb[c & 3] + b1v;
                if (c + 4 < 32) {
                    int e2 = g + 4 * (c + 4);
                    pa[c & 3] = g_pab[(size_t)sSrc[e2] * PP + j];
                    pb[c & 3] = g_pab[(size_t)sDst[e2] * PP + HH + j];
                }
                float4 a0 = ((const float4*)(sEa + e * FE))[0];
                float4 a1 = ((const float4*)(sEa + e * FE))[1];
                hv = fmaf(a0.x, w1c[0], hv); hv = fmaf(a0.y, w1c[1], hv);
                hv = fmaf(a0.z, w1c[2], hv); hv = fmaf(a0.w, w1c[3], hv);
                hv = fmaf(a1.x, w1c[4], hv); hv = fmaf(a1.y, w1c[5], hv);
                hv = fmaf(a1.z, w1c[6], hv); hv = fmaf(a1.w, w1c[7], hv);
                sH1[e * H1S + j] = __float2half(fmaxf(hv, 0.f));
            }
        }
        __syncthreads();

        {
            float dfr[4][4];
#pragma unroll
            for (int t = 0; t < 4; t++)
#pragma unroll
                for (int q = 0; q < 4; q++) dfr[t][q] = 0.f;

#pragma unroll
            for (int ks = 0; ks < 8; ks++) {
                int k0 = ks * 16;
                unsigned fa0, fa1, fa2, fa3;
                ldsm_x4(fa0, fa1, fa2, fa3,
                        aH1 + ((mrow + a_row) * H1S + k0 + a_kof) * 2);
#pragma unroll
                for (int t = 0; t < 4; t++) {
                    unsigned fb0, fb1;
                    ldsm_x2(fb0, fb1,
                            aBW + ((nbase + t * 8 + b_row) * H1S + k0 + b_kof) * 2);
                    mma16816(dfr[t], fa0, fa1, fa2, fa3, fb0, fb1);
                }
            }

            float p0 = 0.f, p1 = 0.f;
#pragma unroll
            for (int t = 0; t < 4; t++) {
                int c0 = nbase + t * 8 + 2 * (lane & 3);
                float w0 = sW3[c0], w1 = sW3[c0 + 1];
                float bb0 = sB2[c0], bb1 = sB2[c0 + 1];
                p0 = fmaf(fmaxf(dfr[t][0] + bb0, 0.f), w0, p0);
                p0 = fmaf(fmaxf(dfr[t][1] + bb1, 0.f), w1, p0);
                p1 = fmaf(fmaxf(dfr[t][2] + bb0, 0.f), w0, p1);
                p1 = fmaf(fmaxf(dfr[t][3] + bb1, 0.f), w1, p1);
            }
            p0 += __shfl_xor_sync(0xFFFFFFFFu, p0, 1);
            p0 += __shfl_xor_sync(0xFFFFFFFFu, p0, 2);
            p1 += __shfl_xor_sync(0xFFFFFFFFu, p1, 1);
            p1 += __shfl_xor_sync(0xFFFFFFFFu, p1, 2);
            int r0 = mrow + (lane >> 2), r1 = r0 + 8;
            if ((lane & 3) == 0) {
                sPart[r0 * 2 + half] = p0;
                sPart[r1 * 2 + half] = p1;
            }
        }
        __syncthreads();

        if (tid < EPB) {
            int ge = e0 + tid;
            float v = sPart[tid * 2] + sPart[tid * 2 + 1];
            if (ge < NE) out[ge] = tanhf(v + b3v);
        }
    }
}

// ---------------- launch ----------------
extern "C" void kernel_launch(void* const* d_in, const int* in_sizes, int n_in,
                              void* d_out, int out_size) {
    const float* node_features = (const float*)d_in[0];
    const float* edge_attr     = (const float*)d_in[1];
    const float* embed_W       = (const float*)d_in[2];
    const float* embed_b       = (const float*)d_in[3];
    const float* msg_W1        = (const float*)d_in[4];
    const float* msg_b1        = (const float*)d_in[5];
    const float* msg_W2        = (const float*)d_in[6];
    const float* msg_b2        = (const float*)d_in[7];
    const float* upd_W         = (const float*)d_in[8];
    const float* upd_b         = (const float*)d_in[9];
    const float* ln_g          = (const float*)d_in[10];
    const float* ln_b          = (const float*)d_in[11];
    const float* pred_W1       = (const float*)d_in[12];
    const float* pred_b1       = (const float*)d_in[13];
    const float* pred_W2       = (const float*)d_in[14];
    const float* pred_b2       = (const float*)d_in[15];
    const float* pred_W3       = (const float*)d_in[16];
    const float* pred_b3       = (const float*)d_in[17];
    const int*   edge_index    = (const int*)d_in[18];
    float* out = (float*)d_out;

    const int* src = edge_index;
    const int* dst = edge_index + NE;

    cudaFuncSetAttribute(msg_kernel,      cudaFuncAttributeMaxDynamicSharedMemorySize, MSG_SMEM);
    cudaFuncSetAttribute(pred_kernel,     cudaFuncAttributeMaxDynamicSharedMemorySize, PRED_SMEM);
    cudaFuncSetAttribute(updnl_kernel,    cudaFuncAttributeMaxDynamicSharedMemorySize, UPDNL_SMEM);
    cudaFuncSetAttribute(embed_nl_kernel, cudaFuncAttributeMaxDynamicSharedMemorySize, EMB_SMEM);
    cudaFuncSetAttribute(wc_kernel,       cudaFuncAttributeMaxDynamicSharedMemorySize, WC_SMEM);

    init_kernel<<<(NN * HH / 4 + NN / 4 + 255) / 256, 256>>>();
    count_kernel<<<(NE + 255) / 256, 256>>>(dst);
    embed_nl_kernel<<<296, 256, EMB_SMEM>>>(node_features, embed_W, embed_b, msg_W1);
    wc_kernel<<<LL * 16, 512, WC_SMEM>>>(msg_W2, msg_b2, upd_W);

    for (int l = 0; l < LL; l++) {
        msg_kernel<<<296, 512, MSG_SMEM>>>(edge_attr, src, dst,
                                           msg_W1 + l * EIN * HH, msg_b1 + l * HH);
        const float* nextW1 = (l < LL - 1) ? (msg_W1 + (l + 1) * EIN * HH) : pred_W1;
        updnl_kernel<<<148, 512, UPDNL_SMEM>>>(upd_W + (size_t)l * UIN * DD, upd_b + l * DD,
                                               ln_g + l * DD, ln_b + l * DD, nextW1, l);
    }

    pred_kernel<<<296, 512, PRED_SMEM>>>(edge_attr, src, dst,
                                         pred_W1, pred_b1, pred_W2, pred_b2,
                                         pred_W3, pred_b3, out);
}

// round 17
// speedup vs baseline: 3.2125x; 1.0047x over previous
#include <cuda_runtime.h>
#include <cuda_fp16.h>
#include <math.h>

#define NN 50000
#define NE 500000
#define FN 7
#define FE 8
#define DD 64
#define HH 128
#define PP 256
#define EIN 136
#define UIN 192
#define LL 3
#define EPB 128

#define WXS 68
#define WCS 132
#define NLS 68
#define H1S 136

typedef unsigned long long u64;

__device__ __forceinline__ void ffma2(u64 &d, u64 a, u64 b) {
    asm("fma.rn.f32x2 %0, %1, %2, %0;" : "+l"(d) : "l"(a), "l"(b));
}
__device__ __forceinline__ float f2sum(u64 a) {
    float lo, hi;
    asm("mov.b64 {%0, %1}, %2;" : "=f"(lo), "=f"(hi) : "l"(a));
    return lo + hi;
}
__device__ __forceinline__ void red_add_v4(float* p, float4 v) {
    u64 gp;
    asm("cvta.to.global.u64 %0, %1;" : "=l"(gp) : "l"(p));
    asm volatile("red.global.add.v4.f32 [%0], {%1, %2, %3, %4};"
                 :: "l"(gp), "f"(v.x), "f"(v.y), "f"(v.z), "f"(v.w) : "memory");
}
__device__ __forceinline__ void cp16(unsigned saddr, const void* g) {
    asm volatile("cp.async.cg.shared.global [%0], [%1], 16;" :: "r"(saddr), "l"(g));
}
#define CP_COMMIT()   asm volatile("cp.async.commit_group;" ::: "memory")
#define CP_WAIT_ALL() asm volatile("cp.async.wait_group 0;" ::: "memory")

__device__ __forceinline__ unsigned smem_u32(const void* p) {
    unsigned a;
    asm("{ .reg .u64 t; cvta.to.shared.u64 t, %1; cvt.u32.u64 %0, t; }" : "=r"(a) : "l"(p));
    return a;
}
__device__ __forceinline__ void ldsm_x4(unsigned &r0, unsigned &r1, unsigned &r2, unsigned &r3,
                                        unsigned addr) {
    asm volatile("ldmatrix.sync.aligned.m8n8.x4.shared.b16 {%0,%1,%2,%3}, [%4];"
                 : "=r"(r0), "=r"(r1), "=r"(r2), "=r"(r3) : "r"(addr));
}
__device__ __forceinline__ void ldsm_x2(unsigned &r0, unsigned &r1, unsigned addr) {
    asm volatile("ldmatrix.sync.aligned.m8n8.x2.shared.b16 {%0,%1}, [%2];"
                 : "=r"(r0), "=r"(r1) : "r"(addr));
}
__device__ __forceinline__ void mma16816(float* d,
                                         unsigned a0, unsigned a1, unsigned a2, unsigned a3,
                                         unsigned b0, unsigned b1) {
    asm volatile("mma.sync.aligned.m16n8k16.row.col.f32.f16.f16.f32 "
                 "{%0,%1,%2,%3}, {%4,%5,%6,%7}, {%8,%9}, {%0,%1,%2,%3};"
                 : "+f"(d[0]), "+f"(d[1]), "+f"(d[2]), "+f"(d[3])
                 : "r"(a0), "r"(a1), "r"(a2), "r"(a3), "r"(b0), "r"(b1));
}

// ---------------- scratch ----------------
__device__ float  g_x[NN * DD];
__device__ float  g_agg[NN * HH];
__device__ float  g_cnt[NN];
__device__ float  g_pab[NN * PP];     // fp32 Pab for msg layers
__device__ __half g_pabh[NN * PP];    // fp16 Pab for the final (pred) layer
__device__ float  g_wc[LL * HH * DD];
__device__ float  g_bm[LL * DD];

// ---------------- init ----------------
__global__ void init_kernel() {
    int i = blockIdx.x * blockDim.x + threadIdx.x;
    const int A4 = NN * HH / 4;
    if (i < A4) ((float4*)g_agg)[i] = make_float4(0.f, 0.f, 0.f, 0.f);
    else if (i < A4 + NN / 4) ((float4*)g_cnt)[i - A4] = make_float4(0.f, 0.f, 0.f, 0.f);
}

__global__ void count_kernel(const int* __restrict__ dst) {
    int e = blockIdx.x * blockDim.x + threadIdx.x;
    if (e < NE) atomicAdd(&g_cnt[dst[e]], 1.0f);
}

// ---------------- fused embed + node_lin(layer0) ----------------
#define EMB_SMEM ((PP*NLS + FN*DD + DD + 8*FN + 8*DD) * 4)

__global__ void __launch_bounds__(256, 2)
embed_nl_kernel(const float* __restrict__ nf,
                const float* __restrict__ eW, const float* __restrict__ eb,
                const float* __restrict__ W1) {
    extern __shared__ float s[];
    float* sWt = s;
    float* sWe = sWt + PP * NLS;
    float* sBe = sWe + FN * DD;
    float* sNf = sBe + DD;
    float* sX  = sNf + 8 * FN;

    const int tid = threadIdx.x;
    for (int i = tid; i < DD * PP; i += 256) {
        int k = i >> 8, j = i & 255;
        sWt[j * NLS + k] = (j < HH) ? W1[k * HH + j] : W1[(DD + k) * HH + (j - HH)];
    }
    for (int i = tid; i < FN * DD; i += 256) sWe[i] = eW[i];
    if (tid < DD) sBe[tid] = eb[tid];
    __syncthreads();

    const int step = gridDim.x * 8;
    for (int n0 = blockIdx.x * 8; n0 < NN; n0 += step) {
        for (int i = tid; i < 8 * FN; i += 256) {
            int c = i / FN, f = i % FN;
            sNf[i] = nf[(n0 + c) * FN + f];
        }
        __syncthreads();
        for (int i = tid; i < 8 * DD; i += 256) {
            int c = i >> 6, d = i & 63;
            float xv = sBe[d];
#pragma unroll
            for (int f = 0; f < FN; f++) xv += sNf[c * FN + f] * sWe[f * DD + d];
            xv = fmaxf(xv, 0.f);
            sX[c * DD + d] = xv;
            g_x[(n0 + c) * DD + d] = xv;
        }
        __syncthreads();
        u64 acc[8];
#pragma unroll
        for (int c = 0; c < 8; c++) acc[c] = 0ull;
        const float* wr = sWt + tid * NLS;
#pragma unroll 4
        for (int k = 0; k < DD; k += 4) {
            ulonglong2 w = *(const ulonglong2*)(wr + k);
#pragma unroll
            for (int c = 0; c < 8; c++) {
                ulonglong2 v = *(const ulonglong2*)(sX + c * DD + k);
                ffma2(acc[c], w.x, v.x);
                ffma2(acc[c], w.y, v.y);
            }
        }
#pragma unroll
        for (int c = 0; c < 8; c++)
            g_pab[(size_t)(n0 + c) * PP + tid] = f2sum(acc[c]);
        __syncthreads();
    }
}

// ---------------- precompute Wc = W2 @ Wm, bm = b2 @ Wm (grid LL*16) ----------------
#define WC_SMEM ((8*HH + HH*DD) * 4)

__global__ void __launch_bounds__(512)
wc_kernel(const float* __restrict__ W2all, const float* __restrict__ b2all,
          const float* __restrict__ Wall) {
    extern __shared__ float s[];
    float* sW2 = s;
    float* sWm = sW2 + 8 * HH;

    const int l = blockIdx.x >> 4, q = blockIdx.x & 15;
    const float* W2 = W2all + l * HH * HH;
    const float* b2 = b2all + l * HH;
    const float* Wm = Wall + (size_t)l * UIN * DD + DD * DD;

    const int tid = threadIdx.x;
    for (int i = tid; i < 8 * HH; i += 512) sW2[i] = W2[q * 8 * HH + i];
    for (int i = tid; i < HH * DD; i += 512) sWm[i] = Wm[i];
    __syncthreads();

    {
        int k = tid >> 6, d = tid & 63;
        float a0 = 0.f, a1 = 0.f;
#pragma unroll 16
        for (int j = 0; j < HH; j += 2) {
            a0 += sW2[k * HH + j] * sWm[j * DD + d];
            a1 += sW2[k * HH + j + 1] * sWm[(j + 1) * DD + d];
        }
        g_wc[l * HH * DD + (q * 8 + k) * DD + d] = a0 + a1;
    }
    if (q == 0 && tid < DD) {
        float a0 = 0.f, a1 = 0.f;
        for (int j = 0; j < HH; j += 2) {
            a0 += b2[j] * sWm[j * DD + tid];
            a1 += b2[j + 1] * sWm[(j + 1) * DD + tid];
        }
        g_bm[l * DD + tid] = a0 + a1;
    }
}

// ---------------- edge message (8-deep LDG pipeline) ----------------
#define MSG_SMEM ((EPB*HH + EPB*FE + 2*EPB) * 4)

__global__ void __launch_bounds__(512, 2)
msg_kernel(const float* __restrict__ ea,
           const int* __restrict__ src, const int* __restrict__ dst,
           const float* __restrict__ W1, const float* __restrict__ b1) {
    extern __shared__ float s[];
    float* sH   = s;
    float* sEa  = sH + EPB * HH;
    int*   sSrc = (int*)(sEa + EPB * FE);
    int*   sDst = sSrc + EPB;

    const int tid = threadIdx.x;
    const int j = tid & 127, g = tid >> 7;
    const int wid = tid >> 5, lane = tid & 31;
    const float b1v = b1[j];
    float w1c[8];
#pragma unroll
    for (int f = 0; f < 8; f++) w1c[f] = W1[(2 * DD + f) * HH + j];

    int e0 = blockIdx.x * EPB;
    const int step = gridDim.x * EPB;

    for (; e0 < NE; e0 += step) {
        __syncthreads();
        if (tid < 2 * EPB) {
            int le = tid & (EPB - 1);
            int gc = e0 + le; if (gc >= NE) gc = NE - 1;
            if (tid < EPB) sSrc[le] = src[gc];
            else           sDst[le] = dst[gc];
        }
        for (int i = tid; i < EPB * 2; i += 512) {
            int le = i >> 1, frag = i & 1;
            int gc = e0 + le; if (gc >= NE) gc = NE - 1;
            ((float4*)sEa)[i] = ((const float4*)ea)[(size_t)gc * 2 + frag];
        }
        __syncthreads();

        {
            float pa[8], pb[8];
#pragma unroll
            for (int c = 0; c < 8; c++) {
                int e = g + 4 * c;
                pa[c] = g_pab[(size_t)sSrc[e] * PP + j];
                pb[c] = g_pab[(size_t)sDst[e] * PP + HH + j];
            }
#pragma unroll
            for (int c = 0; c < 32; c++) {
                int e = g + 4 * c;
                float hv = pa[c & 7] + pb[c & 7] + b1v;
                if (c + 8 < 32) {
                    int e2 = g + 4 * (c + 8);
                    pa[c & 7] = g_pab[(size_t)sSrc[e2] * PP + j];
                    pb[c & 7] = g_pab[(size_t)sDst[e2] * PP + HH + j];
                }
                float4 a0 = ((const float4*)(sEa + e * FE))[0];
                float4 a1 = ((const float4*)(sEa + e * FE))[1];
                hv = fmaf(a0.x, w1c[0], hv); hv = fmaf(a0.y, w1c[1], hv);
                hv = fmaf(a0.z, w1c[2], hv); hv = fmaf(a0.w, w1c[3], hv);
                hv = fmaf(a1.x, w1c[4], hv); hv = fmaf(a1.y, w1c[5], hv);
                hv = fmaf(a1.z, w1c[6], hv); hv = fmaf(a1.w, w1c[7], hv);
                sH[e * HH + j] = fmaxf(hv, 0.f);
            }
        }
        __syncthreads();

#pragma unroll
        for (int t = 0; t < 8; t++) {
            int le = wid * 8 + t;
            if (e0 + le < NE) {
                float4 m = ((const float4*)(sH + le * HH))[lane];
                red_add_v4(g_agg + (size_t)sDst[le] * HH + lane * 4, m);
            }
        }
    }
}

// ---------------- fused node kernel (folded Wc, NPT=16, fp16 final pab) ----------------
#define NPT 16
#define STG (NPT*DD + NPT*HH + NPT)
#define UPDNL_SMEM ((DD*WXS + DD*WCS + PP*NLS + 2*STG + NPT*DD + 64) * 4)

__global__ void __launch_bounds__(512, 1)
updnl_kernel(const float* __restrict__ W, const float* __restrict__ b,
             const float* __restrict__ lg, const float* __restrict__ lb,
             const float* __restrict__ W1next, int layer, int finalLayer) {
    extern __shared__ float s[];
    float* sWxt = s;
    float* sWct = sWxt + DD * WXS;
    float* sWnl = sWct + DD * WCS;
    float* sStg = sWnl + PP * NLS;
    float* sXn  = sStg + 2 * STG;
    float* sRed = sXn + NPT * DD;

    const unsigned aStg = (unsigned)__cvta_generic_to_shared(sStg);
    const float* wc = g_wc + layer * HH * DD;
    const float* bm = g_bm + layer * DD;

    const int tid = threadIdx.x;
    for (int i = tid; i < DD * DD; i += 512) { int t = i >> 6, d = i & 63; sWxt[d * WXS + t] = W[t * DD + d]; }
    for (int i = tid; i < HH * DD; i += 512) { int k = i >> 6, d = i & 63; sWct[d * WCS + k] = wc[k * DD + d]; }
    for (int i = tid; i < DD * PP; i += 512) {
        int k = i >> 8, j = i & 255;
        sWnl[j * NLS + k] = (j < HH) ? W1next[k * HH + j] : W1next[(DD + k) * HH + (j - HH)];
    }

    const int d = tid & 63, ln = tid >> 6;
    const int wg = (tid >> 5) & 1, lane = tid & 31;
    const int j = tid & 255, grp = tid >> 8;
    const float bv = b[d], gv = lg[d], lbv = lb[d], bmv = bm[d];

    const int stride = gridDim.x * NPT;

#define STAGE(N0, B) { \
    unsigned base = aStg + (B) * STG * 4; \
    cp16(base + (NPT * DD + (tid >> 5) * HH + (tid & 31) * 4) * 4, \
         g_agg + (size_t)((N0) + (tid >> 5)) * HH + (tid & 31) * 4); \
    if (tid < 256) \
        cp16(base + ((tid >> 4) * DD + (tid & 15) * 4) * 4, \
             g_x + (size_t)((N0) + (tid >> 4)) * DD + (tid & 15) * 4); \
    if (tid < 4) \
        cp16(base + (NPT * DD + NPT * HH + tid * 4) * 4, g_cnt + (N0) + tid * 4); }

    int n0 = blockIdx.x * NPT;
    if (n0 < NN) { STAGE(n0, 0); }
    CP_COMMIT();
    __syncthreads();

    int buf = 0;
    for (; n0 < NN; n0 += stride, buf ^= 1) {
        CP_WAIT_ALL();
        __syncthreads();

        const float* sX   = sStg + buf * STG;
        const float* sAgg = sX + NPT * DD;
        const float* sCnt = sAgg + NPT * HH;

        {
            int nn = n0 + (tid >> 5);
            ((float4*)(g_agg + (size_t)nn * HH))[tid & 31] = make_float4(0.f, 0.f, 0.f, 0.f);
        }
        int nnext = n0 + stride;
        if (nnext < NN) { STAGE(nnext, buf ^ 1); }
        CP_COMMIT();

        float outv[2];
        {
            u64 ax0 = 0ull, ax1 = 0ull, ac0 = 0ull, ac1 = 0ull;
            const float* wrx = sWxt + d * WXS;
            const float* wrc = sWct + d * WCS;
            const float* x0 = sX + ln * DD;
            const float* x1 = sX + (ln + 8) * DD;
            const float* a0p = sAgg + ln * HH;
            const float* a1p = sAgg + (ln + 8) * HH;
#pragma unroll 4
            for (int k = 0; k < DD; k += 4) {
                ulonglong2 w = *(const ulonglong2*)(wrx + k);
                ulonglong2 v0 = *(const ulonglong2*)(x0 + k);
                ulonglong2 v1 = *(const ulonglong2*)(x1 + k);
                ffma2(ax0, w.x, v0.x); ffma2(ax0, w.y, v0.y);
                ffma2(ax1, w.x, v1.x); ffma2(ax1, w.y, v1.y);
            }
#pragma unroll 4
            for (int k = 0; k < HH; k += 4) {
                ulonglong2 w = *(const ulonglong2*)(wrc + k);
                ulonglong2 v0 = *(const ulonglong2*)(a0p + k);
                ulonglong2 v1 = *(const ulonglong2*)(a1p + k);
                ffma2(ac0, w.x, v0.x); ffma2(ac0, w.y, v0.y);
                ffma2(ac1, w.x, v1.x); ffma2(ac1, w.y, v1.y);
            }
            float c0 = sCnt[ln],     i0 = 1.f / (c0 + 1e-6f);
            float c1 = sCnt[ln + 8], i1 = 1.f / (c1 + 1e-6f);
            outv[0] = x0[d] + fmaxf(f2sum(ax0) + f2sum(ac0) * i0 + c0 * i0 * bmv + bv, 0.f);
            outv[1] = x1[d] + fmaxf(f2sum(ax1) + f2sum(ac1) * i1 + c1 * i1 * bmv + bv, 0.f);
        }

#pragma unroll
        for (int c = 0; c < 2; c++) {
            int nc = ln + 8 * c;
            float s1 = outv[c], s2 = outv[c] * outv[c];
#pragma unroll
            for (int off = 16; off; off >>= 1) {
                s1 += __shfl_xor_sync(0xFFFFFFFFu, s1, off);
                s2 += __shfl_xor_sync(0xFFFFFFFFu, s2, off);
            }
            if (lane == 0) { sRed[(nc * 2 + wg) * 2] = s1; sRed[(nc * 2 + wg) * 2 + 1] = s2; }
        }
        __syncthreads();
#pragma unroll
        for (int c = 0; c < 2; c++) {
            int nc = ln + 8 * c;
            float t1 = sRed[nc * 4] + sRed[nc * 4 + 2];
            float t2 = sRed[nc * 4 + 1] + sRed[nc * 4 + 3];
            float mu = t1 * (1.f / DD);
            float var = t2 * (1.f / DD) - mu * mu;
            float xn = (outv[c] - mu) * rsqrtf(var + 1e-5f) * gv + lbv;
            g_x[(size_t)(n0 + nc) * DD + d] = xn;
            sXn[nc * DD + d] = xn;
        }
        __syncthreads();

        u64 acc[8];
#pragma unroll
        for (int c = 0; c < 8; c++) acc[c] = 0ull;
        const float* wr2 = sWnl + j * NLS;
#pragma unroll 4
        for (int k = 0; k < DD; k += 4) {
            ulonglong2 w = *(const ulonglong2*)(wr2 + k);
#pragma unroll
            for (int c = 0; c < 8; c++) {
                ulonglong2 v = *(const ulonglong2*)(sXn + (grp + 2 * c) * DD + k);
                ffma2(acc[c], w.x, v.x);
                ffma2(acc[c], w.y, v.y);
            }
        }
        if (finalLayer) {
#pragma unroll
            for (int c = 0; c < 8; c++)
                g_pabh[(size_t)(n0 + grp + 2 * c) * PP + j] = __float2half(f2sum(acc[c]));
        } else {
#pragma unroll
            for (int c = 0; c < 8; c++)
                g_pab[(size_t)(n0 + grp + 2 * c) * PP + j] = f2sum(acc[c]);
        }
        __syncthreads();
    }
#undef STAGE
}

// ---------------- edge predictor (fp16 pab gather + mma.sync + frag epilogue) ----------------
#define PRED_SMEM (34816 + 17408 + 4096 + 1024 + 512 + 1024)

__global__ void __launch_bounds__(512, 2)
pred_kernel(const float* __restrict__ ea,
            const int* __restrict__ src, const int* __restrict__ dst,
            const float* __restrict__ W1, const float* __restrict__ b1,
            const float* __restrict__ W2, const float* __restrict__ b2,
            const float* __restrict__ W3, const float* __restrict__ b3,
            float* __restrict__ out) {
    extern __shared__ char sc[];
    __half* sH1 = (__half*)sc;                       // [128][136] fp16
    __half* sBW = (__half*)(sc + 34816);             // [64][136] fp16
    float*  sEa = (float*)(sc + 34816 + 17408);      // [128][8]
    int*    sSrc = (int*)(sEa + EPB * FE);
    int*    sDst = sSrc + EPB;
    float*  sW3 = (float*)(sDst + EPB);              // 64
    float*  sB2 = sW3 + DD;                          // 64
    float*  sPart = sB2 + DD;                        // [128][2]

    const int tid = threadIdx.x;
    const int wid = tid >> 5, lane = tid & 31;
    const int j = tid & 127, g = tid >> 7;

    for (int i = tid; i < HH * DD; i += 512) {
        int k = i >> 6, n = i & 63;
        sBW[n * H1S + k] = __float2half(W2[i]);
    }
    if (tid < DD) { sW3[tid] = W3[tid]; sB2[tid] = b2[tid]; }

    const unsigned aH1 = smem_u32(sH1);
    const unsigned aBW = smem_u32(sBW);

    const float b1v = b1[j], b3v = b3[0];
    float w1c[8];
#pragma unroll
    for (int f = 0; f < 8; f++) w1c[f] = W1[(2 * DD + f) * HH + j];

    const int mrow = (wid & 7) * 16;
    const int nbase = (wid >> 3) * 32;
    const int half = wid >> 3;
    const int a_row = (lane & 7) + ((lane >> 3) & 1) * 8;
    const int a_kof = (lane >> 4) * 8;
    const int b_row = lane & 7;
    const int b_kof = ((lane >> 3) & 1) * 8;

    int e0 = blockIdx.x * EPB;
    const int step = gridDim.x * EPB;

    for (; e0 < NE; e0 += step) {
        __syncthreads();
        if (tid < 2 * EPB) {
            int le = tid & (EPB - 1);
            int gc = e0 + le; if (gc >= NE) gc = NE - 1;
            if (tid < EPB) sSrc[le] = src[gc];
            else           sDst[le] = dst[gc];
        }
        for (int i = tid; i < EPB * 2; i += 512) {
            int le = i >> 1, frag = i & 1;
            int gc = e0 + le; if (gc >= NE) gc = NE - 1;
            ((float4*)sEa)[i] = ((const float4*)ea)[(size_t)gc * 2 + frag];
        }
        __syncthreads();

        // ---- phase A: h1 = relu(Pa + Pb + ea@W1c + b1) -> fp16 [e][136] (fp16 gather) ----
        {
            __half pa[8], pb[8];
#pragma unroll
            for (int c = 0; c < 8; c++) {
                int e = g + 4 * c;
                pa[c] = g_pabh[(size_t)sSrc[e] * PP + j];
                pb[c] = g_pabh[(size_t)sDst[e] * PP + HH + j];
            }
#pragma unroll
            for (int c = 0; c < 32; c++) {
                int e = g + 4 * c;
                float hv = __half2float(pa[c & 7]) + __half2float(pb[c & 7]) + b1v;
                if (c + 8 < 32) {
                    int e2 = g + 4 * (c + 8);
                    pa[c & 7] = g_pabh[(size_t)sSrc[e2] * PP + j];
                    pb[c & 7] = g_pabh[(size_t)sDst[e2] * PP + HH + j];
                }
                float4 a0 = ((const float4*)(sEa + e * FE))[0];
                float4 a1 = ((const float4*)(sEa + e * FE))[1];
                hv = fmaf(a0.x, w1c[0], hv); hv = fmaf(a0.y, w1c[1], hv);
                hv = fmaf(a0.z, w1c[2], hv); hv = fmaf(a0.w, w1c[3], hv);
                hv = fmaf(a1.x, w1c[4], hv); hv = fmaf(a1.y, w1c[5], hv);
                hv = fmaf(a1.z, w1c[6], hv); hv = fmaf(a1.w, w1c[7], hv);
                sH1[e * H1S + j] = __float2half(fmaxf(hv, 0.f));
            }
        }
        __syncthreads();

        {
            float dfr[4][4];
#pragma unroll
            for (int t = 0; t < 4; t++)
#pragma unroll
                for (int q = 0; q < 4; q++) dfr[t][q] = 0.f;

#pragma unroll
            for (int ks = 0; ks < 8; ks++) {
                int k0 = ks * 16;
                unsigned fa0, fa1, fa2, fa3;
                ldsm_x4(fa0, fa1, fa2, fa3,
                        aH1 + ((mrow + a_row) * H1S + k0 + a_kof) * 2);
#pragma unroll
                for (int t = 0; t < 4; t++) {
                    unsigned fb0, fb1;
                    ldsm_x2(fb0, fb1,
                            aBW + ((nbase + t * 8 + b_row) * H1S + k0 + b_kof) * 2);
                    mma16816(dfr[t], fa0, fa1, fa2, fa3, fb0, fb1);
                }
            }

            float p0 = 0.f, p1 = 0.f;
#pragma unroll
            for (int t = 0; t < 4; t++) {
                int c0 = nbase + t * 8 + 2 * (lane & 3);
                float w0 = sW3[c0], w1 = sW3[c0 + 1];
                float bb0 = sB2[c0], bb1 = sB2[c0 + 1];
                p0 = fmaf(fmaxf(dfr[t][0] + bb0, 0.f), w0, p0);
                p0 = fmaf(fmaxf(dfr[t][1] + bb1, 0.f), w1, p0);
                p1 = fmaf(fmaxf(dfr[t][2] + bb0, 0.f), w0, p1);
                p1 = fmaf(fmaxf(dfr[t][3] + bb1, 0.f), w1, p1);
            }
            p0 += __shfl_xor_sync(0xFFFFFFFFu, p0, 1);
            p0 += __shfl_xor_sync(0xFFFFFFFFu, p0, 2);
            p1 += __shfl_xor_sync(0xFFFFFFFFu, p1, 1);
            p1 += __shfl_xor_sync(0xFFFFFFFFu, p1, 2);
            int r0 = mrow + (lane >> 2), r1 = r0 + 8;
            if ((lane & 3) == 0) {
                sPart[r0 * 2 + half] = p0;
                sPart[r1 * 2 + half] = p1;
            }
        }
        __syncthreads();

        if (tid < EPB) {
            int ge = e0 + tid;
            float v = sPart[tid * 2] + sPart[tid * 2 + 1];
            if (ge < NE) out[ge] = tanhf(v + b3v);
        }
    }
}

// ---------------- launch ----------------
extern "C" void kernel_launch(void* const* d_in, const int* in_sizes, int n_in,
                              void* d_out, int out_size) {
    const float* node_features = (const float*)d_in[0];
    const float* edge_attr     = (const float*)d_in[1];
    const float* embed_W       = (const float*)d_in[2];
    const float* embed_b       = (const float*)d_in[3];
    const float* msg_W1        = (const float*)d_in[4];
    const float* msg_b1        = (const float*)d_in[5];
    const float* msg_W2        = (const float*)d_in[6];
    const float* msg_b2        = (const float*)d_in[7];
    const float* upd_W         = (const float*)d_in[8];
    const float* upd_b         = (const float*)d_in[9];
    const float* ln_g          = (const float*)d_in[10];
    const float* ln_b          = (const float*)d_in[11];
    const float* pred_W1       = (const float*)d_in[12];
    const float* pred_b1       = (const float*)d_in[13];
    const float* pred_W2       = (const float*)d_in[14];
    const float* pred_b2       = (const float*)d_in[15];
    const float* pred_W3       = (const float*)d_in[16];
    const float* pred_b3       = (const float*)d_in[17];
    const int*   edge_index    = (const int*)d_in[18];
    float* out = (float*)d_out;

    const int* src = edge_index;
    const int* dst = edge_index + NE;

    cudaFuncSetAttribute(msg_kernel,      cudaFuncAttributeMaxDynamicSharedMemorySize, MSG_SMEM);
    cudaFuncSetAttribute(pred_kernel,     cudaFuncAttributeMaxDynamicSharedMemorySize, PRED_SMEM);
    cudaFuncSetAttribute(updnl_kernel,    cudaFuncAttributeMaxDynamicSharedMemorySize, UPDNL_SMEM);
    cudaFuncSetAttribute(embed_nl_kernel, cudaFuncAttributeMaxDynamicSharedMemorySize, EMB_SMEM);
    cudaFuncSetAttribute(wc_kernel,       cudaFuncAttributeMaxDynamicSharedMemorySize, WC_SMEM);

    init_kernel<<<(NN * HH / 4 + NN / 4 + 255) / 256, 256>>>();
    count_kernel<<<(NE + 255) / 256, 256>>>(dst);
    embed_nl_kernel<<<296, 256, EMB_SMEM>>>(node_features, embed_W, embed_b, msg_W1);
    wc_kernel<<<LL * 16, 512, WC_SMEM>>>(msg_W2, msg_b2, upd_W);

    for (int l = 0; l < LL; l++) {
        msg_kernel<<<296, 512, MSG_SMEM>>>(edge_attr, src, dst,
                                           msg_W1 + l * EIN * HH, msg_b1 + l * HH);
        const float* nextW1 = (l < LL - 1) ? (msg_W1 + (l + 1) * EIN * HH) : pred_W1;
        updnl_kernel<<<148, 512, UPDNL_SMEM>>>(upd_W + (size_t)l * UIN * DD, upd_b + l * DD,
                                               ln_g + l * DD, ln_b + l * DD, nextW1, l,
                                               (l == LL - 1) ? 1 : 0);
    }

    pred_kernel<<<296, 512, PRED_SMEM>>>(edge_attr, src, dst,
                                         pred_W1, pred_b1, pred_W2, pred_b2,
                                         pred_W3, pred_b3, out);
}